// round 5
// baseline (speedup 1.0000x reference)
#include <cuda_runtime.h>
#include <math.h>

#define BB 1024
#define NN 32
#define DOBS 17
#define DACT 6
#define DIN 23
#define HH 256
#define NSTEPS 5

// Transposed W2 (row j holds W2[:,j]) for vectorized forward reads.
__device__ float g_W2T[2][HH * HH];

__global__ void transpose_w2(const float* __restrict__ w2a,
                             const float* __restrict__ w2b) {
    int j = blockIdx.x;   // 0..255
    int k = threadIdx.x;  // 0..255
    g_W2T[0][j * HH + k] = w2a[k * HH + j];
    g_W2T[1][j * HH + k] = w2b[k * HH + j];
}

__global__ __launch_bounds__(256, 2) void svgd_kernel(
    const float* __restrict__ obs, const float* __restrict__ a0,
    const float* __restrict__ W1a, const float* __restrict__ B1a,
    const float* __restrict__ W2a, const float* __restrict__ B2a,
    const float* __restrict__ W3a, const float* __restrict__ B3a,
    const float* __restrict__ W1b, const float* __restrict__ B1b,
    const float* __restrict__ W2b, const float* __restrict__ B2b,
    const float* __restrict__ W3b, const float* __restrict__ B3b,
    float* __restrict__ out)
{
    __shared__ __align__(16) float s_h[NN * HH];   // 32 KB: h1 / dh2 / dh1 / sort scratch
    __shared__ float s_x[NN * 32];                 // input rows (obs | act), stride 32
    __shared__ float s_d2[NN * NN];
    __shared__ float s_K[NN * NN];
    __shared__ float s_q[2][NN];
    __shared__ __align__(16) float s_s[NN * 8];    // score, stride 8
    __shared__ float s_a[NN * 8];                  // actions, stride 8
    __shared__ float s_logp[NN];
    __shared__ float s_lpn[NN];
    __shared__ float s_red[8 * NN];
    __shared__ float s_gate[NN];

    const int b = blockIdx.x;
    const int tid = threadIdx.x;
    const int lane = tid & 31;
    const int warp = tid >> 5;

    // Load obs + a0
    for (int idx = tid; idx < NN * DOBS; idx += 256) {
        int n = idx / DOBS, k = idx % DOBS;
        s_x[n * 32 + k] = obs[(b * NN + n) * DOBS + k];
    }
    for (int idx = tid; idx < NN * DACT; idx += 256) {
        int n = idx / DACT, d = idx % DACT;
        s_a[n * 8 + d] = a0[(b * NN + n) * DACT + d];
    }
    if (tid < NN) s_logp[tid] = 0.0f;
    __syncthreads();
    if (tid < NN) {
        float ss = 0.0f;
        #pragma unroll
        for (int d = 0; d < DACT; d++) { float v = s_a[tid * 8 + d]; ss += v * v; }
        s_lpn[tid] = -3.0f * logf(6.283185307179586f * 0.3f) - (0.5f / 0.3f) * ss;
    }

    for (int step = 0; step < NSTEPS; ++step) {
        __syncthreads();
        for (int idx = tid; idx < NN * DACT; idx += 256) {
            int n = idx / DACT, d = idx % DACT;
            s_x[n * 32 + DOBS + d] = s_a[n * 8 + d];
        }
        for (int idx = tid; idx < NN * 8; idx += 256) s_s[idx] = 0.0f;
        __syncthreads();

        unsigned m1[2], m2[2];

        // ================= forward both Q nets =================
        for (int net = 0; net < 2; ++net) {
            const float* W1 = net ? W1b : W1a;
            const float* B1 = net ? B1b : B1a;
            const float* B2 = net ? B2b : B2a;
            const float* W3 = net ? W3b : W3a;
            const float* B3 = net ? B3b : B3a;

            // ---- layer1: thread j computes h1[n][j] for all n ----
            float c[DIN];
            #pragma unroll
            for (int k = 0; k < DIN; k++) c[k] = W1[k * HH + tid];
            float bb1 = B1[tid];
            unsigned mm1 = 0;
            for (int n = 0; n < NN; n++) {
                float z = bb1;
                #pragma unroll
                for (int k = 0; k < DIN; k++) z += s_x[n * 32 + k] * c[k];
                if (z > 0.0f) mm1 |= (1u << n); else z = 0.0f;
                s_h[n * HH + tid] = z;
            }
            m1[net] = mm1;
            __syncthreads();

            // ---- layer2 + fused q partials: double-buffered LDG.128 weights ----
            float acc[NN];
            #pragma unroll
            for (int n = 0; n < NN; n++) acc[n] = 0.0f;
            const float* W2Tr = g_W2T[net] + tid * HH;
            float4 wa = *(const float4*)&W2Tr[0];
            float4 wb = *(const float4*)&W2Tr[4];
            #pragma unroll 4
            for (int kb = 0; kb < HH; kb += 8) {
                int nk = (kb + 8) & (HH - 1);   // wraps to 0 on last iter (in-bounds)
                float4 wan = *(const float4*)&W2Tr[nk];
                float4 wbn = *(const float4*)&W2Tr[nk + 4];
                #pragma unroll
                for (int n = 0; n < NN; n++) {
                    float4 ha = *(const float4*)&s_h[n * HH + kb];
                    float4 hb = *(const float4*)&s_h[n * HH + kb + 4];
                    acc[n] += ha.x * wa.x + ha.y * wa.y + ha.z * wa.z + ha.w * wa.w
                            + hb.x * wb.x + hb.y * wb.y + hb.z * wb.z + hb.w * wb.w;
                }
                wa = wan; wb = wbn;
            }
            float bb2 = B2[tid], w3v = W3[tid];
            unsigned mm2 = 0;
            #pragma unroll
            for (int n = 0; n < NN; n++) {
                float z = acc[n] + bb2;
                if (z > 0.0f) { mm2 |= (1u << n); acc[n] = z * w3v; }
                else acc[n] = 0.0f;
            }
            m2[net] = mm2;

            // block-reduce acc[n] -> q[n]
            #pragma unroll
            for (int n = 0; n < NN; n++) {
                float v = acc[n];
                v += __shfl_xor_sync(0xffffffffu, v, 16);
                v += __shfl_xor_sync(0xffffffffu, v, 8);
                v += __shfl_xor_sync(0xffffffffu, v, 4);
                v += __shfl_xor_sync(0xffffffffu, v, 2);
                v += __shfl_xor_sync(0xffffffffu, v, 1);
                if (lane == 0) s_red[warp * NN + n] = v;
            }
            __syncthreads();
            if (tid < NN) {
                float q = B3[0];
                #pragma unroll
                for (int w = 0; w < 8; w++) q += s_red[w * NN + tid];
                s_q[net][tid] = q;
            }
            __syncthreads();
        }

        if (tid < NN) s_gate[tid] = (s_q[0][tid] <= s_q[1][tid]) ? 1.0f : 0.0f;
        __syncthreads();

        // ================= backward both Q nets (input grad only) =================
        for (int net = 0; net < 2; ++net) {
            const float* W1 = net ? W1b : W1a;
            const float* W2 = net ? W2b : W2a;
            const float* W3 = net ? W3b : W3a;
            float w3v = W3[tid];
            unsigned mm2 = m2[net], mm1 = m1[net];

            // dh2[n][j] = gate[n]*W3[j]*mask2
            for (int n = 0; n < NN; n++) {
                float g = net ? (1.0f - s_gate[n]) : s_gate[n];
                s_h[n * HH + tid] = ((mm2 >> n) & 1u) ? g * w3v : 0.0f;
            }
            __syncthreads();

            // dh1[n][k=tid] = sum_j dh2[n][j] * W2[tid][j]  (row j-contiguous)
            float acc[NN];
            #pragma unroll
            for (int n = 0; n < NN; n++) acc[n] = 0.0f;
            const float* w2r = W2 + tid * HH;
            float4 wa = *(const float4*)&w2r[0];
            float4 wb = *(const float4*)&w2r[4];
            #pragma unroll 4
            for (int jb = 0; jb < HH; jb += 8) {
                int nj = (jb + 8) & (HH - 1);
                float4 wan = *(const float4*)&w2r[nj];
                float4 wbn = *(const float4*)&w2r[nj + 4];
                #pragma unroll
                for (int n = 0; n < NN; n++) {
                    float4 da = *(const float4*)&s_h[n * HH + jb];
                    float4 db = *(const float4*)&s_h[n * HH + jb + 4];
                    acc[n] += da.x * wa.x + da.y * wa.y + da.z * wa.z + da.w * wa.w
                            + db.x * wb.x + db.y * wb.y + db.z * wb.z + db.w * wb.w;
                }
                wa = wan; wb = wbn;
            }
            __syncthreads();  // all dh2 reads done before overwrite
            for (int n = 0; n < NN; n++)
                s_h[n * HH + tid] = ((mm1 >> n) & 1u) ? acc[n] : 0.0f;
            __syncthreads();

            // da[n][d] = sum_k dh1[n][k] * W1[17+d][k] -> accumulate into s_s
            if (tid < NN * DACT) {
                int n = tid / DACT, d = tid % DACT;
                const float* w1r = W1 + (DOBS + d) * HH;
                float sum = 0.0f;
                for (int k = 0; k < HH; k += 4) {
                    float4 h4 = *(const float4*)&s_h[n * HH + k];
                    float4 w4 = *(const float4*)&w1r[k];
                    sum += h4.x * w4.x + h4.y * w4.y + h4.z * w4.z + h4.w * w4.w;
                }
                s_s[n * 8 + d] += sum;
            }
            __syncthreads();
        }

        // ================= SVGD update =================
        for (int p = tid; p < NN * NN; p += 256) {
            int i = p >> 5, j = p & 31;
            float ds = 0.0f;
            #pragma unroll
            for (int d = 0; d < DACT; d++) {
                float df = s_a[i * 8 + d] - s_a[j * 8 + d];
                ds += df * df;
            }
            s_d2[p] = ds;
            s_h[p] = ds;  // sort copy
        }
        __syncthreads();

        // bitonic sort of 1024 values (exact median)
        for (int ks = 2; ks <= NN * NN; ks <<= 1) {
            for (int jj = ks >> 1; jj > 0; jj >>= 1) {
                #pragma unroll
                for (int e = 0; e < 4; e++) {
                    int idx = (e << 8) | tid;
                    int ixj = idx ^ jj;
                    if (ixj > idx) {
                        float va = s_h[idx], vb = s_h[ixj];
                        bool up = ((idx & ks) == 0);
                        if ((va > vb) == up) { s_h[idx] = vb; s_h[ixj] = va; }
                    }
                }
                __syncthreads();
            }
        }

        float med = 0.5f * (s_h[511] + s_h[512]);
        float hm = med / logf(33.0f);
        float gamma = 1.0f / (2.0f * hm + 1e-8f);
        for (int p = tid; p < NN * NN; p += 256)
            s_K[p] = expf(-gamma * s_d2[p]);
        __syncthreads();

        float anew[DACT];
        float lpdelta = 0.0f;
        if (tid < NN) {
            int i = tid;
            float ai[DACT];
            #pragma unroll
            for (int d = 0; d < DACT; d++) ai[d] = s_a[i * 8 + d];
            float ph[DACT] = {0, 0, 0, 0, 0, 0};
            float t1 = 0.0f, t2s = 0.0f;
            for (int j = 0; j < NN; j++) {
                float Kij = s_K[i * 32 + j];
                float dot = 0.0f;
                #pragma unroll
                for (int d = 0; d < DACT; d++) {
                    float df = ai[d] - s_a[j * 8 + d];
                    float sj = s_s[j * 8 + d];
                    dot += df * sj;
                    ph[d] += Kij * sj + 2.0f * gamma * Kij * df;
                }
                t1 += -2.0f * gamma * Kij * dot;
                float I = (i == j) ? 1.0f : 0.0f;
                t2s += 2.0f * gamma * Kij * s_d2[i * 32 + j] - 6.0f * (Kij - I);
            }
            t1 *= (1.0f / 31.0f);
            float t2 = -2.0f * gamma * t2s * (1.0f / 31.0f);
            lpdelta = 0.05f * (t1 + t2);
            #pragma unroll
            for (int d = 0; d < DACT; d++)
                anew[d] = ai[d] + 0.05f * ph[d] * (1.0f / 32.0f);
        }
        __syncthreads();
        if (tid < NN) {
            s_logp[tid] -= lpdelta;
            #pragma unroll
            for (int d = 0; d < DACT; d++) s_a[tid * 8 + d] = anew[d];
        }
        __syncthreads();
    }

    // ================= finalize =================
    __syncthreads();
    if (tid < NN) {
        int n = tid;
        float lpt = 0.0f;
        #pragma unroll
        for (int d = 0; d < DACT; d++) {
            float av = s_a[n * 8 + d];
            float x = -2.0f * av;
            float sp = (x > 0.0f) ? (x + log1pf(expf(-x))) : log1pf(expf(x));
            lpt += -2.0f * (0.6931471805599453f - av - sp);
            out[(b * NN + n) * DACT + d] = tanhf(av);
        }
        s_red[n] = s_lpn[n] + s_logp[n] + lpt;
    }
    __syncthreads();
    if (tid == 0) {
        float m = 0.0f;
        for (int n = 0; n < NN; n++) m += s_red[n];
        out[BB * NN * DACT + b] = m * (1.0f / 32.0f);
    }
}

extern "C" void kernel_launch(void* const* d_in, const int* in_sizes, int n_in,
                              void* d_out, int out_size) {
    const float* obs  = (const float*)d_in[0];
    const float* a0   = (const float*)d_in[1];
    const float* q1W1 = (const float*)d_in[2];
    const float* q1b1 = (const float*)d_in[3];
    const float* q1W2 = (const float*)d_in[4];
    const float* q1b2 = (const float*)d_in[5];
    const float* q1W3 = (const float*)d_in[6];
    const float* q1b3 = (const float*)d_in[7];
    const float* q2W1 = (const float*)d_in[8];
    const float* q2b1 = (const float*)d_in[9];
    const float* q2W2 = (const float*)d_in[10];
    const float* q2b2 = (const float*)d_in[11];
    const float* q2W3 = (const float*)d_in[12];
    const float* q2b3 = (const float*)d_in[13];
    float* out = (float*)d_out;

    transpose_w2<<<HH, HH>>>(q1W2, q2W2);
    svgd_kernel<<<BB, 256>>>(obs, a0,
                             q1W1, q1b1, q1W2, q1b2, q1W3, q1b3,
                             q2W1, q2b1, q2W2, q2b2, q2W3, q2b3,
                             out);
}

// round 6
// speedup vs baseline: 1.9932x; 1.9932x over previous
#include <cuda_runtime.h>
#include <math.h>

#define BB 1024
#define NN 32
#define DOBS 17
#define DACT 6
#define DIN 23
#define HH 256
#define NSTEPS 5

// W2 transposed: row j holds W2[:,j] (k-contiguous) for coalesced BACKWARD reads.
__device__ float g_W2T[2][HH * HH];

__global__ void transpose_w2(const float* __restrict__ w2a,
                             const float* __restrict__ w2b) {
    int j = blockIdx.x;
    int k = threadIdx.x;
    g_W2T[0][j * HH + k] = w2a[k * HH + j];
    g_W2T[1][j * HH + k] = w2b[k * HH + j];
}

__global__ __launch_bounds__(256, 2) void svgd_kernel(
    const float* __restrict__ obs, const float* __restrict__ a0,
    const float* __restrict__ W1a, const float* __restrict__ B1a,
    const float* __restrict__ W2a, const float* __restrict__ B2a,
    const float* __restrict__ W3a, const float* __restrict__ B3a,
    const float* __restrict__ W1b, const float* __restrict__ B1b,
    const float* __restrict__ W2b, const float* __restrict__ B2b,
    const float* __restrict__ W3b, const float* __restrict__ B3b,
    float* __restrict__ out)
{
    __shared__ __align__(16) float s_h[NN * HH];   // h1 / dh2 / dh1 / sort scratch (32 KB)
    __shared__ float s_x[NN * 32];                 // input rows (obs|act), stride 32
    __shared__ float s_d2[NN * NN];
    __shared__ float s_K[NN * NN];                 // ALSO aliased: mask1 bitfield during fwd/bwd
    __shared__ float s_q[2][NN];
    __shared__ __align__(16) float s_s[NN * 8];
    __shared__ float s_a[NN * 8];
    __shared__ float s_logp[NN];
    __shared__ float s_lpn[NN];
    __shared__ float s_red[8 * NN];
    __shared__ float s_gate[NN];

    unsigned* s_m1 = (unsigned*)s_K;               // [net*HH + k] : 32 n-bits each (2 KB of 4 KB)

    const int b = blockIdx.x;
    const int tid = threadIdx.x;
    const int lane = tid & 31;
    const int warp = tid >> 5;
    // GEMM tile mapping: 8 particles x 4 columns per thread
    const int n0   = (warp >> 1) * 8;                 // particle group base
    const int bcol = (((warp & 1) << 5) | lane) * 4;  // column base (lane-consecutive)

    // Load obs + a0
    for (int idx = tid; idx < NN * DOBS; idx += 256) {
        int n = idx / DOBS, k = idx % DOBS;
        s_x[n * 32 + k] = obs[(b * NN + n) * DOBS + k];
    }
    for (int idx = tid; idx < NN * DACT; idx += 256) {
        int n = idx / DACT, d = idx % DACT;
        s_a[n * 8 + d] = a0[(b * NN + n) * DACT + d];
    }
    if (tid < NN) s_logp[tid] = 0.0f;
    __syncthreads();
    if (tid < NN) {
        float ss = 0.0f;
        #pragma unroll
        for (int d = 0; d < DACT; d++) { float v = s_a[tid * 8 + d]; ss += v * v; }
        s_lpn[tid] = -3.0f * logf(6.283185307179586f * 0.3f) - (0.5f / 0.3f) * ss;
    }

    for (int step = 0; step < NSTEPS; ++step) {
        __syncthreads();
        for (int idx = tid; idx < NN * DACT; idx += 256) {
            int n = idx / DACT, d = idx % DACT;
            s_x[n * 32 + DOBS + d] = s_a[n * 8 + d];
        }
        for (int idx = tid; idx < NN * 8; idx += 256) s_s[idx] = 0.0f;
        __syncthreads();

        unsigned m2[2];

        // ================= forward both Q nets =================
        for (int net = 0; net < 2; ++net) {
            const float* W1 = net ? W1b : W1a;
            const float* B1 = net ? B1b : B1a;
            const float* W2 = net ? W2b : W2a;
            const float* B2 = net ? B2b : B2a;
            const float* W3 = net ? W3b : W3a;
            const float* B3 = net ? B3b : B3a;

            // ---- layer1: thread j = hidden unit; coalesced scalar W1 reads ----
            {
                float c[DIN];
                #pragma unroll
                for (int k = 0; k < DIN; k++) c[k] = W1[k * HH + tid];
                float bb1 = B1[tid];
                unsigned mm1 = 0;
                for (int n = 0; n < NN; n++) {
                    float z = bb1;
                    #pragma unroll
                    for (int k = 0; k < DIN; k++) z += s_x[n * 32 + k] * c[k];
                    if (z > 0.0f) mm1 |= (1u << n); else z = 0.0f;
                    s_h[n * HH + tid] = z;
                }
                s_m1[net * HH + tid] = mm1;
            }
            __syncthreads();

            // ---- layer2 GEMM: acc[8n][4j], coalesced W2 row reads ----
            float acc[8][4];
            #pragma unroll
            for (int i = 0; i < 8; i++)
                #pragma unroll
                for (int jc = 0; jc < 4; jc++) acc[i][jc] = 0.0f;

            #pragma unroll 2
            for (int k = 0; k < HH; k += 4) {
                float4 wv0 = *(const float4*)&W2[(k + 0) * HH + bcol];
                float4 wv1 = *(const float4*)&W2[(k + 1) * HH + bcol];
                float4 wv2 = *(const float4*)&W2[(k + 2) * HH + bcol];
                float4 wv3 = *(const float4*)&W2[(k + 3) * HH + bcol];
                #pragma unroll
                for (int i = 0; i < 8; i++) {
                    float4 h4 = *(const float4*)&s_h[(n0 + i) * HH + k];
                    acc[i][0] += h4.x * wv0.x + h4.y * wv1.x + h4.z * wv2.x + h4.w * wv3.x;
                    acc[i][1] += h4.x * wv0.y + h4.y * wv1.y + h4.z * wv2.y + h4.w * wv3.y;
                    acc[i][2] += h4.x * wv0.z + h4.y * wv1.z + h4.z * wv2.z + h4.w * wv3.z;
                    acc[i][3] += h4.x * wv0.w + h4.y * wv1.w + h4.z * wv2.w + h4.w * wv3.w;
                }
            }

            float4 b2v = *(const float4*)&B2[bcol];
            float4 w3v = *(const float4*)&W3[bcol];
            unsigned mm2 = 0;
            float qp[8];
            #pragma unroll
            for (int i = 0; i < 8; i++) {
                float z0 = acc[i][0] + b2v.x;
                float z1 = acc[i][1] + b2v.y;
                float z2 = acc[i][2] + b2v.z;
                float z3 = acc[i][3] + b2v.w;
                float v0 = 0.0f, v1 = 0.0f, v2 = 0.0f, v3 = 0.0f;
                if (z0 > 0.0f) { mm2 |= 1u << (4 * i + 0); v0 = z0 * w3v.x; }
                if (z1 > 0.0f) { mm2 |= 1u << (4 * i + 1); v1 = z1 * w3v.y; }
                if (z2 > 0.0f) { mm2 |= 1u << (4 * i + 2); v2 = z2 * w3v.z; }
                if (z3 > 0.0f) { mm2 |= 1u << (4 * i + 3); v3 = z3 * w3v.w; }
                qp[i] = (v0 + v1) + (v2 + v3);
            }
            m2[net] = mm2;

            // warp-reduce each of the 8 partial q's (sums over this warp's 128 j)
            #pragma unroll
            for (int i = 0; i < 8; i++) {
                float v = qp[i];
                v += __shfl_xor_sync(0xffffffffu, v, 16);
                v += __shfl_xor_sync(0xffffffffu, v, 8);
                v += __shfl_xor_sync(0xffffffffu, v, 4);
                v += __shfl_xor_sync(0xffffffffu, v, 2);
                v += __shfl_xor_sync(0xffffffffu, v, 1);
                if (lane == 0) s_red[warp * 8 + i] = v;
            }
            __syncthreads();
            if (tid < NN) {
                int g = tid >> 3, i = tid & 7;
                s_q[net][tid] = s_red[16 * g + i] + s_red[16 * g + 8 + i] + B3[0];
            }
            __syncthreads();
        }

        if (tid < NN) s_gate[tid] = (s_q[0][tid] <= s_q[1][tid]) ? 1.0f : 0.0f;
        __syncthreads();

        // ================= backward both Q nets (input grad only) =================
        for (int net = 0; net < 2; ++net) {
            const float* W1 = net ? W1b : W1a;
            const float* W3 = net ? W3b : W3a;
            const float* W2T = g_W2T[net];
            float4 w3v = *(const float4*)&W3[bcol];
            unsigned mm2 = m2[net];

            // dh2[n][j] = gate[n]*W3[j]*mask2 (same tile this thread owned in fwd)
            #pragma unroll
            for (int i = 0; i < 8; i++) {
                float gv = s_gate[n0 + i];
                if (net) gv = 1.0f - gv;
                float4 v;
                v.x = (mm2 >> (4 * i + 0)) & 1u ? gv * w3v.x : 0.0f;
                v.y = (mm2 >> (4 * i + 1)) & 1u ? gv * w3v.y : 0.0f;
                v.z = (mm2 >> (4 * i + 2)) & 1u ? gv * w3v.z : 0.0f;
                v.w = (mm2 >> (4 * i + 3)) & 1u ? gv * w3v.w : 0.0f;
                *(float4*)&s_h[(n0 + i) * HH + bcol] = v;
            }
            __syncthreads();

            // dh1[8n][4k(=bcol)] = sum_j dh2[n][j] * W2T[j][k]  (coalesced W2T reads)
            float acc[8][4];
            #pragma unroll
            for (int i = 0; i < 8; i++)
                #pragma unroll
                for (int kc = 0; kc < 4; kc++) acc[i][kc] = 0.0f;

            #pragma unroll 2
            for (int j = 0; j < HH; j += 4) {
                float4 wv0 = *(const float4*)&W2T[(j + 0) * HH + bcol];
                float4 wv1 = *(const float4*)&W2T[(j + 1) * HH + bcol];
                float4 wv2 = *(const float4*)&W2T[(j + 2) * HH + bcol];
                float4 wv3 = *(const float4*)&W2T[(j + 3) * HH + bcol];
                #pragma unroll
                for (int i = 0; i < 8; i++) {
                    float4 d4 = *(const float4*)&s_h[(n0 + i) * HH + j];
                    acc[i][0] += d4.x * wv0.x + d4.y * wv1.x + d4.z * wv2.x + d4.w * wv3.x;
                    acc[i][1] += d4.x * wv0.y + d4.y * wv1.y + d4.z * wv2.y + d4.w * wv3.y;
                    acc[i][2] += d4.x * wv0.z + d4.y * wv1.z + d4.z * wv2.z + d4.w * wv3.z;
                    acc[i][3] += d4.x * wv0.w + d4.y * wv1.w + d4.z * wv2.w + d4.w * wv3.w;
                }
            }

            unsigned u0 = s_m1[net * HH + bcol + 0];
            unsigned u1 = s_m1[net * HH + bcol + 1];
            unsigned u2 = s_m1[net * HH + bcol + 2];
            unsigned u3 = s_m1[net * HH + bcol + 3];
            __syncthreads();  // all dh2 reads complete before overwrite

            #pragma unroll
            for (int i = 0; i < 8; i++) {
                int n = n0 + i;
                float4 v;
                v.x = (u0 >> n) & 1u ? acc[i][0] : 0.0f;
                v.y = (u1 >> n) & 1u ? acc[i][1] : 0.0f;
                v.z = (u2 >> n) & 1u ? acc[i][2] : 0.0f;
                v.w = (u3 >> n) & 1u ? acc[i][3] : 0.0f;
                *(float4*)&s_h[n * HH + bcol] = v;
            }
            __syncthreads();

            // da[n][d] = sum_k dh1[n][k] * W1[17+d][k] -> accumulate into s_s
            if (tid < NN * DACT) {
                int n = tid / DACT, d = tid % DACT;
                const float* w1r = W1 + (DOBS + d) * HH;
                float sum = 0.0f;
                for (int k = 0; k < HH; k += 4) {
                    float4 h4 = *(const float4*)&s_h[n * HH + k];
                    float4 w4 = *(const float4*)&w1r[k];
                    sum += h4.x * w4.x + h4.y * w4.y + h4.z * w4.z + h4.w * w4.w;
                }
                s_s[n * 8 + d] += sum;
            }
            __syncthreads();
        }

        // ================= SVGD update =================
        for (int p = tid; p < NN * NN; p += 256) {
            int i = p >> 5, j = p & 31;
            float ds = 0.0f;
            #pragma unroll
            for (int d = 0; d < DACT; d++) {
                float df = s_a[i * 8 + d] - s_a[j * 8 + d];
                ds += df * df;
            }
            s_d2[p] = ds;
            s_h[p] = ds;  // sort copy
        }
        __syncthreads();

        // bitonic sort of 1024 values (exact median)
        for (int ks = 2; ks <= NN * NN; ks <<= 1) {
            for (int jj = ks >> 1; jj > 0; jj >>= 1) {
                #pragma unroll
                for (int e = 0; e < 4; e++) {
                    int idx = (e << 8) | tid;
                    int ixj = idx ^ jj;
                    if (ixj > idx) {
                        float va = s_h[idx], vb = s_h[ixj];
                        bool up = ((idx & ks) == 0);
                        if ((va > vb) == up) { s_h[idx] = vb; s_h[ixj] = va; }
                    }
                }
                __syncthreads();
            }
        }

        float med = 0.5f * (s_h[511] + s_h[512]);
        float hm = med / logf(33.0f);
        float gamma = 1.0f / (2.0f * hm + 1e-8f);
        for (int p = tid; p < NN * NN; p += 256)
            s_K[p] = expf(-gamma * s_d2[p]);   // overwrites mask bitfield (dead now)
        __syncthreads();

        float anew[DACT];
        float lpdelta = 0.0f;
        if (tid < NN) {
            int i = tid;
            float ai[DACT];
            #pragma unroll
            for (int d = 0; d < DACT; d++) ai[d] = s_a[i * 8 + d];
            float ph[DACT] = {0, 0, 0, 0, 0, 0};
            float t1 = 0.0f, t2s = 0.0f;
            for (int j = 0; j < NN; j++) {
                float Kij = s_K[i * 32 + j];
                float dot = 0.0f;
                #pragma unroll
                for (int d = 0; d < DACT; d++) {
                    float df = ai[d] - s_a[j * 8 + d];
                    float sj = s_s[j * 8 + d];
                    dot += df * sj;
                    ph[d] += Kij * sj + 2.0f * gamma * Kij * df;
                }
                t1 += -2.0f * gamma * Kij * dot;
                float I = (i == j) ? 1.0f : 0.0f;
                t2s += 2.0f * gamma * Kij * s_d2[i * 32 + j] - 6.0f * (Kij - I);
            }
            t1 *= (1.0f / 31.0f);
            float t2 = -2.0f * gamma * t2s * (1.0f / 31.0f);
            lpdelta = 0.05f * (t1 + t2);
            #pragma unroll
            for (int d = 0; d < DACT; d++)
                anew[d] = ai[d] + 0.05f * ph[d] * (1.0f / 32.0f);
        }
        __syncthreads();
        if (tid < NN) {
            s_logp[tid] -= lpdelta;
            #pragma unroll
            for (int d = 0; d < DACT; d++) s_a[tid * 8 + d] = anew[d];
        }
        __syncthreads();
    }

    // ================= finalize =================
    __syncthreads();
    if (tid < NN) {
        int n = tid;
        float lpt = 0.0f;
        #pragma unroll
        for (int d = 0; d < DACT; d++) {
            float av = s_a[n * 8 + d];
            float x = -2.0f * av;
            float sp = (x > 0.0f) ? (x + log1pf(expf(-x))) : log1pf(expf(x));
            lpt += -2.0f * (0.6931471805599453f - av - sp);
            out[(b * NN + n) * DACT + d] = tanhf(av);
        }
        s_red[n] = s_lpn[n] + s_logp[n] + lpt;
    }
    __syncthreads();
    if (tid == 0) {
        float m = 0.0f;
        for (int n = 0; n < NN; n++) m += s_red[n];
        out[BB * NN * DACT + b] = m * (1.0f / 32.0f);
    }
}

extern "C" void kernel_launch(void* const* d_in, const int* in_sizes, int n_in,
                              void* d_out, int out_size) {
    const float* obs  = (const float*)d_in[0];
    const float* a0   = (const float*)d_in[1];
    const float* q1W1 = (const float*)d_in[2];
    const float* q1b1 = (const float*)d_in[3];
    const float* q1W2 = (const float*)d_in[4];
    const float* q1b2 = (const float*)d_in[5];
    const float* q1W3 = (const float*)d_in[6];
    const float* q1b3 = (const float*)d_in[7];
    const float* q2W1 = (const float*)d_in[8];
    const float* q2b1 = (const float*)d_in[9];
    const float* q2W2 = (const float*)d_in[10];
    const float* q2b2 = (const float*)d_in[11];
    const float* q2W3 = (const float*)d_in[12];
    const float* q2b3 = (const float*)d_in[13];
    float* out = (float*)d_out;

    transpose_w2<<<HH, HH>>>(q1W2, q2W2);
    svgd_kernel<<<BB, 256>>>(obs, a0,
                             q1W1, q1b1, q1W2, q1b2, q1W3, q1b3,
                             q2W1, q2b1, q2W2, q2b2, q2W3, q2b3,
                             out);
}

// round 7
// speedup vs baseline: 2.2648x; 1.1362x over previous
#include <cuda_runtime.h>
#include <math.h>

#define BB 1024
#define NN 32
#define DOBS 17
#define DACT 6
#define DIN 23
#define HH 256
#define NSTEPS 5

// W2 transposed: row j holds W2[:,j] (k-contiguous) for coalesced BACKWARD reads.
__device__ float g_W2T[2][HH * HH];

__global__ void transpose_w2(const float* __restrict__ w2a,
                             const float* __restrict__ w2b) {
    int j = blockIdx.x;
    int k = threadIdx.x;
    g_W2T[0][j * HH + k] = w2a[k * HH + j];
    g_W2T[1][j * HH + k] = w2b[k * HH + j];
}

// ---- packed f32x2 helpers (sm_103a) ----
__device__ __forceinline__ unsigned long long fma2(unsigned long long a,
                                                   unsigned long long b,
                                                   unsigned long long c) {
    unsigned long long d;
    asm("fma.rn.f32x2 %0, %1, %2, %3;" : "=l"(d) : "l"(a), "l"(b), "l"(c));
    return d;
}
__device__ __forceinline__ unsigned long long pack2(float x, float y) {
    unsigned long long r;
    asm("mov.b64 %0, {%1, %2};" : "=l"(r) : "f"(x), "f"(y));
    return r;
}
__device__ __forceinline__ void unpack2(unsigned long long v, float& lo, float& hi) {
    asm("mov.b64 {%0, %1}, %2;" : "=f"(lo), "=f"(hi) : "l"(v));
}

__global__ __launch_bounds__(256, 2) void svgd_kernel(
    const float* __restrict__ obs, const float* __restrict__ a0,
    const float* __restrict__ W1a, const float* __restrict__ B1a,
    const float* __restrict__ W2a, const float* __restrict__ B2a,
    const float* __restrict__ W3a, const float* __restrict__ B3a,
    const float* __restrict__ W1b, const float* __restrict__ B1b,
    const float* __restrict__ W2b, const float* __restrict__ B2b,
    const float* __restrict__ W3b, const float* __restrict__ B3b,
    float* __restrict__ out)
{
    __shared__ __align__(16) float s_h[NN * HH];   // h1 / dh2 / dh1 / sort scratch (32 KB)
    __shared__ float s_x[NN * 32];                 // input rows (obs|act), stride 32
    __shared__ float s_d2[NN * NN];
    __shared__ float s_K[NN * NN];                 // aliased: mask1 bitfield during fwd/bwd
    __shared__ float s_q[2][NN];
    __shared__ __align__(16) float s_s[NN * 8];
    __shared__ float s_a[NN * 8];
    __shared__ float s_logp[NN];
    __shared__ float s_lpn[NN];
    __shared__ float s_red[8 * NN];
    __shared__ float s_gate[NN];

    unsigned* s_m1 = (unsigned*)s_K;               // [net*HH + k] : 32 n-bits each

    const int b = blockIdx.x;
    const int tid = threadIdx.x;
    const int lane = tid & 31;
    const int warp = tid >> 5;
    // GEMM tile mapping: 8 particles x 4 columns per thread
    const int n0   = (warp >> 1) * 8;                 // particle group base
    const int bcol = (((warp & 1) << 5) | lane) * 4;  // column base (lane-consecutive)

    // Load obs + a0
    for (int idx = tid; idx < NN * DOBS; idx += 256) {
        int n = idx / DOBS, k = idx % DOBS;
        s_x[n * 32 + k] = obs[(b * NN + n) * DOBS + k];
    }
    for (int idx = tid; idx < NN * DACT; idx += 256) {
        int n = idx / DACT, d = idx % DACT;
        s_a[n * 8 + d] = a0[(b * NN + n) * DACT + d];
    }
    if (tid < NN) s_logp[tid] = 0.0f;
    __syncthreads();
    if (tid < NN) {
        float ss = 0.0f;
        #pragma unroll
        for (int d = 0; d < DACT; d++) { float v = s_a[tid * 8 + d]; ss += v * v; }
        s_lpn[tid] = -3.0f * logf(6.283185307179586f * 0.3f) - (0.5f / 0.3f) * ss;
    }

    for (int step = 0; step < NSTEPS; ++step) {
        __syncthreads();
        for (int idx = tid; idx < NN * DACT; idx += 256) {
            int n = idx / DACT, d = idx % DACT;
            s_x[n * 32 + DOBS + d] = s_a[n * 8 + d];
        }
        for (int idx = tid; idx < NN * 8; idx += 256) s_s[idx] = 0.0f;
        __syncthreads();

        unsigned m2[2];

        // ================= forward both Q nets =================
        for (int net = 0; net < 2; ++net) {
            const float* W1 = net ? W1b : W1a;
            const float* B1 = net ? B1b : B1a;
            const float* W2 = net ? W2b : W2a;
            const float* B2 = net ? B2b : B2a;
            const float* W3 = net ? W3b : W3a;
            const float* B3 = net ? B3b : B3a;

            // ---- layer1: thread j = hidden unit; coalesced scalar W1 reads ----
            {
                float c[DIN];
                #pragma unroll
                for (int k = 0; k < DIN; k++) c[k] = W1[k * HH + tid];
                float bb1 = B1[tid];
                unsigned mm1 = 0;
                for (int n = 0; n < NN; n++) {
                    float z = bb1;
                    #pragma unroll
                    for (int k = 0; k < DIN; k++) z += s_x[n * 32 + k] * c[k];
                    if (z > 0.0f) mm1 |= (1u << n); else z = 0.0f;
                    s_h[n * HH + tid] = z;
                }
                s_m1[net * HH + tid] = mm1;
            }
            __syncthreads();

            // ---- layer2 GEMM (f32x2 over j-pairs): acc2[8n][2 jp] ----
            unsigned long long acc2[8][2];
            #pragma unroll
            for (int i = 0; i < 8; i++) { acc2[i][0] = 0ull; acc2[i][1] = 0ull; }

            #pragma unroll 2
            for (int k = 0; k < HH; k += 4) {
                ulonglong2 w0 = *(const ulonglong2*)&W2[(k + 0) * HH + bcol];
                ulonglong2 w1 = *(const ulonglong2*)&W2[(k + 1) * HH + bcol];
                ulonglong2 w2 = *(const ulonglong2*)&W2[(k + 2) * HH + bcol];
                ulonglong2 w3 = *(const ulonglong2*)&W2[(k + 3) * HH + bcol];
                #pragma unroll
                for (int i = 0; i < 8; i++) {
                    float4 h4 = *(const float4*)&s_h[(n0 + i) * HH + k];
                    unsigned long long hp0 = pack2(h4.x, h4.x);
                    unsigned long long hp1 = pack2(h4.y, h4.y);
                    unsigned long long hp2 = pack2(h4.z, h4.z);
                    unsigned long long hp3 = pack2(h4.w, h4.w);
                    acc2[i][0] = fma2(hp0, w0.x, acc2[i][0]);
                    acc2[i][1] = fma2(hp0, w0.y, acc2[i][1]);
                    acc2[i][0] = fma2(hp1, w1.x, acc2[i][0]);
                    acc2[i][1] = fma2(hp1, w1.y, acc2[i][1]);
                    acc2[i][0] = fma2(hp2, w2.x, acc2[i][0]);
                    acc2[i][1] = fma2(hp2, w2.y, acc2[i][1]);
                    acc2[i][0] = fma2(hp3, w3.x, acc2[i][0]);
                    acc2[i][1] = fma2(hp3, w3.y, acc2[i][1]);
                }
            }

            float4 b2v = *(const float4*)&B2[bcol];
            float4 w3v = *(const float4*)&W3[bcol];
            unsigned mm2 = 0;
            float qp[8];
            #pragma unroll
            for (int i = 0; i < 8; i++) {
                float z0, z1, z2, z3;
                unpack2(acc2[i][0], z0, z1);
                unpack2(acc2[i][1], z2, z3);
                z0 += b2v.x; z1 += b2v.y; z2 += b2v.z; z3 += b2v.w;
                float v0 = 0.0f, v1 = 0.0f, v2 = 0.0f, v3 = 0.0f;
                if (z0 > 0.0f) { mm2 |= 1u << (4 * i + 0); v0 = z0 * w3v.x; }
                if (z1 > 0.0f) { mm2 |= 1u << (4 * i + 1); v1 = z1 * w3v.y; }
                if (z2 > 0.0f) { mm2 |= 1u << (4 * i + 2); v2 = z2 * w3v.z; }
                if (z3 > 0.0f) { mm2 |= 1u << (4 * i + 3); v3 = z3 * w3v.w; }
                qp[i] = (v0 + v1) + (v2 + v3);
            }
            m2[net] = mm2;

            // warp-reduce each of the 8 partial q's
            #pragma unroll
            for (int i = 0; i < 8; i++) {
                float v = qp[i];
                v += __shfl_xor_sync(0xffffffffu, v, 16);
                v += __shfl_xor_sync(0xffffffffu, v, 8);
                v += __shfl_xor_sync(0xffffffffu, v, 4);
                v += __shfl_xor_sync(0xffffffffu, v, 2);
                v += __shfl_xor_sync(0xffffffffu, v, 1);
                if (lane == 0) s_red[warp * 8 + i] = v;
            }
            __syncthreads();
            if (tid < NN) {
                int g = tid >> 3, i = tid & 7;
                s_q[net][tid] = s_red[16 * g + i] + s_red[16 * g + 8 + i] + B3[0];
            }
            __syncthreads();
        }

        if (tid < NN) s_gate[tid] = (s_q[0][tid] <= s_q[1][tid]) ? 1.0f : 0.0f;
        __syncthreads();

        // ================= backward both Q nets (input grad only) =================
        for (int net = 0; net < 2; ++net) {
            const float* W1 = net ? W1b : W1a;
            const float* W3 = net ? W3b : W3a;
            const float* W2T = g_W2T[net];
            float4 w3v = *(const float4*)&W3[bcol];
            unsigned mm2 = m2[net];

            // dh2[n][j] = gate[n]*W3[j]*mask2 (same tile this thread owned in fwd)
            #pragma unroll
            for (int i = 0; i < 8; i++) {
                float gv = s_gate[n0 + i];
                if (net) gv = 1.0f - gv;
                float4 v;
                v.x = (mm2 >> (4 * i + 0)) & 1u ? gv * w3v.x : 0.0f;
                v.y = (mm2 >> (4 * i + 1)) & 1u ? gv * w3v.y : 0.0f;
                v.z = (mm2 >> (4 * i + 2)) & 1u ? gv * w3v.z : 0.0f;
                v.w = (mm2 >> (4 * i + 3)) & 1u ? gv * w3v.w : 0.0f;
                *(float4*)&s_h[(n0 + i) * HH + bcol] = v;
            }
            __syncthreads();

            // dh1[8n][4k] = sum_j dh2[n][j] * W2T[j][k]  (f32x2 over k-pairs)
            unsigned long long acc2[8][2];
            #pragma unroll
            for (int i = 0; i < 8; i++) { acc2[i][0] = 0ull; acc2[i][1] = 0ull; }

            #pragma unroll 2
            for (int j = 0; j < HH; j += 4) {
                ulonglong2 w0 = *(const ulonglong2*)&W2T[(j + 0) * HH + bcol];
                ulonglong2 w1 = *(const ulonglong2*)&W2T[(j + 1) * HH + bcol];
                ulonglong2 w2 = *(const ulonglong2*)&W2T[(j + 2) * HH + bcol];
                ulonglong2 w3 = *(const ulonglong2*)&W2T[(j + 3) * HH + bcol];
                #pragma unroll
                for (int i = 0; i < 8; i++) {
                    float4 d4 = *(const float4*)&s_h[(n0 + i) * HH + j];
                    unsigned long long dp0 = pack2(d4.x, d4.x);
                    unsigned long long dp1 = pack2(d4.y, d4.y);
                    unsigned long long dp2 = pack2(d4.z, d4.z);
                    unsigned long long dp3 = pack2(d4.w, d4.w);
                    acc2[i][0] = fma2(dp0, w0.x, acc2[i][0]);
                    acc2[i][1] = fma2(dp0, w0.y, acc2[i][1]);
                    acc2[i][0] = fma2(dp1, w1.x, acc2[i][0]);
                    acc2[i][1] = fma2(dp1, w1.y, acc2[i][1]);
                    acc2[i][0] = fma2(dp2, w2.x, acc2[i][0]);
                    acc2[i][1] = fma2(dp2, w2.y, acc2[i][1]);
                    acc2[i][0] = fma2(dp3, w3.x, acc2[i][0]);
                    acc2[i][1] = fma2(dp3, w3.y, acc2[i][1]);
                }
            }

            unsigned u0 = s_m1[net * HH + bcol + 0];
            unsigned u1 = s_m1[net * HH + bcol + 1];
            unsigned u2 = s_m1[net * HH + bcol + 2];
            unsigned u3 = s_m1[net * HH + bcol + 3];
            __syncthreads();  // all dh2 reads complete before overwrite

            #pragma unroll
            for (int i = 0; i < 8; i++) {
                int n = n0 + i;
                float a0v, a1v, a2v, a3v;
                unpack2(acc2[i][0], a0v, a1v);
                unpack2(acc2[i][1], a2v, a3v);
                float4 v;
                v.x = (u0 >> n) & 1u ? a0v : 0.0f;
                v.y = (u1 >> n) & 1u ? a1v : 0.0f;
                v.z = (u2 >> n) & 1u ? a2v : 0.0f;
                v.w = (u3 >> n) & 1u ? a3v : 0.0f;
                *(float4*)&s_h[n * HH + bcol] = v;
            }
            __syncthreads();

            // da[n][d] = sum_k dh1[n][k] * W1[17+d][k] -> accumulate into s_s
            if (tid < NN * DACT) {
                int n = tid / DACT, d = tid % DACT;
                const float* w1r = W1 + (DOBS + d) * HH;
                float sum = 0.0f;
                for (int k = 0; k < HH; k += 4) {
                    float4 h4 = *(const float4*)&s_h[n * HH + k];
                    float4 w4 = *(const float4*)&w1r[k];
                    sum += h4.x * w4.x + h4.y * w4.y + h4.z * w4.z + h4.w * w4.w;
                }
                s_s[n * 8 + d] += sum;
            }
            __syncthreads();
        }

        // ================= SVGD update =================
        for (int p = tid; p < NN * NN; p += 256) {
            int i = p >> 5, j = p & 31;
            float ds = 0.0f;
            #pragma unroll
            for (int d = 0; d < DACT; d++) {
                float df = s_a[i * 8 + d] - s_a[j * 8 + d];
                ds += df * df;
            }
            s_d2[p] = ds;
            s_h[p] = ds;  // sort copy
        }
        __syncthreads();

        // bitonic sort of 1024 values (exact median)
        for (int ks = 2; ks <= NN * NN; ks <<= 1) {
            for (int jj = ks >> 1; jj > 0; jj >>= 1) {
                #pragma unroll
                for (int e = 0; e < 4; e++) {
                    int idx = (e << 8) | tid;
                    int ixj = idx ^ jj;
                    if (ixj > idx) {
                        float va = s_h[idx], vb = s_h[ixj];
                        bool up = ((idx & ks) == 0);
                        if ((va > vb) == up) { s_h[idx] = vb; s_h[ixj] = va; }
                    }
                }
                __syncthreads();
            }
        }

        float med = 0.5f * (s_h[511] + s_h[512]);
        float hm = med / logf(33.0f);
        float gamma = 1.0f / (2.0f * hm + 1e-8f);
        for (int p = tid; p < NN * NN; p += 256)
            s_K[p] = expf(-gamma * s_d2[p]);   // overwrites mask bitfield (dead now)
        __syncthreads();

        float anew[DACT];
        float lpdelta = 0.0f;
        if (tid < NN) {
            int i = tid;
            float ai[DACT];
            #pragma unroll
            for (int d = 0; d < DACT; d++) ai[d] = s_a[i * 8 + d];
            float ph[DACT] = {0, 0, 0, 0, 0, 0};
            float t1 = 0.0f, t2s = 0.0f;
            for (int j = 0; j < NN; j++) {
                float Kij = s_K[i * 32 + j];
                float dot = 0.0f;
                #pragma unroll
                for (int d = 0; d < DACT; d++) {
                    float df = ai[d] - s_a[j * 8 + d];
                    float sj = s_s[j * 8 + d];
                    dot += df * sj;
                    ph[d] += Kij * sj + 2.0f * gamma * Kij * df;
                }
                t1 += -2.0f * gamma * Kij * dot;
                float I = (i == j) ? 1.0f : 0.0f;
                t2s += 2.0f * gamma * Kij * s_d2[i * 32 + j] - 6.0f * (Kij - I);
            }
            t1 *= (1.0f / 31.0f);
            float t2 = -2.0f * gamma * t2s * (1.0f / 31.0f);
            lpdelta = 0.05f * (t1 + t2);
            #pragma unroll
            for (int d = 0; d < DACT; d++)
                anew[d] = ai[d] + 0.05f * ph[d] * (1.0f / 32.0f);
        }
        __syncthreads();
        if (tid < NN) {
            s_logp[tid] -= lpdelta;
            #pragma unroll
            for (int d = 0; d < DACT; d++) s_a[tid * 8 + d] = anew[d];
        }
        __syncthreads();
    }

    // ================= finalize =================
    __syncthreads();
    if (tid < NN) {
        int n = tid;
        float lpt = 0.0f;
        #pragma unroll
        for (int d = 0; d < DACT; d++) {
            float av = s_a[n * 8 + d];
            float x = -2.0f * av;
            float sp = (x > 0.0f) ? (x + log1pf(expf(-x))) : log1pf(expf(x));
            lpt += -2.0f * (0.6931471805599453f - av - sp);
            out[(b * NN + n) * DACT + d] = tanhf(av);
        }
        s_red[n] = s_lpn[n] + s_logp[n] + lpt;
    }
    __syncthreads();
    if (tid == 0) {
        float m = 0.0f;
        for (int n = 0; n < NN; n++) m += s_red[n];
        out[BB * NN * DACT + b] = m * (1.0f / 32.0f);
    }
}

extern "C" void kernel_launch(void* const* d_in, const int* in_sizes, int n_in,
                              void* d_out, int out_size) {
    const float* obs  = (const float*)d_in[0];
    const float* a0   = (const float*)d_in[1];
    const float* q1W1 = (const float*)d_in[2];
    const float* q1b1 = (const float*)d_in[3];
    const float* q1W2 = (const float*)d_in[4];
    const float* q1b2 = (const float*)d_in[5];
    const float* q1W3 = (const float*)d_in[6];
    const float* q1b3 = (const float*)d_in[7];
    const float* q2W1 = (const float*)d_in[8];
    const float* q2b1 = (const float*)d_in[9];
    const float* q2W2 = (const float*)d_in[10];
    const float* q2b2 = (const float*)d_in[11];
    const float* q2W3 = (const float*)d_in[12];
    const float* q2b3 = (const float*)d_in[13];
    float* out = (float*)d_out;

    transpose_w2<<<HH, HH>>>(q1W2, q2W2);
    svgd_kernel<<<BB, 256>>>(obs, a0,
                             q1W1, q1b1, q1W2, q1b2, q1W3, q1b3,
                             q2W1, q2b1, q2W2, q2b2, q2W3, q2b3,
                             out);
}

// round 8
// speedup vs baseline: 2.4406x; 1.0776x over previous
#include <cuda_runtime.h>
#include <math.h>

#define BB 1024
#define NN 32
#define DOBS 17
#define DACT 6
#define DIN 23
#define HH 256
#define NSTEPS 5
#define HPAD 260   // padded s_h row stride (words): 16B-aligned, banks spread 4n

// W2 transposed: row j holds W2[:,j] (k-contiguous) for coalesced BACKWARD reads.
__device__ float g_W2T[2][HH * HH];

__global__ void transpose_w2(const float* __restrict__ w2a,
                             const float* __restrict__ w2b) {
    int j = blockIdx.x;
    int k = threadIdx.x;
    g_W2T[0][j * HH + k] = w2a[k * HH + j];
    g_W2T[1][j * HH + k] = w2b[k * HH + j];
}

// ---- packed f32x2 helpers (sm_103a) ----
__device__ __forceinline__ unsigned long long fma2(unsigned long long a,
                                                   unsigned long long b,
                                                   unsigned long long c) {
    unsigned long long d;
    asm("fma.rn.f32x2 %0, %1, %2, %3;" : "=l"(d) : "l"(a), "l"(b), "l"(c));
    return d;
}
__device__ __forceinline__ unsigned long long pack2(float x, float y) {
    unsigned long long r;
    asm("mov.b64 %0, {%1, %2};" : "=l"(r) : "f"(x), "f"(y));
    return r;
}
__device__ __forceinline__ void unpack2(unsigned long long v, float& lo, float& hi) {
    asm("mov.b64 {%0, %1}, %2;" : "=f"(lo), "=f"(hi) : "l"(v));
}

__global__ __launch_bounds__(256, 2) void svgd_kernel(
    const float* __restrict__ obs, const float* __restrict__ a0,
    const float* __restrict__ W1a, const float* __restrict__ B1a,
    const float* __restrict__ W2a, const float* __restrict__ B2a,
    const float* __restrict__ W3a, const float* __restrict__ B3a,
    const float* __restrict__ W1b, const float* __restrict__ B1b,
    const float* __restrict__ W2b, const float* __restrict__ B2b,
    const float* __restrict__ W3b, const float* __restrict__ B3b,
    float* __restrict__ out)
{
    __shared__ __align__(16) float s_h[NN * HPAD];  // h1 / dh2 / dh1 / sort scratch
    __shared__ float s_x[NN * 32];                  // input rows (obs|act), stride 32
    __shared__ float s_d2[NN * NN];
    __shared__ float s_K[NN * NN];                  // aliased: mask1 + mask2 during fwd/bwd
    __shared__ float s_q[2][NN];
    __shared__ __align__(16) float s_s[NN * 8];
    __shared__ float s_a[NN * 8];
    __shared__ float s_logp[NN];
    __shared__ float s_lpn[NN];
    __shared__ float s_red[64];
    __shared__ int s_orig[NN];                      // slot -> original particle
    __shared__ int s_cnt1;                          // # particles selecting net0

    unsigned* s_m1  = (unsigned*)s_K;               // words [0,512): [net*HH + k] bit n
    unsigned* s_m2u = ((unsigned*)s_K) + 512;       // words [512,1024): [net*256 + warp*32 + lane]

    const int b = blockIdx.x;
    const int tid = threadIdx.x;
    const int lane = tid & 31;
    const int warp = tid >> 5;
    // GEMM tile mapping: 8 particles x 4 columns per thread
    const int n0    = (warp >> 1) * 8;                 // particle/slot group base
    const int hhalf = warp & 1;                        // column half
    const int bcol  = ((hhalf << 5) | lane) * 4;       // column base (lane-consecutive)

    // Load obs + a0
    for (int idx = tid; idx < NN * DOBS; idx += 256) {
        int n = idx / DOBS, k = idx % DOBS;
        s_x[n * 32 + k] = obs[(b * NN + n) * DOBS + k];
    }
    for (int idx = tid; idx < NN * DACT; idx += 256) {
        int n = idx / DACT, d = idx % DACT;
        s_a[n * 8 + d] = a0[(b * NN + n) * DACT + d];
    }
    if (tid < NN) s_logp[tid] = 0.0f;
    __syncthreads();
    if (tid < NN) {
        float ss = 0.0f;
        #pragma unroll
        for (int d = 0; d < DACT; d++) { float v = s_a[tid * 8 + d]; ss += v * v; }
        s_lpn[tid] = -3.0f * logf(6.283185307179586f * 0.3f) - (0.5f / 0.3f) * ss;
    }

    for (int step = 0; step < NSTEPS; ++step) {
        __syncthreads();
        for (int idx = tid; idx < NN * DACT; idx += 256) {
            int n = idx / DACT, d = idx % DACT;
            s_x[n * 32 + DOBS + d] = s_a[n * 8 + d];
        }
        __syncthreads();

        // ================= forward both Q nets =================
        for (int net = 0; net < 2; ++net) {
            const float* W1 = net ? W1b : W1a;
            const float* B1 = net ? B1b : B1a;
            const float* W2 = net ? W2b : W2a;
            const float* B2 = net ? B2b : B2a;
            const float* W3 = net ? W3b : W3a;
            const float* B3 = net ? B3b : B3a;

            // ---- layer1: thread j = hidden unit ----
            {
                float c[DIN];
                #pragma unroll
                for (int k = 0; k < DIN; k++) c[k] = W1[k * HH + tid];
                float bb1 = B1[tid];
                unsigned mm1 = 0;
                for (int n = 0; n < NN; n++) {
                    float z = bb1;
                    #pragma unroll
                    for (int k = 0; k < DIN; k++) z += s_x[n * 32 + k] * c[k];
                    if (z > 0.0f) mm1 |= (1u << n); else z = 0.0f;
                    s_h[n * HPAD + tid] = z;
                }
                s_m1[net * HH + tid] = mm1;
            }
            __syncthreads();

            // ---- layer2 GEMM (f32x2 over j-pairs) ----
            unsigned long long acc2[8][2];
            #pragma unroll
            for (int i = 0; i < 8; i++) { acc2[i][0] = 0ull; acc2[i][1] = 0ull; }

            #pragma unroll 2
            for (int k = 0; k < HH; k += 4) {
                ulonglong2 w0 = *(const ulonglong2*)&W2[(k + 0) * HH + bcol];
                ulonglong2 w1 = *(const ulonglong2*)&W2[(k + 1) * HH + bcol];
                ulonglong2 w2 = *(const ulonglong2*)&W2[(k + 2) * HH + bcol];
                ulonglong2 w3 = *(const ulonglong2*)&W2[(k + 3) * HH + bcol];
                #pragma unroll
                for (int i = 0; i < 8; i++) {
                    float4 h4 = *(const float4*)&s_h[(n0 + i) * HPAD + k];
                    unsigned long long hp0 = pack2(h4.x, h4.x);
                    unsigned long long hp1 = pack2(h4.y, h4.y);
                    unsigned long long hp2 = pack2(h4.z, h4.z);
                    unsigned long long hp3 = pack2(h4.w, h4.w);
                    acc2[i][0] = fma2(hp0, w0.x, acc2[i][0]);
                    acc2[i][1] = fma2(hp0, w0.y, acc2[i][1]);
                    acc2[i][0] = fma2(hp1, w1.x, acc2[i][0]);
                    acc2[i][1] = fma2(hp1, w1.y, acc2[i][1]);
                    acc2[i][0] = fma2(hp2, w2.x, acc2[i][0]);
                    acc2[i][1] = fma2(hp2, w2.y, acc2[i][1]);
                    acc2[i][0] = fma2(hp3, w3.x, acc2[i][0]);
                    acc2[i][1] = fma2(hp3, w3.y, acc2[i][1]);
                }
            }

            float4 b2v = *(const float4*)&B2[bcol];
            float4 w3v = *(const float4*)&W3[bcol];
            unsigned mm2 = 0;
            float qp[8];
            #pragma unroll
            for (int i = 0; i < 8; i++) {
                float z0, z1, z2, z3;
                unpack2(acc2[i][0], z0, z1);
                unpack2(acc2[i][1], z2, z3);
                z0 += b2v.x; z1 += b2v.y; z2 += b2v.z; z3 += b2v.w;
                float v0 = 0.0f, v1 = 0.0f, v2 = 0.0f, v3 = 0.0f;
                if (z0 > 0.0f) { mm2 |= 1u << (4 * i + 0); v0 = z0 * w3v.x; }
                if (z1 > 0.0f) { mm2 |= 1u << (4 * i + 1); v1 = z1 * w3v.y; }
                if (z2 > 0.0f) { mm2 |= 1u << (4 * i + 2); v2 = z2 * w3v.z; }
                if (z3 > 0.0f) { mm2 |= 1u << (4 * i + 3); v3 = z3 * w3v.w; }
                qp[i] = (v0 + v1) + (v2 + v3);
            }
            s_m2u[net * 256 + warp * 32 + lane] = mm2;

            #pragma unroll
            for (int i = 0; i < 8; i++) {
                float v = qp[i];
                v += __shfl_xor_sync(0xffffffffu, v, 16);
                v += __shfl_xor_sync(0xffffffffu, v, 8);
                v += __shfl_xor_sync(0xffffffffu, v, 4);
                v += __shfl_xor_sync(0xffffffffu, v, 2);
                v += __shfl_xor_sync(0xffffffffu, v, 1);
                if (lane == 0) s_red[warp * 8 + i] = v;
            }
            __syncthreads();
            if (tid < NN) {
                int g = tid >> 3, i = tid & 7;
                s_q[net][tid] = s_red[16 * g + i] + s_red[16 * g + 8 + i] + B3[0];
            }
            __syncthreads();
        }

        // ---- gate + stable partition permutation (net0-selected first) ----
        if (tid < NN) {
            bool g = s_q[0][tid] <= s_q[1][tid];
            unsigned ball = __ballot_sync(0xffffffffu, g);
            int c1 = __popc(ball);
            int below = __popc(ball & ((1u << tid) - 1u));
            int slot = g ? below : (c1 + (tid - below));
            s_orig[slot] = tid;
            if (tid == 0) s_cnt1 = c1;
        }
        __syncthreads();

        // ================= backward (single pass, per-particle net select) =================
        {
            const int cnt1 = s_cnt1;
            const float* W2Ta = g_W2T[0];
            const float* W2Tb = g_W2T[1];
            float4 w3av = *(const float4*)&W3a[bcol];
            float4 w3bv = *(const float4*)&W3b[bcol];

            int og[8];
            #pragma unroll
            for (int i = 0; i < 8; i++) og[i] = s_orig[n0 + i];

            // dh2[slot][j] = mask2_sel * W3_sel[j]
            #pragma unroll
            for (int i = 0; i < 8; i++) {
                int o = og[i];
                bool sA = (n0 + i) < cnt1;
                unsigned mm = s_m2u[(sA ? 0 : 256) + ((o >> 3) * 2 + hhalf) * 32 + lane];
                float4 wv = sA ? w3av : w3bv;
                int bb = (o & 7) * 4;
                float4 v;
                v.x = (mm >> (bb + 0)) & 1u ? wv.x : 0.0f;
                v.y = (mm >> (bb + 1)) & 1u ? wv.y : 0.0f;
                v.z = (mm >> (bb + 2)) & 1u ? wv.z : 0.0f;
                v.w = (mm >> (bb + 3)) & 1u ? wv.w : 0.0f;
                *(float4*)&s_h[(n0 + i) * HPAD + bcol] = v;
            }
            __syncthreads();

            // dh1[slot][4k] = sum_j dh2[slot][j] * W2T_sel[j][k]
            unsigned long long acc2[8][2];
            #pragma unroll
            for (int i = 0; i < 8; i++) { acc2[i][0] = 0ull; acc2[i][1] = 0ull; }

            if (n0 + 8 <= cnt1 || n0 >= cnt1) {
                // pure group: one net's weights only
                const float* W2T = (n0 + 8 <= cnt1) ? W2Ta : W2Tb;
                #pragma unroll 2
                for (int j = 0; j < HH; j += 4) {
                    ulonglong2 w0 = *(const ulonglong2*)&W2T[(j + 0) * HH + bcol];
                    ulonglong2 w1 = *(const ulonglong2*)&W2T[(j + 1) * HH + bcol];
                    ulonglong2 w2 = *(const ulonglong2*)&W2T[(j + 2) * HH + bcol];
                    ulonglong2 w3 = *(const ulonglong2*)&W2T[(j + 3) * HH + bcol];
                    #pragma unroll
                    for (int i = 0; i < 8; i++) {
                        float4 d4 = *(const float4*)&s_h[(n0 + i) * HPAD + j];
                        unsigned long long dp0 = pack2(d4.x, d4.x);
                        unsigned long long dp1 = pack2(d4.y, d4.y);
                        unsigned long long dp2 = pack2(d4.z, d4.z);
                        unsigned long long dp3 = pack2(d4.w, d4.w);
                        acc2[i][0] = fma2(dp0, w0.x, acc2[i][0]);
                        acc2[i][1] = fma2(dp0, w0.y, acc2[i][1]);
                        acc2[i][0] = fma2(dp1, w1.x, acc2[i][0]);
                        acc2[i][1] = fma2(dp1, w1.y, acc2[i][1]);
                        acc2[i][0] = fma2(dp2, w2.x, acc2[i][0]);
                        acc2[i][1] = fma2(dp2, w2.y, acc2[i][1]);
                        acc2[i][0] = fma2(dp3, w3.x, acc2[i][0]);
                        acc2[i][1] = fma2(dp3, w3.y, acc2[i][1]);
                    }
                }
            } else {
                // mixed boundary group (at most one per CTA): predicated per-net sub-passes
                #pragma unroll 2
                for (int j = 0; j < HH; j += 4) {
                    {
                        ulonglong2 w0 = *(const ulonglong2*)&W2Ta[(j + 0) * HH + bcol];
                        ulonglong2 w1 = *(const ulonglong2*)&W2Ta[(j + 1) * HH + bcol];
                        ulonglong2 w2 = *(const ulonglong2*)&W2Ta[(j + 2) * HH + bcol];
                        ulonglong2 w3 = *(const ulonglong2*)&W2Ta[(j + 3) * HH + bcol];
                        #pragma unroll
                        for (int i = 0; i < 8; i++) {
                            if (n0 + i < cnt1) {
                                float4 d4 = *(const float4*)&s_h[(n0 + i) * HPAD + j];
                                unsigned long long dp0 = pack2(d4.x, d4.x);
                                unsigned long long dp1 = pack2(d4.y, d4.y);
                                unsigned long long dp2 = pack2(d4.z, d4.z);
                                unsigned long long dp3 = pack2(d4.w, d4.w);
                                acc2[i][0] = fma2(dp0, w0.x, acc2[i][0]);
                                acc2[i][1] = fma2(dp0, w0.y, acc2[i][1]);
                                acc2[i][0] = fma2(dp1, w1.x, acc2[i][0]);
                                acc2[i][1] = fma2(dp1, w1.y, acc2[i][1]);
                                acc2[i][0] = fma2(dp2, w2.x, acc2[i][0]);
                                acc2[i][1] = fma2(dp2, w2.y, acc2[i][1]);
                                acc2[i][0] = fma2(dp3, w3.x, acc2[i][0]);
                                acc2[i][1] = fma2(dp3, w3.y, acc2[i][1]);
                            }
                        }
                    }
                    {
                        ulonglong2 w0 = *(const ulonglong2*)&W2Tb[(j + 0) * HH + bcol];
                        ulonglong2 w1 = *(const ulonglong2*)&W2Tb[(j + 1) * HH + bcol];
                        ulonglong2 w2 = *(const ulonglong2*)&W2Tb[(j + 2) * HH + bcol];
                        ulonglong2 w3 = *(const ulonglong2*)&W2Tb[(j + 3) * HH + bcol];
                        #pragma unroll
                        for (int i = 0; i < 8; i++) {
                            if (n0 + i >= cnt1) {
                                float4 d4 = *(const float4*)&s_h[(n0 + i) * HPAD + j];
                                unsigned long long dp0 = pack2(d4.x, d4.x);
                                unsigned long long dp1 = pack2(d4.y, d4.y);
                                unsigned long long dp2 = pack2(d4.z, d4.z);
                                unsigned long long dp3 = pack2(d4.w, d4.w);
                                acc2[i][0] = fma2(dp0, w0.x, acc2[i][0]);
                                acc2[i][1] = fma2(dp0, w0.y, acc2[i][1]);
                                acc2[i][0] = fma2(dp1, w1.x, acc2[i][0]);
                                acc2[i][1] = fma2(dp1, w1.y, acc2[i][1]);
                                acc2[i][0] = fma2(dp2, w2.x, acc2[i][0]);
                                acc2[i][1] = fma2(dp2, w2.y, acc2[i][1]);
                                acc2[i][0] = fma2(dp3, w3.x, acc2[i][0]);
                                acc2[i][1] = fma2(dp3, w3.y, acc2[i][1]);
                            }
                        }
                    }
                }
            }

            // relu mask1 (selected net, original-particle bit) and dh1 write
            unsigned ua0 = s_m1[bcol + 0], ua1 = s_m1[bcol + 1];
            unsigned ua2 = s_m1[bcol + 2], ua3 = s_m1[bcol + 3];
            unsigned ub0 = s_m1[HH + bcol + 0], ub1 = s_m1[HH + bcol + 1];
            unsigned ub2 = s_m1[HH + bcol + 2], ub3 = s_m1[HH + bcol + 3];
            __syncthreads();  // all dh2 reads complete before overwrite

            #pragma unroll
            for (int i = 0; i < 8; i++) {
                int o = og[i];
                bool sA = (n0 + i) < cnt1;
                unsigned m0 = sA ? ua0 : ub0;
                unsigned m1v = sA ? ua1 : ub1;
                unsigned m2v = sA ? ua2 : ub2;
                unsigned m3v = sA ? ua3 : ub3;
                float a0v, a1v, a2v, a3v;
                unpack2(acc2[i][0], a0v, a1v);
                unpack2(acc2[i][1], a2v, a3v);
                float4 v;
                v.x = (m0 >> o) & 1u ? a0v : 0.0f;
                v.y = (m1v >> o) & 1u ? a1v : 0.0f;
                v.z = (m2v >> o) & 1u ? a2v : 0.0f;
                v.w = (m3v >> o) & 1u ? a3v : 0.0f;
                *(float4*)&s_h[(n0 + i) * HPAD + bcol] = v;
            }
            __syncthreads();

            // da[orig][d] = sum_k dh1[slot][k] * W1_sel[17+d][k]
            if (tid < NN * DACT) {
                int sl = tid / DACT, d = tid % DACT;
                int o = s_orig[sl];
                const float* W1sel = (sl < cnt1) ? W1a : W1b;
                const float* w1r = W1sel + (DOBS + d) * HH;
                float sum = 0.0f;
                for (int k = 0; k < HH; k += 4) {
                    float4 h4 = *(const float4*)&s_h[sl * HPAD + k];
                    float4 w4 = *(const float4*)&w1r[k];
                    sum += h4.x * w4.x + h4.y * w4.y + h4.z * w4.z + h4.w * w4.w;
                }
                s_s[o * 8 + d] = sum;
            }
            __syncthreads();
        }

        // ================= SVGD update =================
        for (int p = tid; p < NN * NN; p += 256) {
            int i = p >> 5, j = p & 31;
            float ds = 0.0f;
            #pragma unroll
            for (int d = 0; d < DACT; d++) {
                float df = s_a[i * 8 + d] - s_a[j * 8 + d];
                ds += df * df;
            }
            s_d2[p] = ds;
            s_h[p] = ds;  // sort copy
        }
        __syncthreads();

        // bitonic sort of 1024 values (exact median)
        for (int ks = 2; ks <= NN * NN; ks <<= 1) {
            for (int jj = ks >> 1; jj > 0; jj >>= 1) {
                #pragma unroll
                for (int e = 0; e < 4; e++) {
                    int idx = (e << 8) | tid;
                    int ixj = idx ^ jj;
                    if (ixj > idx) {
                        float va = s_h[idx], vb = s_h[ixj];
                        bool up = ((idx & ks) == 0);
                        if ((va > vb) == up) { s_h[idx] = vb; s_h[ixj] = va; }
                    }
                }
                __syncthreads();
            }
        }

        float med = 0.5f * (s_h[511] + s_h[512]);
        float hm = med / logf(33.0f);
        float gamma = 1.0f / (2.0f * hm + 1e-8f);
        for (int p = tid; p < NN * NN; p += 256)
            s_K[p] = expf(-gamma * s_d2[p]);   // overwrites mask bitfields (dead now)
        __syncthreads();

        float anew[DACT];
        float lpdelta = 0.0f;
        if (tid < NN) {
            int i = tid;
            float ai[DACT];
            #pragma unroll
            for (int d = 0; d < DACT; d++) ai[d] = s_a[i * 8 + d];
            float ph[DACT] = {0, 0, 0, 0, 0, 0};
            float t1 = 0.0f, t2s = 0.0f;
            for (int j = 0; j < NN; j++) {
                float Kij = s_K[i * 32 + j];
                float dot = 0.0f;
                #pragma unroll
                for (int d = 0; d < DACT; d++) {
                    float df = ai[d] - s_a[j * 8 + d];
                    float sj = s_s[j * 8 + d];
                    dot += df * sj;
                    ph[d] += Kij * sj + 2.0f * gamma * Kij * df;
                }
                t1 += -2.0f * gamma * Kij * dot;
                float I = (i == j) ? 1.0f : 0.0f;
                t2s += 2.0f * gamma * Kij * s_d2[i * 32 + j] - 6.0f * (Kij - I);
            }
            t1 *= (1.0f / 31.0f);
            float t2 = -2.0f * gamma * t2s * (1.0f / 31.0f);
            lpdelta = 0.05f * (t1 + t2);
            #pragma unroll
            for (int d = 0; d < DACT; d++)
                anew[d] = ai[d] + 0.05f * ph[d] * (1.0f / 32.0f);
        }
        __syncthreads();
        if (tid < NN) {
            s_logp[tid] -= lpdelta;
            #pragma unroll
            for (int d = 0; d < DACT; d++) s_a[tid * 8 + d] = anew[d];
        }
        __syncthreads();
    }

    // ================= finalize =================
    __syncthreads();
    if (tid < NN) {
        int n = tid;
        float lpt = 0.0f;
        #pragma unroll
        for (int d = 0; d < DACT; d++) {
            float av = s_a[n * 8 + d];
            float x = -2.0f * av;
            float sp = (x > 0.0f) ? (x + log1pf(expf(-x))) : log1pf(expf(x));
            lpt += -2.0f * (0.6931471805599453f - av - sp);
            out[(b * NN + n) * DACT + d] = tanhf(av);
        }
        s_red[n] = s_lpn[n] + s_logp[n] + lpt;
    }
    __syncthreads();
    if (tid == 0) {
        float m = 0.0f;
        for (int n = 0; n < NN; n++) m += s_red[n];
        out[BB * NN * DACT + b] = m * (1.0f / 32.0f);
    }
}

extern "C" void kernel_launch(void* const* d_in, const int* in_sizes, int n_in,
                              void* d_out, int out_size) {
    const float* obs  = (const float*)d_in[0];
    const float* a0   = (const float*)d_in[1];
    const float* q1W1 = (const float*)d_in[2];
    const float* q1b1 = (const float*)d_in[3];
    const float* q1W2 = (const float*)d_in[4];
    const float* q1b2 = (const float*)d_in[5];
    const float* q1W3 = (const float*)d_in[6];
    const float* q1b3 = (const float*)d_in[7];
    const float* q2W1 = (const float*)d_in[8];
    const float* q2b1 = (const float*)d_in[9];
    const float* q2W2 = (const float*)d_in[10];
    const float* q2b2 = (const float*)d_in[11];
    const float* q2W3 = (const float*)d_in[12];
    const float* q2b3 = (const float*)d_in[13];
    float* out = (float*)d_out;

    transpose_w2<<<HH, HH>>>(q1W2, q2W2);
    svgd_kernel<<<BB, 256>>>(obs, a0,
                             q1W1, q1b1, q1W2, q1b2, q1W3, q1b3,
                             q2W1, q2b1, q2W2, q2b2, q2W3, q2b3,
                             out);
}

// round 9
// speedup vs baseline: 2.5250x; 1.0346x over previous
#include <cuda_runtime.h>
#include <math.h>

#define BB 1024
#define NN 32
#define DOBS 17
#define DACT 6
#define DIN 23
#define HH 256
#define NSTEPS 5
#define HPAD 260
#define AST 6      // s_a / s_s row stride

// W2 transposed (fp32) for SIMT backward.
__device__ float g_W2T[2][HH * HH];
// Forward weights, tf32 hi/lo split, fragment-major:
// idx = ((kStep*32 + nTg)*2 + breg)*32 + lane
//   k = kStep*8 + (lane&3) + 4*breg ; j = nTg*8 + (lane>>2)
__device__ float g_BfHi[2][HH * HH];
__device__ float g_BfLo[2][HH * HH];

__device__ __forceinline__ unsigned f2tf(float x) {
    unsigned r; asm("cvt.rna.tf32.f32 %0, %1;" : "=r"(r) : "f"(x)); return r;
}

__global__ void prep_weights(const float* __restrict__ w2a,
                             const float* __restrict__ w2b) {
    int idx = blockIdx.x * 256 + threadIdx.x;   // 0..65535
    int net = blockIdx.y;
    const float* W2 = net ? w2b : w2a;
    // transpose (coalesced read)
    int k = idx >> 8, j = idx & 255;
    g_W2T[net][j * HH + k] = W2[k * HH + j];
    // fragment-major tf32 split
    int lane = idx & 31;
    int breg = (idx >> 5) & 1;
    int nTg  = (idx >> 6) & 31;
    int ks   = idx >> 11;
    int kk = ks * 8 + (lane & 3) + 4 * breg;
    int jj = nTg * 8 + (lane >> 2);
    float w = W2[kk * HH + jj];
    unsigned hi = f2tf(w);
    float hif = __uint_as_float(hi);
    unsigned lo = f2tf(w - hif);
    g_BfHi[net][idx] = hif;
    g_BfLo[net][idx] = __uint_as_float(lo);
}

__device__ __forceinline__ void mma_tf32(float& d0, float& d1, float& d2, float& d3,
                                         unsigned a0, unsigned a1, unsigned a2, unsigned a3,
                                         unsigned b0, unsigned b1) {
    asm("mma.sync.aligned.m16n8k8.row.col.f32.tf32.tf32.f32 "
        "{%0,%1,%2,%3}, {%4,%5,%6,%7}, {%8,%9}, {%0,%1,%2,%3};"
        : "+f"(d0), "+f"(d1), "+f"(d2), "+f"(d3)
        : "r"(a0), "r"(a1), "r"(a2), "r"(a3), "r"(b0), "r"(b1));
}

__global__ __launch_bounds__(256, 2) void svgd_kernel(
    const float* __restrict__ obs, const float* __restrict__ a0,
    const float* __restrict__ W1a, const float* __restrict__ B1a,
    const float* __restrict__ W2a, const float* __restrict__ B2a,
    const float* __restrict__ W3a, const float* __restrict__ B3a,
    const float* __restrict__ W1b, const float* __restrict__ B1b,
    const float* __restrict__ W2b, const float* __restrict__ B2b,
    const float* __restrict__ W3b, const float* __restrict__ B3b,
    float* __restrict__ out)
{
    __shared__ __align__(16) float s_h[NN * HPAD];   // h / dh2 / dh1 / sort scratch
    __shared__ __align__(16) float s_x[NN * 32];     // inputs; aliased by d2 in svgd
    __shared__ __align__(16) unsigned char s_u[8192]; // masks (fwd/bwd) | K (svgd)
    __shared__ float s_q[2][NN];
    __shared__ float s_s[NN * AST];
    __shared__ float s_a[NN * AST];
    __shared__ float s_logp[NN];
    __shared__ float s_lpn[NN];
    __shared__ float s_red[8 * NN];
    __shared__ int s_orig[NN];
    __shared__ int s_cnt1;

    unsigned* s_m1 = (unsigned*)s_u;                 // [net*HH + k], bit n
    unsigned char* s_m2c = s_u + 2048;               // [net*1024 + (j>>1)*8 + (n&7)]
    float* s_d2p = (float*)s_x;                      // d2 aliases s_x (obs reloaded each step)
    float* s_Kp  = (float*)(s_u + 4096);             // K aliases upper mask region

    const int b = blockIdx.x;
    const int tid = threadIdx.x;
    const int lane = tid & 31;
    const int warp = tid >> 5;
    const int laneq = lane >> 2;      // 0..7
    const int lanet = lane & 3;       // 0..3
    // SIMT bwd tile mapping (unchanged from R7)
    const int n0    = (warp >> 1) * 8;
    const int hhalf = warp & 1;
    const int bcol  = ((hhalf << 5) | lane) * 4;

    for (int idx = tid; idx < NN * DACT; idx += 256) {
        int n = idx / DACT, d = idx % DACT;
        s_a[n * AST + d] = a0[(b * NN + n) * DACT + d];
    }
    if (tid < NN) s_logp[tid] = 0.0f;
    __syncthreads();
    if (tid < NN) {
        float ss = 0.0f;
        #pragma unroll
        for (int d = 0; d < DACT; d++) { float v = s_a[tid * AST + d]; ss += v * v; }
        s_lpn[tid] = -3.0f * logf(6.283185307179586f * 0.3f) - (0.5f / 0.3f) * ss;
    }

    for (int step = 0; step < NSTEPS; ++step) {
        __syncthreads();
        // (re)load obs (s_x clobbered by d2 each step) + current actions
        for (int idx = tid; idx < NN * DOBS; idx += 256) {
            int n = idx / DOBS, k = idx % DOBS;
            s_x[n * 32 + k] = obs[(b * NN + n) * DOBS + k];
        }
        for (int idx = tid; idx < NN * DACT; idx += 256) {
            int n = idx / DACT, d = idx % DACT;
            s_x[n * 32 + DOBS + d] = s_a[n * AST + d];
        }
        __syncthreads();

        // ================= forward both Q nets (layer2 via tf32 mma) =================
        for (int net = 0; net < 2; ++net) {
            const float* W1 = net ? W1b : W1a;
            const float* B1 = net ? B1b : B1a;
            const float* B2 = net ? B2b : B2a;
            const float* W3 = net ? W3b : W3a;
            const float* B3 = net ? B3b : B3a;

            // ---- layer1 (SIMT): thread = hidden unit ----
            {
                float c[DIN];
                #pragma unroll
                for (int k = 0; k < DIN; k++) c[k] = W1[k * HH + tid];
                float bb1 = B1[tid];
                unsigned mm1 = 0;
                for (int n = 0; n < NN; n++) {
                    float z = bb1;
                    #pragma unroll
                    for (int k = 0; k < DIN; k++) z += s_x[n * 32 + k] * c[k];
                    if (z > 0.0f) mm1 |= (1u << n); else z = 0.0f;
                    s_h[n * HPAD + tid] = z;
                }
                s_m1[net * HH + tid] = mm1;
            }
            __syncthreads();

            // ---- layer2: Z = h @ W2 via split-tf32 mma ----
            float D[2][4][4];
            #pragma unroll
            for (int mT = 0; mT < 2; mT++)
                #pragma unroll
                for (int t = 0; t < 4; t++)
                    #pragma unroll
                    for (int c = 0; c < 4; c++) D[mT][t][c] = 0.0f;

            const float* BH = g_BfHi[net];
            const float* BL = g_BfLo[net];

            for (int ks = 0; ks < 32; ks++) {
                unsigned bh[4][2], bl[4][2];
                int base = ((ks * 32 + warp * 4) * 2) * 32 + lane;
                #pragma unroll
                for (int t = 0; t < 4; t++) {
                    bh[t][0] = __float_as_uint(BH[base + t * 64]);
                    bh[t][1] = __float_as_uint(BH[base + t * 64 + 32]);
                    bl[t][0] = __float_as_uint(BL[base + t * 64]);
                    bl[t][1] = __float_as_uint(BL[base + t * 64 + 32]);
                }
                #pragma unroll
                for (int mT = 0; mT < 2; mT++) {
                    int r = mT * 16 + laneq;
                    float a0f = s_h[r * HPAD + ks * 8 + lanet];
                    float a1f = s_h[(r + 8) * HPAD + ks * 8 + lanet];
                    float a2f = s_h[r * HPAD + ks * 8 + lanet + 4];
                    float a3f = s_h[(r + 8) * HPAD + ks * 8 + lanet + 4];
                    unsigned ah0 = f2tf(a0f), ah1 = f2tf(a1f);
                    unsigned ah2 = f2tf(a2f), ah3 = f2tf(a3f);
                    unsigned al0 = f2tf(a0f - __uint_as_float(ah0));
                    unsigned al1 = f2tf(a1f - __uint_as_float(ah1));
                    unsigned al2 = f2tf(a2f - __uint_as_float(ah2));
                    unsigned al3 = f2tf(a3f - __uint_as_float(ah3));
                    #pragma unroll
                    for (int t = 0; t < 4; t++) {
                        mma_tf32(D[mT][t][0], D[mT][t][1], D[mT][t][2], D[mT][t][3],
                                 ah0, ah1, ah2, ah3, bh[t][0], bh[t][1]);
                        mma_tf32(D[mT][t][0], D[mT][t][1], D[mT][t][2], D[mT][t][3],
                                 ah0, ah1, ah2, ah3, bl[t][0], bl[t][1]);
                        mma_tf32(D[mT][t][0], D[mT][t][1], D[mT][t][2], D[mT][t][3],
                                 al0, al1, al2, al3, bh[t][0], bh[t][1]);
                    }
                }
            }

            // ---- epilogue: bias, relu, mask bytes, q partials ----
            float qr[2][2] = {{0.0f, 0.0f}, {0.0f, 0.0f}};
            #pragma unroll
            for (int t = 0; t < 4; t++) {
                int j0 = warp * 32 + t * 8 + 2 * lanet;
                float b2_0 = B2[j0], b2_1 = B2[j0 + 1];
                float w3_0 = W3[j0], w3_1 = W3[j0 + 1];
                unsigned byte = 0;
                #pragma unroll
                for (int mT = 0; mT < 2; mT++) {
                    float z00 = D[mT][t][0] + b2_0;
                    float z01 = D[mT][t][1] + b2_1;
                    float z10 = D[mT][t][2] + b2_0;
                    float z11 = D[mT][t][3] + b2_1;
                    if (z00 > 0.0f) { byte |= 1u << (4 * mT + 0); qr[mT][0] += z00 * w3_0; }
                    if (z01 > 0.0f) { byte |= 1u << (4 * mT + 1); qr[mT][0] += z01 * w3_1; }
                    if (z10 > 0.0f) { byte |= 1u << (4 * mT + 2); qr[mT][1] += z10 * w3_0; }
                    if (z11 > 0.0f) { byte |= 1u << (4 * mT + 3); qr[mT][1] += z11 * w3_1; }
                }
                s_m2c[net * 1024 + (j0 >> 1) * 8 + laneq] = (unsigned char)byte;
            }
            #pragma unroll
            for (int mT = 0; mT < 2; mT++)
                #pragma unroll
                for (int u = 0; u < 2; u++) {
                    float v = qr[mT][u];
                    v += __shfl_xor_sync(0xffffffffu, v, 1);
                    v += __shfl_xor_sync(0xffffffffu, v, 2);
                    if (lanet == 0) s_red[warp * 32 + mT * 16 + 8 * u + laneq] = v;
                }
            __syncthreads();
            if (tid < NN) {
                float q = B3[0];
                #pragma unroll
                for (int w = 0; w < 8; w++) q += s_red[w * 32 + tid];
                s_q[net][tid] = q;
            }
            __syncthreads();
        }

        // ---- gate + stable partition (net0-selected first) ----
        if (tid < NN) {
            bool g = s_q[0][tid] <= s_q[1][tid];
            unsigned ball = __ballot_sync(0xffffffffu, g);
            int c1 = __popc(ball);
            int below = __popc(ball & ((1u << tid) - 1u));
            int slot = g ? below : (c1 + (tid - below));
            s_orig[slot] = tid;
            if (tid == 0) s_cnt1 = c1;
        }
        __syncthreads();

        // ================= backward (SIMT, gate-partitioned, R7) =================
        {
            const int cnt1 = s_cnt1;
            const float* W2Ta = g_W2T[0];
            const float* W2Tb = g_W2T[1];
            float4 w3av = *(const float4*)&W3a[bcol];
            float4 w3bv = *(const float4*)&W3b[bcol];

            int og[8];
            #pragma unroll
            for (int i = 0; i < 8; i++) og[i] = s_orig[n0 + i];

            // dh2[slot][j] = mask2_sel * W3_sel[j]
            #pragma unroll
            for (int i = 0; i < 8; i++) {
                int o = og[i];
                bool sA = (n0 + i) < cnt1;
                const unsigned char* mb = s_m2c + (sA ? 0 : 1024);
                int bitb = 4 * (o >> 4) + 2 * ((o >> 3) & 1);
                unsigned by0 = mb[(bcol >> 1) * 8 + (o & 7)];
                unsigned by1 = mb[((bcol >> 1) + 1) * 8 + (o & 7)];
                float4 wv = sA ? w3av : w3bv;
                float4 v;
                v.x = (by0 >> (bitb + 0)) & 1u ? wv.x : 0.0f;
                v.y = (by0 >> (bitb + 1)) & 1u ? wv.y : 0.0f;
                v.z = (by1 >> (bitb + 0)) & 1u ? wv.z : 0.0f;
                v.w = (by1 >> (bitb + 1)) & 1u ? wv.w : 0.0f;
                *(float4*)&s_h[(n0 + i) * HPAD + bcol] = v;
            }
            __syncthreads();

            float accs[8][4];
            #pragma unroll
            for (int i = 0; i < 8; i++)
                #pragma unroll
                for (int kc = 0; kc < 4; kc++) accs[i][kc] = 0.0f;

            if (n0 + 8 <= cnt1 || n0 >= cnt1) {
                const float* W2T = (n0 + 8 <= cnt1) ? W2Ta : W2Tb;
                #pragma unroll 2
                for (int j = 0; j < HH; j += 4) {
                    float4 wv0 = *(const float4*)&W2T[(j + 0) * HH + bcol];
                    float4 wv1 = *(const float4*)&W2T[(j + 1) * HH + bcol];
                    float4 wv2 = *(const float4*)&W2T[(j + 2) * HH + bcol];
                    float4 wv3 = *(const float4*)&W2T[(j + 3) * HH + bcol];
                    #pragma unroll
                    for (int i = 0; i < 8; i++) {
                        float4 d4 = *(const float4*)&s_h[(n0 + i) * HPAD + j];
                        accs[i][0] += d4.x * wv0.x + d4.y * wv1.x + d4.z * wv2.x + d4.w * wv3.x;
                        accs[i][1] += d4.x * wv0.y + d4.y * wv1.y + d4.z * wv2.y + d4.w * wv3.y;
                        accs[i][2] += d4.x * wv0.z + d4.y * wv1.z + d4.z * wv2.z + d4.w * wv3.z;
                        accs[i][3] += d4.x * wv0.w + d4.y * wv1.w + d4.z * wv2.w + d4.w * wv3.w;
                    }
                }
            } else {
                #pragma unroll 2
                for (int j = 0; j < HH; j += 4) {
                    {
                        float4 wv0 = *(const float4*)&W2Ta[(j + 0) * HH + bcol];
                        float4 wv1 = *(const float4*)&W2Ta[(j + 1) * HH + bcol];
                        float4 wv2 = *(const float4*)&W2Ta[(j + 2) * HH + bcol];
                        float4 wv3 = *(const float4*)&W2Ta[(j + 3) * HH + bcol];
                        #pragma unroll
                        for (int i = 0; i < 8; i++) {
                            if (n0 + i < cnt1) {
                                float4 d4 = *(const float4*)&s_h[(n0 + i) * HPAD + j];
                                accs[i][0] += d4.x * wv0.x + d4.y * wv1.x + d4.z * wv2.x + d4.w * wv3.x;
                                accs[i][1] += d4.x * wv0.y + d4.y * wv1.y + d4.z * wv2.y + d4.w * wv3.y;
                                accs[i][2] += d4.x * wv0.z + d4.y * wv1.z + d4.z * wv2.z + d4.w * wv3.z;
                                accs[i][3] += d4.x * wv0.w + d4.y * wv1.w + d4.z * wv2.w + d4.w * wv3.w;
                            }
                        }
                    }
                    {
                        float4 wv0 = *(const float4*)&W2Tb[(j + 0) * HH + bcol];
                        float4 wv1 = *(const float4*)&W2Tb[(j + 1) * HH + bcol];
                        float4 wv2 = *(const float4*)&W2Tb[(j + 2) * HH + bcol];
                        float4 wv3 = *(const float4*)&W2Tb[(j + 3) * HH + bcol];
                        #pragma unroll
                        for (int i = 0; i < 8; i++) {
                            if (n0 + i >= cnt1) {
                                float4 d4 = *(const float4*)&s_h[(n0 + i) * HPAD + j];
                                accs[i][0] += d4.x * wv0.x + d4.y * wv1.x + d4.z * wv2.x + d4.w * wv3.x;
                                accs[i][1] += d4.x * wv0.y + d4.y * wv1.y + d4.z * wv2.y + d4.w * wv3.y;
                                accs[i][2] += d4.x * wv0.z + d4.y * wv1.z + d4.z * wv2.z + d4.w * wv3.z;
                                accs[i][3] += d4.x * wv0.w + d4.y * wv1.w + d4.z * wv2.w + d4.w * wv3.w;
                            }
                        }
                    }
                }
            }

            unsigned ua0 = s_m1[bcol + 0], ua1 = s_m1[bcol + 1];
            unsigned ua2 = s_m1[bcol + 2], ua3 = s_m1[bcol + 3];
            unsigned ub0 = s_m1[HH + bcol + 0], ub1 = s_m1[HH + bcol + 1];
            unsigned ub2 = s_m1[HH + bcol + 2], ub3 = s_m1[HH + bcol + 3];
            __syncthreads();

            #pragma unroll
            for (int i = 0; i < 8; i++) {
                int o = og[i];
                bool sA = (n0 + i) < cnt1;
                unsigned m0 = sA ? ua0 : ub0;
                unsigned m1v = sA ? ua1 : ub1;
                unsigned m2v = sA ? ua2 : ub2;
                unsigned m3v = sA ? ua3 : ub3;
                float4 v;
                v.x = (m0 >> o) & 1u ? accs[i][0] : 0.0f;
                v.y = (m1v >> o) & 1u ? accs[i][1] : 0.0f;
                v.z = (m2v >> o) & 1u ? accs[i][2] : 0.0f;
                v.w = (m3v >> o) & 1u ? accs[i][3] : 0.0f;
                *(float4*)&s_h[(n0 + i) * HPAD + bcol] = v;
            }
            __syncthreads();

            if (tid < NN * DACT) {
                int sl = tid / DACT, d = tid % DACT;
                int o = s_orig[sl];
                const float* W1sel = (sl < s_cnt1) ? W1a : W1b;
                const float* w1r = W1sel + (DOBS + d) * HH;
                float sum = 0.0f;
                for (int k = 0; k < HH; k += 4) {
                    float4 h4 = *(const float4*)&s_h[sl * HPAD + k];
                    float4 w4 = *(const float4*)&w1r[k];
                    sum += h4.x * w4.x + h4.y * w4.y + h4.z * w4.z + h4.w * w4.w;
                }
                s_s[o * AST + d] = sum;
            }
            __syncthreads();
        }

        // ================= SVGD update =================
        for (int p = tid; p < NN * NN; p += 256) {
            int i = p >> 5, j = p & 31;
            float ds = 0.0f;
            #pragma unroll
            for (int d = 0; d < DACT; d++) {
                float df = s_a[i * AST + d] - s_a[j * AST + d];
                ds += df * df;
            }
            s_d2p[p] = ds;
            s_h[p] = ds;  // sort copy
        }
        __syncthreads();

        for (int ks = 2; ks <= NN * NN; ks <<= 1) {
            for (int jj = ks >> 1; jj > 0; jj >>= 1) {
                #pragma unroll
                for (int e = 0; e < 4; e++) {
                    int idx = (e << 8) | tid;
                    int ixj = idx ^ jj;
                    if (ixj > idx) {
                        float va = s_h[idx], vb = s_h[ixj];
                        bool up = ((idx & ks) == 0);
                        if ((va > vb) == up) { s_h[idx] = vb; s_h[ixj] = va; }
                    }
                }
                __syncthreads();
            }
        }

        float med = 0.5f * (s_h[511] + s_h[512]);
        float hm = med / logf(33.0f);
        float gamma = 1.0f / (2.0f * hm + 1e-8f);
        for (int p = tid; p < NN * NN; p += 256)
            s_Kp[p] = expf(-gamma * s_d2p[p]);
        __syncthreads();

        float anew[DACT];
        float lpdelta = 0.0f;
        if (tid < NN) {
            int i = tid;
            float ai[DACT];
            #pragma unroll
            for (int d = 0; d < DACT; d++) ai[d] = s_a[i * AST + d];
            float ph[DACT] = {0, 0, 0, 0, 0, 0};
            float t1 = 0.0f, t2s = 0.0f;
            for (int j = 0; j < NN; j++) {
                float Kij = s_Kp[i * 32 + j];
                float dot = 0.0f;
                #pragma unroll
                for (int d = 0; d < DACT; d++) {
                    float df = ai[d] - s_a[j * AST + d];
                    float sj = s_s[j * AST + d];
                    dot += df * sj;
                    ph[d] += Kij * sj + 2.0f * gamma * Kij * df;
                }
                t1 += -2.0f * gamma * Kij * dot;
                float I = (i == j) ? 1.0f : 0.0f;
                t2s += 2.0f * gamma * Kij * s_d2p[i * 32 + j] - 6.0f * (Kij - I);
            }
            t1 *= (1.0f / 31.0f);
            float t2 = -2.0f * gamma * t2s * (1.0f / 31.0f);
            lpdelta = 0.05f * (t1 + t2);
            #pragma unroll
            for (int d = 0; d < DACT; d++)
                anew[d] = ai[d] + 0.05f * ph[d] * (1.0f / 32.0f);
        }
        __syncthreads();
        if (tid < NN) {
            s_logp[tid] -= lpdelta;
            #pragma unroll
            for (int d = 0; d < DACT; d++) s_a[tid * AST + d] = anew[d];
        }
        __syncthreads();
    }

    // ================= finalize =================
    __syncthreads();
    if (tid < NN) {
        int n = tid;
        float lpt = 0.0f;
        #pragma unroll
        for (int d = 0; d < DACT; d++) {
            float av = s_a[n * AST + d];
            float x = -2.0f * av;
            float sp = (x > 0.0f) ? (x + log1pf(expf(-x))) : log1pf(expf(x));
            lpt += -2.0f * (0.6931471805599453f - av - sp);
            out[(b * NN + n) * DACT + d] = tanhf(av);
        }
        s_red[n] = s_lpn[n] + s_logp[n] + lpt;
    }
    __syncthreads();
    if (tid == 0) {
        float m = 0.0f;
        for (int n = 0; n < NN; n++) m += s_red[n];
        out[BB * NN * DACT + b] = m * (1.0f / 32.0f);
    }
}

extern "C" void kernel_launch(void* const* d_in, const int* in_sizes, int n_in,
                              void* d_out, int out_size) {
    const float* obs  = (const float*)d_in[0];
    const float* a0   = (const float*)d_in[1];
    const float* q1W1 = (const float*)d_in[2];
    const float* q1b1 = (const float*)d_in[3];
    const float* q1W2 = (const float*)d_in[4];
    const float* q1b2 = (const float*)d_in[5];
    const float* q1W3 = (const float*)d_in[6];
    const float* q1b3 = (const float*)d_in[7];
    const float* q2W1 = (const float*)d_in[8];
    const float* q2b1 = (const float*)d_in[9];
    const float* q2W2 = (const float*)d_in[10];
    const float* q2b2 = (const float*)d_in[11];
    const float* q2W3 = (const float*)d_in[12];
    const float* q2b3 = (const float*)d_in[13];
    float* out = (float*)d_out;

    prep_weights<<<dim3(256, 2), 256>>>(q1W2, q2W2);
    svgd_kernel<<<BB, 256>>>(obs, a0,
                             q1W1, q1b1, q1W2, q1b2, q1W3, q1b3,
                             q2W1, q2b1, q2W2, q2b2, q2W3, q2b3,
                             out);
}

// round 10
// speedup vs baseline: 3.4082x; 1.3498x over previous
#include <cuda_runtime.h>
#include <math.h>

#define BB 1024
#define NN 32
#define DOBS 17
#define DACT 6
#define DIN 23
#define HH 256
#define NSTEPS 5
#define HPAD 260
#define AST 6      // s_a / s_s row stride

// Forward weights (W2: kdim=k, ndim=j), tf32 hi/lo, fragment-major:
// idx = ((kStep*32 + nTg)*2 + breg)*32 + lane
//   k = kStep*8 + (lane&3) + 4*breg ; j = nTg*8 + (lane>>2)
__device__ float g_BfHi[2][HH * HH];
__device__ float g_BfLo[2][HH * HH];
// Backward weights (W2T: kdim=j, ndim=k), tf32 hi/lo, fragment-major:
//   j = kStep*8 + (lane&3) + 4*breg ; k = nTg*8 + (lane>>2) ; value = W2[k][j]
__device__ float g_BbHi[2][HH * HH];
__device__ float g_BbLo[2][HH * HH];

__device__ __forceinline__ unsigned f2tf(float x) {
    unsigned r; asm("cvt.rna.tf32.f32 %0, %1;" : "=r"(r) : "f"(x)); return r;
}

__global__ void prep_weights(const float* __restrict__ w2a,
                             const float* __restrict__ w2b) {
    int idx = blockIdx.x * 256 + threadIdx.x;   // 0..65535
    int net = blockIdx.y;
    const float* W2 = net ? w2b : w2a;
    int lane = idx & 31;
    int breg = (idx >> 5) & 1;
    int nTg  = (idx >> 6) & 31;
    int ks   = idx >> 11;
    // forward
    {
        int kk = ks * 8 + (lane & 3) + 4 * breg;
        int jj = nTg * 8 + (lane >> 2);
        float w = W2[kk * HH + jj];
        unsigned hi = f2tf(w);
        float hif = __uint_as_float(hi);
        g_BfHi[net][idx] = hif;
        g_BfLo[net][idx] = __uint_as_float(f2tf(w - hif));
    }
    // backward (roles swapped: K-dim = j, N-dim = k)
    {
        int jj = ks * 8 + (lane & 3) + 4 * breg;
        int kk = nTg * 8 + (lane >> 2);
        float w = W2[kk * HH + jj];
        unsigned hi = f2tf(w);
        float hif = __uint_as_float(hi);
        g_BbHi[net][idx] = hif;
        g_BbLo[net][idx] = __uint_as_float(f2tf(w - hif));
    }
}

__device__ __forceinline__ void mma_tf32(float& d0, float& d1, float& d2, float& d3,
                                         unsigned a0, unsigned a1, unsigned a2, unsigned a3,
                                         unsigned b0, unsigned b1) {
    asm("mma.sync.aligned.m16n8k8.row.col.f32.tf32.tf32.f32 "
        "{%0,%1,%2,%3}, {%4,%5,%6,%7}, {%8,%9}, {%0,%1,%2,%3};"
        : "+f"(d0), "+f"(d1), "+f"(d2), "+f"(d3)
        : "r"(a0), "r"(a1), "r"(a2), "r"(a3), "r"(b0), "r"(b1));
}

__global__ __launch_bounds__(256, 2) void svgd_kernel(
    const float* __restrict__ obs, const float* __restrict__ a0,
    const float* __restrict__ W1a, const float* __restrict__ B1a,
    const float* __restrict__ W2a, const float* __restrict__ B2a,
    const float* __restrict__ W3a, const float* __restrict__ B3a,
    const float* __restrict__ W1b, const float* __restrict__ B1b,
    const float* __restrict__ W2b, const float* __restrict__ B2b,
    const float* __restrict__ W3b, const float* __restrict__ B3b,
    float* __restrict__ out)
{
    __shared__ __align__(16) float s_h[NN * HPAD];    // h / dh2 / dh1 / sort scratch
    __shared__ __align__(16) float s_x[NN * 32];      // inputs; aliased by d2 in svgd
    __shared__ __align__(16) unsigned char s_u[8192]; // masks (fwd/bwd) | K (svgd)
    __shared__ float s_q[2][NN];
    __shared__ float s_s[NN * AST];
    __shared__ float s_a[NN * AST];
    __shared__ float s_logp[NN];
    __shared__ float s_lpn[NN];
    __shared__ float s_red[8 * NN];
    __shared__ int s_orig[NN];
    __shared__ int s_cnt1;

    unsigned* s_m1 = (unsigned*)s_u;                 // [net*HH + k], bit o
    unsigned char* s_m2c = s_u + 2048;               // [net*1024 + (j>>1)*8 + (n&7)]
    float* s_d2p = (float*)s_x;
    float* s_Kp  = (float*)(s_u + 4096);

    const int b = blockIdx.x;
    const int tid = threadIdx.x;
    const int lane = tid & 31;
    const int warp = tid >> 5;
    const int laneq = lane >> 2;      // 0..7
    const int lanet = lane & 3;       // 0..3
    const int n0    = (warp >> 1) * 8;
    const int hhalf = warp & 1;
    const int bcol  = ((hhalf << 5) | lane) * 4;

    for (int idx = tid; idx < NN * DACT; idx += 256) {
        int n = idx / DACT, d = idx % DACT;
        s_a[n * AST + d] = a0[(b * NN + n) * DACT + d];
    }
    if (tid < NN) s_logp[tid] = 0.0f;
    __syncthreads();
    if (tid < NN) {
        float ss = 0.0f;
        #pragma unroll
        for (int d = 0; d < DACT; d++) { float v = s_a[tid * AST + d]; ss += v * v; }
        s_lpn[tid] = -3.0f * logf(6.283185307179586f * 0.3f) - (0.5f / 0.3f) * ss;
    }

    for (int step = 0; step < NSTEPS; ++step) {
        __syncthreads();
        for (int idx = tid; idx < NN * DOBS; idx += 256) {
            int n = idx / DOBS, k = idx % DOBS;
            s_x[n * 32 + k] = obs[(b * NN + n) * DOBS + k];
        }
        for (int idx = tid; idx < NN * DACT; idx += 256) {
            int n = idx / DACT, d = idx % DACT;
            s_x[n * 32 + DOBS + d] = s_a[n * AST + d];
        }
        __syncthreads();

        // ================= forward both Q nets (layer2 via tf32 mma) =================
        for (int net = 0; net < 2; ++net) {
            const float* W1 = net ? W1b : W1a;
            const float* B1 = net ? B1b : B1a;
            const float* B2 = net ? B2b : B2a;
            const float* W3 = net ? W3b : W3a;
            const float* B3 = net ? B3b : B3a;

            // ---- layer1 (SIMT) ----
            {
                float c[DIN];
                #pragma unroll
                for (int k = 0; k < DIN; k++) c[k] = W1[k * HH + tid];
                float bb1 = B1[tid];
                unsigned mm1 = 0;
                for (int n = 0; n < NN; n++) {
                    float z = bb1;
                    #pragma unroll
                    for (int k = 0; k < DIN; k++) z += s_x[n * 32 + k] * c[k];
                    if (z > 0.0f) mm1 |= (1u << n); else z = 0.0f;
                    s_h[n * HPAD + tid] = z;
                }
                s_m1[net * HH + tid] = mm1;
            }
            __syncthreads();

            // ---- layer2 mma ----
            float D[2][4][4];
            #pragma unroll
            for (int mT = 0; mT < 2; mT++)
                #pragma unroll
                for (int t = 0; t < 4; t++)
                    #pragma unroll
                    for (int c = 0; c < 4; c++) D[mT][t][c] = 0.0f;

            const float* BH = g_BfHi[net];
            const float* BL = g_BfLo[net];

            for (int ks = 0; ks < 32; ks++) {
                unsigned bh[4][2], bl[4][2];
                int base = ((ks * 32 + warp * 4) * 2) * 32 + lane;
                #pragma unroll
                for (int t = 0; t < 4; t++) {
                    bh[t][0] = __float_as_uint(BH[base + t * 64]);
                    bh[t][1] = __float_as_uint(BH[base + t * 64 + 32]);
                    bl[t][0] = __float_as_uint(BL[base + t * 64]);
                    bl[t][1] = __float_as_uint(BL[base + t * 64 + 32]);
                }
                #pragma unroll
                for (int mT = 0; mT < 2; mT++) {
                    int r = mT * 16 + laneq;
                    float a0f = s_h[r * HPAD + ks * 8 + lanet];
                    float a1f = s_h[(r + 8) * HPAD + ks * 8 + lanet];
                    float a2f = s_h[r * HPAD + ks * 8 + lanet + 4];
                    float a3f = s_h[(r + 8) * HPAD + ks * 8 + lanet + 4];
                    unsigned ah0 = f2tf(a0f), ah1 = f2tf(a1f);
                    unsigned ah2 = f2tf(a2f), ah3 = f2tf(a3f);
                    unsigned al0 = f2tf(a0f - __uint_as_float(ah0));
                    unsigned al1 = f2tf(a1f - __uint_as_float(ah1));
                    unsigned al2 = f2tf(a2f - __uint_as_float(ah2));
                    unsigned al3 = f2tf(a3f - __uint_as_float(ah3));
                    #pragma unroll
                    for (int t = 0; t < 4; t++) {
                        mma_tf32(D[mT][t][0], D[mT][t][1], D[mT][t][2], D[mT][t][3],
                                 ah0, ah1, ah2, ah3, bh[t][0], bh[t][1]);
                        mma_tf32(D[mT][t][0], D[mT][t][1], D[mT][t][2], D[mT][t][3],
                                 ah0, ah1, ah2, ah3, bl[t][0], bl[t][1]);
                        mma_tf32(D[mT][t][0], D[mT][t][1], D[mT][t][2], D[mT][t][3],
                                 al0, al1, al2, al3, bh[t][0], bh[t][1]);
                    }
                }
            }

            // ---- epilogue ----
            float qr[2][2] = {{0.0f, 0.0f}, {0.0f, 0.0f}};
            #pragma unroll
            for (int t = 0; t < 4; t++) {
                int j0 = warp * 32 + t * 8 + 2 * lanet;
                float b2_0 = B2[j0], b2_1 = B2[j0 + 1];
                float w3_0 = W3[j0], w3_1 = W3[j0 + 1];
                unsigned byte = 0;
                #pragma unroll
                for (int mT = 0; mT < 2; mT++) {
                    float z00 = D[mT][t][0] + b2_0;
                    float z01 = D[mT][t][1] + b2_1;
                    float z10 = D[mT][t][2] + b2_0;
                    float z11 = D[mT][t][3] + b2_1;
                    if (z00 > 0.0f) { byte |= 1u << (4 * mT + 0); qr[mT][0] += z00 * w3_0; }
                    if (z01 > 0.0f) { byte |= 1u << (4 * mT + 1); qr[mT][0] += z01 * w3_1; }
                    if (z10 > 0.0f) { byte |= 1u << (4 * mT + 2); qr[mT][1] += z10 * w3_0; }
                    if (z11 > 0.0f) { byte |= 1u << (4 * mT + 3); qr[mT][1] += z11 * w3_1; }
                }
                s_m2c[net * 1024 + (j0 >> 1) * 8 + laneq] = (unsigned char)byte;
            }
            #pragma unroll
            for (int mT = 0; mT < 2; mT++)
                #pragma unroll
                for (int u = 0; u < 2; u++) {
                    float v = qr[mT][u];
                    v += __shfl_xor_sync(0xffffffffu, v, 1);
                    v += __shfl_xor_sync(0xffffffffu, v, 2);
                    if (lanet == 0) s_red[warp * 32 + mT * 16 + 8 * u + laneq] = v;
                }
            __syncthreads();
            if (tid < NN) {
                float q = B3[0];
                #pragma unroll
                for (int w = 0; w < 8; w++) q += s_red[w * 32 + tid];
                s_q[net][tid] = q;
            }
            __syncthreads();
        }

        // ---- gate + stable partition (net0-selected first) ----
        if (tid < NN) {
            bool g = s_q[0][tid] <= s_q[1][tid];
            unsigned ball = __ballot_sync(0xffffffffu, g);
            int c1 = __popc(ball);
            int below = __popc(ball & ((1u << tid) - 1u));
            int slot = g ? below : (c1 + (tid - below));
            s_orig[slot] = tid;
            if (tid == 0) s_cnt1 = c1;
        }
        __syncthreads();

        // ================= backward (tf32 mma, gate-partitioned) =================
        {
            const int cnt1 = s_cnt1;
            float4 w3av = *(const float4*)&W3a[bcol];
            float4 w3bv = *(const float4*)&W3b[bcol];

            // dh2[slot][j] = mask2_sel * W3_sel[j]
            #pragma unroll
            for (int i = 0; i < 8; i++) {
                int o = s_orig[n0 + i];
                bool sA = (n0 + i) < cnt1;
                const unsigned char* mb = s_m2c + (sA ? 0 : 1024);
                int bitb = 4 * (o >> 4) + 2 * ((o >> 3) & 1);
                unsigned by0 = mb[(bcol >> 1) * 8 + (o & 7)];
                unsigned by1 = mb[((bcol >> 1) + 1) * 8 + (o & 7)];
                float4 wv = sA ? w3av : w3bv;
                float4 v;
                v.x = (by0 >> (bitb + 0)) & 1u ? wv.x : 0.0f;
                v.y = (by0 >> (bitb + 1)) & 1u ? wv.y : 0.0f;
                v.z = (by1 >> (bitb + 0)) & 1u ? wv.z : 0.0f;
                v.w = (by1 >> (bitb + 1)) & 1u ? wv.w : 0.0f;
                *(float4*)&s_h[(n0 + i) * HPAD + bcol] = v;
            }
            __syncthreads();

            // dh1 = dh2 @ W2T via split-tf32 mma, per-tile net selection
            float D[2][4][4];
            #pragma unroll
            for (int mT = 0; mT < 2; mT++)
                #pragma unroll
                for (int t = 0; t < 4; t++)
                    #pragma unroll
                    for (int c = 0; c < 4; c++) D[mT][t][c] = 0.0f;

            #pragma unroll
            for (int mT = 0; mT < 2; mT++) {
                int rlo = mT * 16;
                bool pureA = (cnt1 >= rlo + 16);
                bool pureB = (cnt1 <= rlo);
                if (pureA || pureB) {
                    const float* BH = pureA ? g_BbHi[0] : g_BbHi[1];
                    const float* BL = pureA ? g_BbLo[0] : g_BbLo[1];
                    for (int ks = 0; ks < 32; ks++) {
                        unsigned bh[4][2], bl[4][2];
                        int base = ((ks * 32 + warp * 4) * 2) * 32 + lane;
                        #pragma unroll
                        for (int t = 0; t < 4; t++) {
                            bh[t][0] = __float_as_uint(BH[base + t * 64]);
                            bh[t][1] = __float_as_uint(BH[base + t * 64 + 32]);
                            bl[t][0] = __float_as_uint(BL[base + t * 64]);
                            bl[t][1] = __float_as_uint(BL[base + t * 64 + 32]);
                        }
                        int r = rlo + laneq;
                        float a0f = s_h[r * HPAD + ks * 8 + lanet];
                        float a1f = s_h[(r + 8) * HPAD + ks * 8 + lanet];
                        float a2f = s_h[r * HPAD + ks * 8 + lanet + 4];
                        float a3f = s_h[(r + 8) * HPAD + ks * 8 + lanet + 4];
                        unsigned ah0 = f2tf(a0f), ah1 = f2tf(a1f);
                        unsigned ah2 = f2tf(a2f), ah3 = f2tf(a3f);
                        unsigned al0 = f2tf(a0f - __uint_as_float(ah0));
                        unsigned al1 = f2tf(a1f - __uint_as_float(ah1));
                        unsigned al2 = f2tf(a2f - __uint_as_float(ah2));
                        unsigned al3 = f2tf(a3f - __uint_as_float(ah3));
                        #pragma unroll
                        for (int t = 0; t < 4; t++) {
                            mma_tf32(D[mT][t][0], D[mT][t][1], D[mT][t][2], D[mT][t][3],
                                     ah0, ah1, ah2, ah3, bh[t][0], bh[t][1]);
                            mma_tf32(D[mT][t][0], D[mT][t][1], D[mT][t][2], D[mT][t][3],
                                     ah0, ah1, ah2, ah3, bl[t][0], bl[t][1]);
                            mma_tf32(D[mT][t][0], D[mT][t][1], D[mT][t][2], D[mT][t][3],
                                     al0, al1, al2, al3, bh[t][0], bh[t][1]);
                        }
                    }
                } else {
                    // mixed tile: two passes with row-zeroed A
                    int r = rlo + laneq;
                    bool rA0 = (r < cnt1), rA1 = (r + 8 < cnt1);
                    for (int ks = 0; ks < 32; ks++) {
                        int base = ((ks * 32 + warp * 4) * 2) * 32 + lane;
                        float a0f = s_h[r * HPAD + ks * 8 + lanet];
                        float a1f = s_h[(r + 8) * HPAD + ks * 8 + lanet];
                        float a2f = s_h[r * HPAD + ks * 8 + lanet + 4];
                        float a3f = s_h[(r + 8) * HPAD + ks * 8 + lanet + 4];
                        unsigned ah0 = f2tf(a0f), ah1 = f2tf(a1f);
                        unsigned ah2 = f2tf(a2f), ah3 = f2tf(a3f);
                        unsigned al0 = f2tf(a0f - __uint_as_float(ah0));
                        unsigned al1 = f2tf(a1f - __uint_as_float(ah1));
                        unsigned al2 = f2tf(a2f - __uint_as_float(ah2));
                        unsigned al3 = f2tf(a3f - __uint_as_float(ah3));
                        // pass A (rows < cnt1)
                        {
                            unsigned xh0 = rA0 ? ah0 : 0u, xl0 = rA0 ? al0 : 0u;
                            unsigned xh1 = rA1 ? ah1 : 0u, xl1 = rA1 ? al1 : 0u;
                            unsigned xh2 = rA0 ? ah2 : 0u, xl2 = rA0 ? al2 : 0u;
                            unsigned xh3 = rA1 ? ah3 : 0u, xl3 = rA1 ? al3 : 0u;
                            #pragma unroll
                            for (int t = 0; t < 4; t++) {
                                unsigned b0 = __float_as_uint(g_BbHi[0][base + t * 64]);
                                unsigned b1 = __float_as_uint(g_BbHi[0][base + t * 64 + 32]);
                                unsigned c0 = __float_as_uint(g_BbLo[0][base + t * 64]);
                                unsigned c1 = __float_as_uint(g_BbLo[0][base + t * 64 + 32]);
                                mma_tf32(D[mT][t][0], D[mT][t][1], D[mT][t][2], D[mT][t][3],
                                         xh0, xh1, xh2, xh3, b0, b1);
                                mma_tf32(D[mT][t][0], D[mT][t][1], D[mT][t][2], D[mT][t][3],
                                         xh0, xh1, xh2, xh3, c0, c1);
                                mma_tf32(D[mT][t][0], D[mT][t][1], D[mT][t][2], D[mT][t][3],
                                         xl0, xl1, xl2, xl3, b0, b1);
                            }
                        }
                        // pass B (rows >= cnt1)
                        {
                            unsigned xh0 = rA0 ? 0u : ah0, xl0 = rA0 ? 0u : al0;
                            unsigned xh1 = rA1 ? 0u : ah1, xl1 = rA1 ? 0u : al1;
                            unsigned xh2 = rA0 ? 0u : ah2, xl2 = rA0 ? 0u : al2;
                            unsigned xh3 = rA1 ? 0u : ah3, xl3 = rA1 ? 0u : al3;
                            #pragma unroll
                            for (int t = 0; t < 4; t++) {
                                unsigned b0 = __float_as_uint(g_BbHi[1][base + t * 64]);
                                unsigned b1 = __float_as_uint(g_BbHi[1][base + t * 64 + 32]);
                                unsigned c0 = __float_as_uint(g_BbLo[1][base + t * 64]);
                                unsigned c1 = __float_as_uint(g_BbLo[1][base + t * 64 + 32]);
                                mma_tf32(D[mT][t][0], D[mT][t][1], D[mT][t][2], D[mT][t][3],
                                         xh0, xh1, xh2, xh3, b0, b1);
                                mma_tf32(D[mT][t][0], D[mT][t][1], D[mT][t][2], D[mT][t][3],
                                         xh0, xh1, xh2, xh3, c0, c1);
                                mma_tf32(D[mT][t][0], D[mT][t][1], D[mT][t][2], D[mT][t][3],
                                         xl0, xl1, xl2, xl3, b0, b1);
                            }
                        }
                    }
                }
            }
            __syncthreads();  // all dh2 reads complete before dh1 writes

            // dh1 epilogue: apply relu mask1 (selected net, original-particle bit)
            const int cnt1e = cnt1;
            #pragma unroll
            for (int mT = 0; mT < 2; mT++) {
                int r0 = mT * 16 + laneq, r1 = r0 + 8;
                int o0 = s_orig[r0], o1 = s_orig[r1];
                int off0 = (r0 < cnt1e) ? 0 : HH;
                int off1 = (r1 < cnt1e) ? 0 : HH;
                #pragma unroll
                for (int t = 0; t < 4; t++) {
                    int c0 = warp * 32 + t * 8 + 2 * lanet;
                    unsigned w00 = s_m1[off0 + c0], w01 = s_m1[off0 + c0 + 1];
                    unsigned w10 = s_m1[off1 + c0], w11 = s_m1[off1 + c0 + 1];
                    float2 v0, v1;
                    v0.x = (w00 >> o0) & 1u ? D[mT][t][0] : 0.0f;
                    v0.y = (w01 >> o0) & 1u ? D[mT][t][1] : 0.0f;
                    v1.x = (w10 >> o1) & 1u ? D[mT][t][2] : 0.0f;
                    v1.y = (w11 >> o1) & 1u ? D[mT][t][3] : 0.0f;
                    *(float2*)&s_h[r0 * HPAD + c0] = v0;
                    *(float2*)&s_h[r1 * HPAD + c0] = v1;
                }
            }
            __syncthreads();

            // da[orig][d] = sum_k dh1[slot][k] * W1_sel[17+d][k]
            if (tid < NN * DACT) {
                int sl = tid / DACT, d = tid % DACT;
                int o = s_orig[sl];
                const float* W1sel = (sl < cnt1) ? W1a : W1b;
                const float* w1r = W1sel + (DOBS + d) * HH;
                float sum = 0.0f;
                for (int k = 0; k < HH; k += 4) {
                    float4 h4 = *(const float4*)&s_h[sl * HPAD + k];
                    float4 w4 = *(const float4*)&w1r[k];
                    sum += h4.x * w4.x + h4.y * w4.y + h4.z * w4.z + h4.w * w4.w;
                }
                s_s[o * AST + d] = sum;
            }
            __syncthreads();
        }

        // ================= SVGD update =================
        for (int p = tid; p < NN * NN; p += 256) {
            int i = p >> 5, j = p & 31;
            float ds = 0.0f;
            #pragma unroll
            for (int d = 0; d < DACT; d++) {
                float df = s_a[i * AST + d] - s_a[j * AST + d];
                ds += df * df;
            }
            s_d2p[p] = ds;
            s_h[p] = ds;
        }
        __syncthreads();

        for (int ks = 2; ks <= NN * NN; ks <<= 1) {
            for (int jj = ks >> 1; jj > 0; jj >>= 1) {
                #pragma unroll
                for (int e = 0; e < 4; e++) {
                    int idx = (e << 8) | tid;
                    int ixj = idx ^ jj;
                    if (ixj > idx) {
                        float va = s_h[idx], vb = s_h[ixj];
                        bool up = ((idx & ks) == 0);
                        if ((va > vb) == up) { s_h[idx] = vb; s_h[ixj] = va; }
                    }
                }
                __syncthreads();
            }
        }

        float med = 0.5f * (s_h[511] + s_h[512]);
        float hm = med / logf(33.0f);
        float gamma = 1.0f / (2.0f * hm + 1e-8f);
        for (int p = tid; p < NN * NN; p += 256)
            s_Kp[p] = expf(-gamma * s_d2p[p]);
        __syncthreads();

        float anew[DACT];
        float lpdelta = 0.0f;
        if (tid < NN) {
            int i = tid;
            float ai[DACT];
            #pragma unroll
            for (int d = 0; d < DACT; d++) ai[d] = s_a[i * AST + d];
            float ph[DACT] = {0, 0, 0, 0, 0, 0};
            float t1 = 0.0f, t2s = 0.0f;
            for (int j = 0; j < NN; j++) {
                float Kij = s_Kp[i * 32 + j];
                float dot = 0.0f;
                #pragma unroll
                for (int d = 0; d < DACT; d++) {
                    float df = ai[d] - s_a[j * AST + d];
                    float sj = s_s[j * AST + d];
                    dot += df * sj;
                    ph[d] += Kij * sj + 2.0f * gamma * Kij * df;
                }
                t1 += -2.0f * gamma * Kij * dot;
                float I = (i == j) ? 1.0f : 0.0f;
                t2s += 2.0f * gamma * Kij * s_d2p[i * 32 + j] - 6.0f * (Kij - I);
            }
            t1 *= (1.0f / 31.0f);
            float t2 = -2.0f * gamma * t2s * (1.0f / 31.0f);
            lpdelta = 0.05f * (t1 + t2);
            #pragma unroll
            for (int d = 0; d < DACT; d++)
                anew[d] = ai[d] + 0.05f * ph[d] * (1.0f / 32.0f);
        }
        __syncthreads();
        if (tid < NN) {
            s_logp[tid] -= lpdelta;
            #pragma unroll
            for (int d = 0; d < DACT; d++) s_a[tid * AST + d] = anew[d];
        }
        __syncthreads();
    }

    // ================= finalize =================
    __syncthreads();
    if (tid < NN) {
        int n = tid;
        float lpt = 0.0f;
        #pragma unroll
        for (int d = 0; d < DACT; d++) {
            float av = s_a[n * AST + d];
            float x = -2.0f * av;
            float sp = (x > 0.0f) ? (x + log1pf(expf(-x))) : log1pf(expf(x));
            lpt += -2.0f * (0.6931471805599453f - av - sp);
            out[(b * NN + n) * DACT + d] = tanhf(av);
        }
        s_red[n] = s_lpn[n] + s_logp[n] + lpt;
    }
    __syncthreads();
    if (tid == 0) {
        float m = 0.0f;
        for (int n = 0; n < NN; n++) m += s_red[n];
        out[BB * NN * DACT + b] = m * (1.0f / 32.0f);
    }
}

extern "C" void kernel_launch(void* const* d_in, const int* in_sizes, int n_in,
                              void* d_out, int out_size) {
    const float* obs  = (const float*)d_in[0];
    const float* a0   = (const float*)d_in[1];
    const float* q1W1 = (const float*)d_in[2];
    const float* q1b1 = (const float*)d_in[3];
    const float* q1W2 = (const float*)d_in[4];
    const float* q1b2 = (const float*)d_in[5];
    const float* q1W3 = (const float*)d_in[6];
    const float* q1b3 = (const float*)d_in[7];
    const float* q2W1 = (const float*)d_in[8];
    const float* q2b1 = (const float*)d_in[9];
    const float* q2W2 = (const float*)d_in[10];
    const float* q2b2 = (const float*)d_in[11];
    const float* q2W3 = (const float*)d_in[12];
    const float* q2b3 = (const float*)d_in[13];
    float* out = (float*)d_out;

    prep_weights<<<dim3(256, 2), 256>>>(q1W2, q2W2);
    svgd_kernel<<<BB, 256>>>(obs, a0,
                             q1W1, q1b1, q1W2, q1b2, q1W3, q1b3,
                             q2W1, q2b1, q2W2, q2b2, q2W3, q2b3,
                             out);
}

// round 11
// speedup vs baseline: 3.6189x; 1.0618x over previous
#include <cuda_runtime.h>
#include <math.h>

#define BB 1024
#define NN 32
#define DOBS 17
#define DACT 6
#define DIN 23
#define HH 256
#define NSTEPS 5
#define AST 6
#define H2ST 260    // s_h2 row stride in float2 units
#define HFST 520    // same region viewed as floats

// B fragments, packed float4 = (hi_breg0, hi_breg1, lo_breg0, lo_breg1).
// flat idx = (ks*32 + nTg)*32 + lane
// fwd: k = ks*8 + (lane&3) [+4], j = nTg*8 + (lane>>2), value = W2[k][j]
// bwd: j = ks*8 + (lane&3) [+4], k = nTg*8 + (lane>>2), value = W2[k][j]
__device__ float4 g_Bf[2][32768];
__device__ float4 g_Bb[2][32768];

__device__ __forceinline__ unsigned f2tf(float x) {
    unsigned r; asm("cvt.rna.tf32.f32 %0, %1;" : "=r"(r) : "f"(x)); return r;
}

__global__ void prep_weights(const float* __restrict__ w2a,
                             const float* __restrict__ w2b) {
    int idx = blockIdx.x * 256 + threadIdx.x;   // 0..32767
    int net = blockIdx.y;
    const float* W2 = net ? w2b : w2a;
    int lane = idx & 31;
    int nTg  = (idx >> 5) & 31;
    int ks   = idx >> 10;
    // forward
    {
        int k0 = ks * 8 + (lane & 3);
        int j  = nTg * 8 + (lane >> 2);
        float w0 = W2[k0 * HH + j], w1 = W2[(k0 + 4) * HH + j];
        float h0 = __uint_as_float(f2tf(w0));
        float h1 = __uint_as_float(f2tf(w1));
        float l0 = __uint_as_float(f2tf(w0 - h0));
        float l1 = __uint_as_float(f2tf(w1 - h1));
        g_Bf[net][idx] = make_float4(h0, h1, l0, l1);
    }
    // backward
    {
        int j0 = ks * 8 + (lane & 3);
        int k  = nTg * 8 + (lane >> 2);
        float w0 = W2[k * HH + j0], w1 = W2[k * HH + j0 + 4];
        float h0 = __uint_as_float(f2tf(w0));
        float h1 = __uint_as_float(f2tf(w1));
        float l0 = __uint_as_float(f2tf(w0 - h0));
        float l1 = __uint_as_float(f2tf(w1 - h1));
        g_Bb[net][idx] = make_float4(h0, h1, l0, l1);
    }
}

__device__ __forceinline__ void mma_tf32(float& d0, float& d1, float& d2, float& d3,
                                         unsigned a0, unsigned a1, unsigned a2, unsigned a3,
                                         unsigned b0, unsigned b1) {
    asm("mma.sync.aligned.m16n8k8.row.col.f32.tf32.tf32.f32 "
        "{%0,%1,%2,%3}, {%4,%5,%6,%7}, {%8,%9}, {%0,%1,%2,%3};"
        : "+f"(d0), "+f"(d1), "+f"(d2), "+f"(d3)
        : "r"(a0), "r"(a1), "r"(a2), "r"(a3), "r"(b0), "r"(b1));
}

// dynamic smem layout (bytes)
#define SM_H2    0        // float2[32*260] = 66560
#define SM_X     66560    // float[1024]    = 4096
#define SM_U     70656    // 8192 (masks | K)
#define SM_Q     78848    // float[64]
#define SM_S     79104    // float[192]
#define SM_A     79872    // float[192]
#define SM_LOGP  80640    // float[32]
#define SM_LPN   80768    // float[32]
#define SM_RED   80896    // float[256]
#define SM_ORIG  81920    // int[32]
#define SM_CNT   82048    // int
#define SM_TOTAL 82064

__global__ __launch_bounds__(256, 2) void svgd_kernel(
    const float* __restrict__ obs, const float* __restrict__ a0,
    const float* __restrict__ W1a, const float* __restrict__ B1a,
    const float* __restrict__ W2a, const float* __restrict__ B2a,
    const float* __restrict__ W3a, const float* __restrict__ B3a,
    const float* __restrict__ W1b, const float* __restrict__ B1b,
    const float* __restrict__ W2b, const float* __restrict__ B2b,
    const float* __restrict__ W3b, const float* __restrict__ B3b,
    float* __restrict__ out)
{
    extern __shared__ __align__(16) unsigned char smem[];
    float2* s_h2 = (float2*)(smem + SM_H2);        // tf32 hi/lo activation pairs
    float*  s_hf = (float*)(smem + SM_H2);         // same region as floats (dh1/sort)
    float*  s_x  = (float*)(smem + SM_X);
    unsigned char* s_u = smem + SM_U;
    float*  s_q  = (float*)(smem + SM_Q);          // [net*32 + n]
    float*  s_s  = (float*)(smem + SM_S);
    float*  s_a  = (float*)(smem + SM_A);
    float*  s_logp = (float*)(smem + SM_LOGP);
    float*  s_lpn  = (float*)(smem + SM_LPN);
    float*  s_red  = (float*)(smem + SM_RED);
    int*    s_orig = (int*)(smem + SM_ORIG);
    int*    s_cnt  = (int*)(smem + SM_CNT);

    unsigned* s_m1 = (unsigned*)s_u;               // [net*HH + k], bit o
    unsigned char* s_m2c = s_u + 2048;             // [net*1024 + (j>>1)*8 + (n&7)]
    float* s_d2p = s_x;                            // d2 aliases s_x
    float* s_Kp  = (float*)(s_u + 4096);

    const int b = blockIdx.x;
    const int tid = threadIdx.x;
    const int lane = tid & 31;
    const int warp = tid >> 5;
    const int laneq = lane >> 2;
    const int lanet = lane & 3;
    const int n0    = (warp >> 1) * 8;
    const int hhalf = warp & 1;
    const int bcol  = ((hhalf << 5) | lane) * 4;

    for (int idx = tid; idx < NN * DACT; idx += 256) {
        int n = idx / DACT, d = idx % DACT;
        s_a[n * AST + d] = a0[(b * NN + n) * DACT + d];
    }
    if (tid < NN) s_logp[tid] = 0.0f;
    __syncthreads();
    if (tid < NN) {
        float ss = 0.0f;
        #pragma unroll
        for (int d = 0; d < DACT; d++) { float v = s_a[tid * AST + d]; ss += v * v; }
        s_lpn[tid] = -3.0f * logf(6.283185307179586f * 0.3f) - (0.5f / 0.3f) * ss;
    }

    for (int step = 0; step < NSTEPS; ++step) {
        __syncthreads();
        for (int idx = tid; idx < NN * DOBS; idx += 256) {
            int n = idx / DOBS, k = idx % DOBS;
            s_x[n * 32 + k] = obs[(b * NN + n) * DOBS + k];
        }
        for (int idx = tid; idx < NN * DACT; idx += 256) {
            int n = idx / DACT, d = idx % DACT;
            s_x[n * 32 + DOBS + d] = s_a[n * AST + d];
        }
        __syncthreads();

        // ================= forward both Q nets =================
        for (int net = 0; net < 2; ++net) {
            const float* W1 = net ? W1b : W1a;
            const float* B1 = net ? B1b : B1a;
            const float* B2 = net ? B2b : B2a;
            const float* W3 = net ? W3b : W3a;
            const float* B3 = net ? B3b : B3a;

            // ---- layer1 (SIMT): write tf32 hi/lo pairs ----
            {
                float c[DIN];
                #pragma unroll
                for (int k = 0; k < DIN; k++) c[k] = W1[k * HH + tid];
                float bb1 = B1[tid];
                unsigned mm1 = 0;
                for (int n = 0; n < NN; n++) {
                    float z = bb1;
                    #pragma unroll
                    for (int k = 0; k < DIN; k++) z += s_x[n * 32 + k] * c[k];
                    if (z > 0.0f) mm1 |= (1u << n); else z = 0.0f;
                    float hi = __uint_as_float(f2tf(z));
                    float lo = __uint_as_float(f2tf(z - hi));
                    s_h2[n * H2ST + tid] = make_float2(hi, lo);
                }
                s_m1[net * HH + tid] = mm1;
            }
            __syncthreads();

            // ---- layer2 mma (no conversions in loop) ----
            float D[2][4][4];
            #pragma unroll
            for (int mT = 0; mT < 2; mT++)
                #pragma unroll
                for (int t = 0; t < 4; t++)
                    #pragma unroll
                    for (int c = 0; c < 4; c++) D[mT][t][c] = 0.0f;

            const float4* BF = g_Bf[net];

            for (int ks = 0; ks < 32; ks++) {
                int base = (ks * 32 + warp * 4) * 32 + lane;
                float4 bv0 = BF[base];
                float4 bv1 = BF[base + 32];
                float4 bv2 = BF[base + 64];
                float4 bv3 = BF[base + 96];
                #pragma unroll
                for (int mT = 0; mT < 2; mT++) {
                    int r = mT * 16 + laneq;
                    const float2* p0 = s_h2 + r * H2ST + ks * 8 + lanet;
                    const float2* p1 = s_h2 + (r + 8) * H2ST + ks * 8 + lanet;
                    float2 A0 = p0[0], A2 = p0[4];
                    float2 A1 = p1[0], A3 = p1[4];
                    unsigned ah0 = __float_as_uint(A0.x), al0 = __float_as_uint(A0.y);
                    unsigned ah1 = __float_as_uint(A1.x), al1 = __float_as_uint(A1.y);
                    unsigned ah2 = __float_as_uint(A2.x), al2 = __float_as_uint(A2.y);
                    unsigned ah3 = __float_as_uint(A3.x), al3 = __float_as_uint(A3.y);
                    mma_tf32(D[mT][0][0], D[mT][0][1], D[mT][0][2], D[mT][0][3],
                             ah0, ah1, ah2, ah3, __float_as_uint(bv0.x), __float_as_uint(bv0.y));
                    mma_tf32(D[mT][0][0], D[mT][0][1], D[mT][0][2], D[mT][0][3],
                             ah0, ah1, ah2, ah3, __float_as_uint(bv0.z), __float_as_uint(bv0.w));
                    mma_tf32(D[mT][0][0], D[mT][0][1], D[mT][0][2], D[mT][0][3],
                             al0, al1, al2, al3, __float_as_uint(bv0.x), __float_as_uint(bv0.y));
                    mma_tf32(D[mT][1][0], D[mT][1][1], D[mT][1][2], D[mT][1][3],
                             ah0, ah1, ah2, ah3, __float_as_uint(bv1.x), __float_as_uint(bv1.y));
                    mma_tf32(D[mT][1][0], D[mT][1][1], D[mT][1][2], D[mT][1][3],
                             ah0, ah1, ah2, ah3, __float_as_uint(bv1.z), __float_as_uint(bv1.w));
                    mma_tf32(D[mT][1][0], D[mT][1][1], D[mT][1][2], D[mT][1][3],
                             al0, al1, al2, al3, __float_as_uint(bv1.x), __float_as_uint(bv1.y));
                    mma_tf32(D[mT][2][0], D[mT][2][1], D[mT][2][2], D[mT][2][3],
                             ah0, ah1, ah2, ah3, __float_as_uint(bv2.x), __float_as_uint(bv2.y));
                    mma_tf32(D[mT][2][0], D[mT][2][1], D[mT][2][2], D[mT][2][3],
                             ah0, ah1, ah2, ah3, __float_as_uint(bv2.z), __float_as_uint(bv2.w));
                    mma_tf32(D[mT][2][0], D[mT][2][1], D[mT][2][2], D[mT][2][3],
                             al0, al1, al2, al3, __float_as_uint(bv2.x), __float_as_uint(bv2.y));
                    mma_tf32(D[mT][3][0], D[mT][3][1], D[mT][3][2], D[mT][3][3],
                             ah0, ah1, ah2, ah3, __float_as_uint(bv3.x), __float_as_uint(bv3.y));
                    mma_tf32(D[mT][3][0], D[mT][3][1], D[mT][3][2], D[mT][3][3],
                             ah0, ah1, ah2, ah3, __float_as_uint(bv3.z), __float_as_uint(bv3.w));
                    mma_tf32(D[mT][3][0], D[mT][3][1], D[mT][3][2], D[mT][3][3],
                             al0, al1, al2, al3, __float_as_uint(bv3.x), __float_as_uint(bv3.y));
                }
            }

            // ---- epilogue ----
            float qr[2][2] = {{0.0f, 0.0f}, {0.0f, 0.0f}};
            #pragma unroll
            for (int t = 0; t < 4; t++) {
                int j0 = warp * 32 + t * 8 + 2 * lanet;
                float b2_0 = B2[j0], b2_1 = B2[j0 + 1];
                float w3_0 = W3[j0], w3_1 = W3[j0 + 1];
                unsigned byte = 0;
                #pragma unroll
                for (int mT = 0; mT < 2; mT++) {
                    float z00 = D[mT][t][0] + b2_0;
                    float z01 = D[mT][t][1] + b2_1;
                    float z10 = D[mT][t][2] + b2_0;
                    float z11 = D[mT][t][3] + b2_1;
                    if (z00 > 0.0f) { byte |= 1u << (4 * mT + 0); qr[mT][0] += z00 * w3_0; }
                    if (z01 > 0.0f) { byte |= 1u << (4 * mT + 1); qr[mT][0] += z01 * w3_1; }
                    if (z10 > 0.0f) { byte |= 1u << (4 * mT + 2); qr[mT][1] += z10 * w3_0; }
                    if (z11 > 0.0f) { byte |= 1u << (4 * mT + 3); qr[mT][1] += z11 * w3_1; }
                }
                s_m2c[net * 1024 + (j0 >> 1) * 8 + laneq] = (unsigned char)byte;
            }
            #pragma unroll
            for (int mT = 0; mT < 2; mT++)
                #pragma unroll
                for (int u = 0; u < 2; u++) {
                    float v = qr[mT][u];
                    v += __shfl_xor_sync(0xffffffffu, v, 1);
                    v += __shfl_xor_sync(0xffffffffu, v, 2);
                    if (lanet == 0) s_red[warp * 32 + mT * 16 + 8 * u + laneq] = v;
                }
            __syncthreads();
            if (tid < NN) {
                float q = B3[0];
                #pragma unroll
                for (int w = 0; w < 8; w++) q += s_red[w * 32 + tid];
                s_q[net * 32 + tid] = q;
            }
            __syncthreads();
        }

        // ---- gate + stable partition ----
        if (tid < NN) {
            bool g = s_q[tid] <= s_q[32 + tid];
            unsigned ball = __ballot_sync(0xffffffffu, g);
            int c1 = __popc(ball);
            int below = __popc(ball & ((1u << tid) - 1u));
            int slot = g ? below : (c1 + (tid - below));
            s_orig[slot] = tid;
            if (tid == 0) s_cnt[0] = c1;
        }
        __syncthreads();

        // ================= backward (tf32 mma, gate-partitioned) =================
        {
            const int cnt1 = s_cnt[0];
            float4 w3av = *(const float4*)&W3a[bcol];
            float4 w3bv = *(const float4*)&W3b[bcol];
            // split W3 once (dh2 values are exactly W3[j] or 0)
            float4 w3aH, w3aL, w3bH, w3bL;
            w3aH.x = __uint_as_float(f2tf(w3av.x)); w3aL.x = __uint_as_float(f2tf(w3av.x - w3aH.x));
            w3aH.y = __uint_as_float(f2tf(w3av.y)); w3aL.y = __uint_as_float(f2tf(w3av.y - w3aH.y));
            w3aH.z = __uint_as_float(f2tf(w3av.z)); w3aL.z = __uint_as_float(f2tf(w3av.z - w3aH.z));
            w3aH.w = __uint_as_float(f2tf(w3av.w)); w3aL.w = __uint_as_float(f2tf(w3av.w - w3aH.w));
            w3bH.x = __uint_as_float(f2tf(w3bv.x)); w3bL.x = __uint_as_float(f2tf(w3bv.x - w3bH.x));
            w3bH.y = __uint_as_float(f2tf(w3bv.y)); w3bL.y = __uint_as_float(f2tf(w3bv.y - w3bH.y));
            w3bH.z = __uint_as_float(f2tf(w3bv.z)); w3bL.z = __uint_as_float(f2tf(w3bv.z - w3bH.z));
            w3bH.w = __uint_as_float(f2tf(w3bv.w)); w3bL.w = __uint_as_float(f2tf(w3bv.w - w3bH.w));

            // dh2 hi/lo pairs straight from pre-split W3
            #pragma unroll
            for (int i = 0; i < 8; i++) {
                int o = s_orig[n0 + i];
                bool sA = (n0 + i) < cnt1;
                const unsigned char* mb = s_m2c + (sA ? 0 : 1024);
                int bitb = 4 * (o >> 4) + 2 * ((o >> 3) & 1);
                unsigned by0 = mb[(bcol >> 1) * 8 + (o & 7)];
                unsigned by1 = mb[((bcol >> 1) + 1) * 8 + (o & 7)];
                float4 H = sA ? w3aH : w3bH;
                float4 L = sA ? w3aL : w3bL;
                bool m0 = (by0 >> (bitb + 0)) & 1u;
                bool m1 = (by0 >> (bitb + 1)) & 1u;
                bool m2 = (by1 >> (bitb + 0)) & 1u;
                bool m3 = (by1 >> (bitb + 1)) & 1u;
                float4 v01, v23;
                v01.x = m0 ? H.x : 0.0f; v01.y = m0 ? L.x : 0.0f;
                v01.z = m1 ? H.y : 0.0f; v01.w = m1 ? L.y : 0.0f;
                v23.x = m2 ? H.z : 0.0f; v23.y = m2 ? L.z : 0.0f;
                v23.z = m3 ? H.w : 0.0f; v23.w = m3 ? L.w : 0.0f;
                *(float4*)&s_h2[(n0 + i) * H2ST + bcol]     = v01;
                *(float4*)&s_h2[(n0 + i) * H2ST + bcol + 2] = v23;
            }
            __syncthreads();

            float D[2][4][4];
            #pragma unroll
            for (int mT = 0; mT < 2; mT++)
                #pragma unroll
                for (int t = 0; t < 4; t++)
                    #pragma unroll
                    for (int c = 0; c < 4; c++) D[mT][t][c] = 0.0f;

            #pragma unroll
            for (int mT = 0; mT < 2; mT++) {
                int rlo = mT * 16;
                bool pureA = (cnt1 >= rlo + 16);
                bool pureB = (cnt1 <= rlo);
                if (pureA || pureB) {
                    const float4* BB4 = pureA ? g_Bb[0] : g_Bb[1];
                    for (int ks = 0; ks < 32; ks++) {
                        int base = (ks * 32 + warp * 4) * 32 + lane;
                        int r = rlo + laneq;
                        const float2* p0 = s_h2 + r * H2ST + ks * 8 + lanet;
                        const float2* p1 = s_h2 + (r + 8) * H2ST + ks * 8 + lanet;
                        float2 A0 = p0[0], A2 = p0[4];
                        float2 A1 = p1[0], A3 = p1[4];
                        unsigned ah0 = __float_as_uint(A0.x), al0 = __float_as_uint(A0.y);
                        unsigned ah1 = __float_as_uint(A1.x), al1 = __float_as_uint(A1.y);
                        unsigned ah2 = __float_as_uint(A2.x), al2 = __float_as_uint(A2.y);
                        unsigned ah3 = __float_as_uint(A3.x), al3 = __float_as_uint(A3.y);
                        #pragma unroll
                        for (int t = 0; t < 4; t++) {
                            float4 bv = BB4[base + t * 32];
                            mma_tf32(D[mT][t][0], D[mT][t][1], D[mT][t][2], D[mT][t][3],
                                     ah0, ah1, ah2, ah3,
                                     __float_as_uint(bv.x), __float_as_uint(bv.y));
                            mma_tf32(D[mT][t][0], D[mT][t][1], D[mT][t][2], D[mT][t][3],
                                     ah0, ah1, ah2, ah3,
                                     __float_as_uint(bv.z), __float_as_uint(bv.w));
                            mma_tf32(D[mT][t][0], D[mT][t][1], D[mT][t][2], D[mT][t][3],
                                     al0, al1, al2, al3,
                                     __float_as_uint(bv.x), __float_as_uint(bv.y));
                        }
                    }
                } else {
                    int r = rlo + laneq;
                    bool rA0 = (r < cnt1), rA1 = (r + 8 < cnt1);
                    for (int ks = 0; ks < 32; ks++) {
                        int base = (ks * 32 + warp * 4) * 32 + lane;
                        const float2* p0 = s_h2 + r * H2ST + ks * 8 + lanet;
                        const float2* p1 = s_h2 + (r + 8) * H2ST + ks * 8 + lanet;
                        float2 A0 = p0[0], A2 = p0[4];
                        float2 A1 = p1[0], A3 = p1[4];
                        unsigned ah0 = __float_as_uint(A0.x), al0 = __float_as_uint(A0.y);
                        unsigned ah1 = __float_as_uint(A1.x), al1 = __float_as_uint(A1.y);
                        unsigned ah2 = __float_as_uint(A2.x), al2 = __float_as_uint(A2.y);
                        unsigned ah3 = __float_as_uint(A3.x), al3 = __float_as_uint(A3.y);
                        // pass A
                        {
                            unsigned xh0 = rA0 ? ah0 : 0u, xl0 = rA0 ? al0 : 0u;
                            unsigned xh1 = rA1 ? ah1 : 0u, xl1 = rA1 ? al1 : 0u;
                            unsigned xh2 = rA0 ? ah2 : 0u, xl2 = rA0 ? al2 : 0u;
                            unsigned xh3 = rA1 ? ah3 : 0u, xl3 = rA1 ? al3 : 0u;
                            #pragma unroll
                            for (int t = 0; t < 4; t++) {
                                float4 bv = g_Bb[0][base + t * 32];
                                mma_tf32(D[mT][t][0], D[mT][t][1], D[mT][t][2], D[mT][t][3],
                                         xh0, xh1, xh2, xh3,
                                         __float_as_uint(bv.x), __float_as_uint(bv.y));
                                mma_tf32(D[mT][t][0], D[mT][t][1], D[mT][t][2], D[mT][t][3],
                                         xh0, xh1, xh2, xh3,
                                         __float_as_uint(bv.z), __float_as_uint(bv.w));
                                mma_tf32(D[mT][t][0], D[mT][t][1], D[mT][t][2], D[mT][t][3],
                                         xl0, xl1, xl2, xl3,
                                         __float_as_uint(bv.x), __float_as_uint(bv.y));
                            }
                        }
                        // pass B
                        {
                            unsigned xh0 = rA0 ? 0u : ah0, xl0 = rA0 ? 0u : al0;
                            unsigned xh1 = rA1 ? 0u : ah1, xl1 = rA1 ? 0u : al1;
                            unsigned xh2 = rA0 ? 0u : ah2, xl2 = rA0 ? 0u : al2;
                            unsigned xh3 = rA1 ? 0u : ah3, xl3 = rA1 ? 0u : al3;
                            #pragma unroll
                            for (int t = 0; t < 4; t++) {
                                float4 bv = g_Bb[1][base + t * 32];
                                mma_tf32(D[mT][t][0], D[mT][t][1], D[mT][t][2], D[mT][t][3],
                                         xh0, xh1, xh2, xh3,
                                         __float_as_uint(bv.x), __float_as_uint(bv.y));
                                mma_tf32(D[mT][t][0], D[mT][t][1], D[mT][t][2], D[mT][t][3],
                                         xh0, xh1, xh2, xh3,
                                         __float_as_uint(bv.z), __float_as_uint(bv.w));
                                mma_tf32(D[mT][t][0], D[mT][t][1], D[mT][t][2], D[mT][t][3],
                                         xl0, xl1, xl2, xl3,
                                         __float_as_uint(bv.x), __float_as_uint(bv.y));
                            }
                        }
                    }
                }
            }
            __syncthreads();  // all dh2 reads complete before dh1 writes

            // dh1 epilogue: relu mask1, write fp32 rows (stride HFST)
            #pragma unroll
            for (int mT = 0; mT < 2; mT++) {
                int r0 = mT * 16 + laneq, r1 = r0 + 8;
                int o0 = s_orig[r0], o1 = s_orig[r1];
                int off0 = (r0 < cnt1) ? 0 : HH;
                int off1 = (r1 < cnt1) ? 0 : HH;
                #pragma unroll
                for (int t = 0; t < 4; t++) {
                    int c0 = warp * 32 + t * 8 + 2 * lanet;
                    unsigned w00 = s_m1[off0 + c0], w01 = s_m1[off0 + c0 + 1];
                    unsigned w10 = s_m1[off1 + c0], w11 = s_m1[off1 + c0 + 1];
                    float2 v0, v1;
                    v0.x = (w00 >> o0) & 1u ? D[mT][t][0] : 0.0f;
                    v0.y = (w01 >> o0) & 1u ? D[mT][t][1] : 0.0f;
                    v1.x = (w10 >> o1) & 1u ? D[mT][t][2] : 0.0f;
                    v1.y = (w11 >> o1) & 1u ? D[mT][t][3] : 0.0f;
                    *(float2*)&s_hf[r0 * HFST + c0] = v0;
                    *(float2*)&s_hf[r1 * HFST + c0] = v1;
                }
            }
            __syncthreads();

            if (tid < NN * DACT) {
                int sl = tid / DACT, d = tid % DACT;
                int o = s_orig[sl];
                const float* W1sel = (sl < cnt1) ? W1a : W1b;
                const float* w1r = W1sel + (DOBS + d) * HH;
                float sum = 0.0f;
                for (int k = 0; k < HH; k += 4) {
                    float4 h4 = *(const float4*)&s_hf[sl * HFST + k];
                    float4 w4 = *(const float4*)&w1r[k];
                    sum += h4.x * w4.x + h4.y * w4.y + h4.z * w4.z + h4.w * w4.w;
                }
                s_s[o * AST + d] = sum;
            }
            __syncthreads();
        }

        // ================= SVGD update =================
        for (int p = tid; p < NN * NN; p += 256) {
            int i = p >> 5, j = p & 31;
            float ds = 0.0f;
            #pragma unroll
            for (int d = 0; d < DACT; d++) {
                float df = s_a[i * AST + d] - s_a[j * AST + d];
                ds += df * df;
            }
            s_d2p[p] = ds;
            s_hf[p] = ds;
        }
        __syncthreads();

        for (int ks = 2; ks <= NN * NN; ks <<= 1) {
            for (int jj = ks >> 1; jj > 0; jj >>= 1) {
                #pragma unroll
                for (int e = 0; e < 4; e++) {
                    int idx = (e << 8) | tid;
                    int ixj = idx ^ jj;
                    if (ixj > idx) {
                        float va = s_hf[idx], vb = s_hf[ixj];
                        bool up = ((idx & ks) == 0);
                        if ((va > vb) == up) { s_hf[idx] = vb; s_hf[ixj] = va; }
                    }
                }
                __syncthreads();
            }
        }

        float med = 0.5f * (s_hf[511] + s_hf[512]);
        float hm = med / logf(33.0f);
        float gamma = 1.0f / (2.0f * hm + 1e-8f);
        for (int p = tid; p < NN * NN; p += 256)
            s_Kp[p] = expf(-gamma * s_d2p[p]);
        __syncthreads();

        float anew[DACT];
        float lpdelta = 0.0f;
        if (tid < NN) {
            int i = tid;
            float ai[DACT];
            #pragma unroll
            for (int d = 0; d < DACT; d++) ai[d] = s_a[i * AST + d];
            float ph[DACT] = {0, 0, 0, 0, 0, 0};
            float t1 = 0.0f, t2s = 0.0f;
            for (int j = 0; j < NN; j++) {
                float Kij = s_Kp[i * 32 + j];
                float dot = 0.0f;
                #pragma unroll
                for (int d = 0; d < DACT; d++) {
                    float df = ai[d] - s_a[j * AST + d];
                    float sj = s_s[j * AST + d];
                    dot += df * sj;
                    ph[d] += Kij * sj + 2.0f * gamma * Kij * df;
                }
                t1 += -2.0f * gamma * Kij * dot;
                float I = (i == j) ? 1.0f : 0.0f;
                t2s += 2.0f * gamma * Kij * s_d2p[i * 32 + j] - 6.0f * (Kij - I);
            }
            t1 *= (1.0f / 31.0f);
            float t2 = -2.0f * gamma * t2s * (1.0f / 31.0f);
            lpdelta = 0.05f * (t1 + t2);
            #pragma unroll
            for (int d = 0; d < DACT; d++)
                anew[d] = ai[d] + 0.05f * ph[d] * (1.0f / 32.0f);
        }
        __syncthreads();
        if (tid < NN) {
            s_logp[tid] -= lpdelta;
            #pragma unroll
            for (int d = 0; d < DACT; d++) s_a[tid * AST + d] = anew[d];
        }
        __syncthreads();
    }

    // ================= finalize =================
    __syncthreads();
    if (tid < NN) {
        int n = tid;
        float lpt = 0.0f;
        #pragma unroll
        for (int d = 0; d < DACT; d++) {
            float av = s_a[n * AST + d];
            float x = -2.0f * av;
            float sp = (x > 0.0f) ? (x + log1pf(expf(-x))) : log1pf(expf(x));
            lpt += -2.0f * (0.6931471805599453f - av - sp);
            out[(b * NN + n) * DACT + d] = tanhf(av);
        }
        s_red[n] = s_lpn[n] + s_logp[n] + lpt;
    }
    __syncthreads();
    if (tid == 0) {
        float m = 0.0f;
        for (int n = 0; n < NN; n++) m += s_red[n];
        out[BB * NN * DACT + b] = m * (1.0f / 32.0f);
    }
}

extern "C" void kernel_launch(void* const* d_in, const int* in_sizes, int n_in,
                              void* d_out, int out_size) {
    const float* obs  = (const float*)d_in[0];
    const float* a0   = (const float*)d_in[1];
    const float* q1W1 = (const float*)d_in[2];
    const float* q1b1 = (const float*)d_in[3];
    const float* q1W2 = (const float*)d_in[4];
    const float* q1b2 = (const float*)d_in[5];
    const float* q1W3 = (const float*)d_in[6];
    const float* q1b3 = (const float*)d_in[7];
    const float* q2W1 = (const float*)d_in[8];
    const float* q2b1 = (const float*)d_in[9];
    const float* q2W2 = (const float*)d_in[10];
    const float* q2b2 = (const float*)d_in[11];
    const float* q2W3 = (const float*)d_in[12];
    const float* q2b3 = (const float*)d_in[13];
    float* out = (float*)d_out;

    cudaFuncSetAttribute(svgd_kernel,
                         cudaFuncAttributeMaxDynamicSharedMemorySize, SM_TOTAL);

    prep_weights<<<dim3(128, 2), 256>>>(q1W2, q2W2);
    svgd_kernel<<<BB, 256, SM_TOTAL>>>(obs, a0,
                             q1W1, q1b1, q1W2, q1b2, q1W3, q1b3,
                             q2W1, q2b1, q2W2, q2b2, q2W3, q2b3,
                             out);
}

// round 12
// speedup vs baseline: 4.1514x; 1.1472x over previous
#include <cuda_runtime.h>
#include <math.h>

#define BB 1024
#define NN 32
#define DOBS 17
#define DACT 6
#define DIN 23
#define HH 256
#define NSTEPS 5
#define AST 6
#define H2ST 260    // s_h2 row stride in float2 units
#define HFST 520    // same region viewed as floats
#define X2ST 26     // s_x2 row stride in float2 units

// Fragment-major packed float4 = (hi_breg0, hi_breg1, lo_breg0, lo_breg1),
// flat idx = (ks*32 + nTg)*32 + lane.
// g_Bf: fwd layer2, B = W2      (k = ks*8+(lane&3)[+4], j = nTg*8+(lane>>2))
// g_Bb: bwd layer2, B = W3.*W2T (j = ks*8+(lane&3)[+4], k = nTg*8+(lane>>2))
// g_B1: fwd layer1, B = W1      (k = ks*8+(lane&3)[+4] (<23), j = nTg*8+(lane>>2))
__device__ float4 g_Bf[2][32768];
__device__ float4 g_Bb[2][32768];
__device__ float4 g_B1[2][3072];

__device__ __forceinline__ unsigned f2tf(float x) {
    unsigned r; asm("cvt.rna.tf32.f32 %0, %1;" : "=r"(r) : "f"(x)); return r;
}

__global__ void prep_weights(const float* __restrict__ w2a,
                             const float* __restrict__ w2b,
                             const float* __restrict__ w3a,
                             const float* __restrict__ w3b,
                             const float* __restrict__ w1a,
                             const float* __restrict__ w1b) {
    int idx = blockIdx.x * 256 + threadIdx.x;   // 0..32767
    int net = blockIdx.y;
    const float* W2 = net ? w2b : w2a;
    const float* W3 = net ? w3b : w3a;
    int lane = idx & 31;
    int nTg  = (idx >> 5) & 31;
    int ks   = idx >> 10;
    // forward layer2
    {
        int k0 = ks * 8 + (lane & 3);
        int j  = nTg * 8 + (lane >> 2);
        float w0 = W2[k0 * HH + j], w1 = W2[(k0 + 4) * HH + j];
        float h0 = __uint_as_float(f2tf(w0));
        float h1 = __uint_as_float(f2tf(w1));
        g_Bf[net][idx] = make_float4(h0, h1,
                                     __uint_as_float(f2tf(w0 - h0)),
                                     __uint_as_float(f2tf(w1 - h1)));
    }
    // backward: V[k][j] = W3[j] * W2[k][j]
    {
        int j0 = ks * 8 + (lane & 3);
        int k  = nTg * 8 + (lane >> 2);
        float w0 = W3[j0]     * W2[k * HH + j0];
        float w1 = W3[j0 + 4] * W2[k * HH + j0 + 4];
        float h0 = __uint_as_float(f2tf(w0));
        float h1 = __uint_as_float(f2tf(w1));
        g_Bb[net][idx] = make_float4(h0, h1,
                                     __uint_as_float(f2tf(w0 - h0)),
                                     __uint_as_float(f2tf(w1 - h1)));
    }
    // forward layer1 (K padded to 24)
    if (idx < 3072) {
        const float* W1 = net ? w1b : w1a;
        int k0 = ks * 8 + (lane & 3);
        int j  = nTg * 8 + (lane >> 2);
        float w0 = (k0 < DIN)     ? W1[k0 * HH + j]       : 0.0f;
        float w1 = (k0 + 4 < DIN) ? W1[(k0 + 4) * HH + j] : 0.0f;
        float h0 = __uint_as_float(f2tf(w0));
        float h1 = __uint_as_float(f2tf(w1));
        g_B1[net][idx] = make_float4(h0, h1,
                                     __uint_as_float(f2tf(w0 - h0)),
                                     __uint_as_float(f2tf(w1 - h1)));
    }
}

__device__ __forceinline__ void mma_tf32(float& d0, float& d1, float& d2, float& d3,
                                         unsigned a0, unsigned a1, unsigned a2, unsigned a3,
                                         unsigned b0, unsigned b1) {
    asm("mma.sync.aligned.m16n8k8.row.col.f32.tf32.tf32.f32 "
        "{%0,%1,%2,%3}, {%4,%5,%6,%7}, {%8,%9}, {%0,%1,%2,%3};"
        : "+f"(d0), "+f"(d1), "+f"(d2), "+f"(d3)
        : "r"(a0), "r"(a1), "r"(a2), "r"(a3), "r"(b0), "r"(b1));
}

// dynamic smem layout (bytes)
#define SM_H2    0        // float2[32*260] = 66560
#define SM_X2    66560    // float2[32*26]  = 6656  (aliased by d2 in svgd phase)
#define SM_U     73216    // m1c[2048] m2c[2048] K[4096] = 8192
#define SM_Q     81408    // float[64]
#define SM_S     81664    // float[192]
#define SM_A     82432    // float[192]
#define SM_LOGP  83200    // float[32]
#define SM_LPN   83328    // float[32]
#define SM_RED   83456    // float[256]
#define SM_ORIG  84480    // int[32]
#define SM_CNT   84608    // int
#define SM_TOTAL 84624

__global__ __launch_bounds__(256, 2) void svgd_kernel(
    const float* __restrict__ obs, const float* __restrict__ a0,
    const float* __restrict__ W1a, const float* __restrict__ B1a,
    const float* __restrict__ W2a, const float* __restrict__ B2a,
    const float* __restrict__ W3a, const float* __restrict__ B3a,
    const float* __restrict__ W1b, const float* __restrict__ B1b,
    const float* __restrict__ W2b, const float* __restrict__ B2b,
    const float* __restrict__ W3b, const float* __restrict__ B3b,
    float* __restrict__ out)
{
    extern __shared__ __align__(16) unsigned char smem[];
    float2* s_h2 = (float2*)(smem + SM_H2);
    float*  s_hf = (float*)(smem + SM_H2);
    float2* s_x2 = (float2*)(smem + SM_X2);
    unsigned char* s_u = smem + SM_U;
    float*  s_q  = (float*)(smem + SM_Q);
    float*  s_s  = (float*)(smem + SM_S);
    float*  s_a  = (float*)(smem + SM_A);
    float*  s_logp = (float*)(smem + SM_LOGP);
    float*  s_lpn  = (float*)(smem + SM_LPN);
    float*  s_red  = (float*)(smem + SM_RED);
    int*    s_orig = (int*)(smem + SM_ORIG);
    int*    s_cnt  = (int*)(smem + SM_CNT);

    unsigned char* s_m1c = s_u;                    // [net*1024 + (k>>1)*8 + (n&7)]
    unsigned char* s_m2c = s_u + 2048;             // [net*1024 + (j>>1)*8 + (n&7)]
    float* s_d2p = (float*)(smem + SM_X2);
    float* s_Kp  = (float*)(s_u + 4096);

    const int b = blockIdx.x;
    const int tid = threadIdx.x;
    const int lane = tid & 31;
    const int warp = tid >> 5;
    const int laneq = lane >> 2;
    const int lanet = lane & 3;

    for (int idx = tid; idx < NN * DACT; idx += 256) {
        int n = idx / DACT, d = idx % DACT;
        s_a[n * AST + d] = a0[(b * NN + n) * DACT + d];
    }
    if (tid < NN) s_logp[tid] = 0.0f;
    __syncthreads();
    if (tid < NN) {
        float ss = 0.0f;
        #pragma unroll
        for (int d = 0; d < DACT; d++) { float v = s_a[tid * AST + d]; ss += v * v; }
        s_lpn[tid] = -3.0f * logf(6.283185307179586f * 0.3f) - (0.5f / 0.3f) * ss;
    }

    for (int step = 0; step < NSTEPS; ++step) {
        __syncthreads();
        // build pre-split inputs x2[n][k] (obs | act | pad), hi/lo tf32 pairs
        for (int idx = tid; idx < NN * X2ST; idx += 256) {
            int n = idx / X2ST, k = idx % X2ST;
            float v = 0.0f;
            if (k < DOBS) v = obs[(b * NN + n) * DOBS + k];
            else if (k < DIN) v = s_a[n * AST + (k - DOBS)];
            float hi = __uint_as_float(f2tf(v));
            float lo = __uint_as_float(f2tf(v - hi));
            s_x2[n * X2ST + k] = make_float2(hi, lo);
        }
        __syncthreads();

        // ================= forward both Q nets (both layers via tf32 mma) =================
        for (int net = 0; net < 2; ++net) {
            const float* B1 = net ? B1b : B1a;
            const float* B2 = net ? B2b : B2a;
            const float* W3 = net ? W3b : W3a;
            const float* B3 = net ? B3b : B3a;

            // ---- layer1 mma: z1 = x @ W1 ----
            {
                float D[2][4][4];
                #pragma unroll
                for (int mT = 0; mT < 2; mT++)
                    #pragma unroll
                    for (int t = 0; t < 4; t++)
                        #pragma unroll
                        for (int c = 0; c < 4; c++) D[mT][t][c] = 0.0f;

                const float4* B1F = g_B1[net];
                #pragma unroll
                for (int ks = 0; ks < 3; ks++) {
                    int base = (ks * 32 + warp * 4) * 32 + lane;
                    float4 bv0 = B1F[base];
                    float4 bv1 = B1F[base + 32];
                    float4 bv2 = B1F[base + 64];
                    float4 bv3 = B1F[base + 96];
                    #pragma unroll
                    for (int mT = 0; mT < 2; mT++) {
                        int r = mT * 16 + laneq;
                        float2 A0 = s_x2[r * X2ST + ks * 8 + lanet];
                        float2 A1 = s_x2[(r + 8) * X2ST + ks * 8 + lanet];
                        float2 A2 = s_x2[r * X2ST + ks * 8 + lanet + 4];
                        float2 A3 = s_x2[(r + 8) * X2ST + ks * 8 + lanet + 4];
                        unsigned ah0 = __float_as_uint(A0.x), al0 = __float_as_uint(A0.y);
                        unsigned ah1 = __float_as_uint(A1.x), al1 = __float_as_uint(A1.y);
                        unsigned ah2 = __float_as_uint(A2.x), al2 = __float_as_uint(A2.y);
                        unsigned ah3 = __float_as_uint(A3.x), al3 = __float_as_uint(A3.y);
                        mma_tf32(D[mT][0][0], D[mT][0][1], D[mT][0][2], D[mT][0][3],
                                 ah0, ah1, ah2, ah3, __float_as_uint(bv0.x), __float_as_uint(bv0.y));
                        mma_tf32(D[mT][0][0], D[mT][0][1], D[mT][0][2], D[mT][0][3],
                                 ah0, ah1, ah2, ah3, __float_as_uint(bv0.z), __float_as_uint(bv0.w));
                        mma_tf32(D[mT][0][0], D[mT][0][1], D[mT][0][2], D[mT][0][3],
                                 al0, al1, al2, al3, __float_as_uint(bv0.x), __float_as_uint(bv0.y));
                        mma_tf32(D[mT][1][0], D[mT][1][1], D[mT][1][2], D[mT][1][3],
                                 ah0, ah1, ah2, ah3, __float_as_uint(bv1.x), __float_as_uint(bv1.y));
                        mma_tf32(D[mT][1][0], D[mT][1][1], D[mT][1][2], D[mT][1][3],
                                 ah0, ah1, ah2, ah3, __float_as_uint(bv1.z), __float_as_uint(bv1.w));
                        mma_tf32(D[mT][1][0], D[mT][1][1], D[mT][1][2], D[mT][1][3],
                                 al0, al1, al2, al3, __float_as_uint(bv1.x), __float_as_uint(bv1.y));
                        mma_tf32(D[mT][2][0], D[mT][2][1], D[mT][2][2], D[mT][2][3],
                                 ah0, ah1, ah2, ah3, __float_as_uint(bv2.x), __float_as_uint(bv2.y));
                        mma_tf32(D[mT][2][0], D[mT][2][1], D[mT][2][2], D[mT][2][3],
                                 ah0, ah1, ah2, ah3, __float_as_uint(bv2.z), __float_as_uint(bv2.w));
                        mma_tf32(D[mT][2][0], D[mT][2][1], D[mT][2][2], D[mT][2][3],
                                 al0, al1, al2, al3, __float_as_uint(bv2.x), __float_as_uint(bv2.y));
                        mma_tf32(D[mT][3][0], D[mT][3][1], D[mT][3][2], D[mT][3][3],
                                 ah0, ah1, ah2, ah3, __float_as_uint(bv3.x), __float_as_uint(bv3.y));
                        mma_tf32(D[mT][3][0], D[mT][3][1], D[mT][3][2], D[mT][3][3],
                                 ah0, ah1, ah2, ah3, __float_as_uint(bv3.z), __float_as_uint(bv3.w));
                        mma_tf32(D[mT][3][0], D[mT][3][1], D[mT][3][2], D[mT][3][3],
                                 al0, al1, al2, al3, __float_as_uint(bv3.x), __float_as_uint(bv3.y));
                    }
                }

                // epilogue: bias, relu, write h hi/lo pairs + mask1 bytes
                #pragma unroll
                for (int t = 0; t < 4; t++) {
                    int j0 = warp * 32 + t * 8 + 2 * lanet;
                    float b1_0 = B1[j0], b1_1 = B1[j0 + 1];
                    unsigned byte = 0;
                    #pragma unroll
                    for (int mT = 0; mT < 2; mT++) {
                        int r0 = mT * 16 + laneq, r1 = r0 + 8;
                        float z00 = D[mT][t][0] + b1_0;
                        float z01 = D[mT][t][1] + b1_1;
                        float z10 = D[mT][t][2] + b1_0;
                        float z11 = D[mT][t][3] + b1_1;
                        if (z00 > 0.0f) byte |= 1u << (4 * mT + 0); else z00 = 0.0f;
                        if (z01 > 0.0f) byte |= 1u << (4 * mT + 1); else z01 = 0.0f;
                        if (z10 > 0.0f) byte |= 1u << (4 * mT + 2); else z10 = 0.0f;
                        if (z11 > 0.0f) byte |= 1u << (4 * mT + 3); else z11 = 0.0f;
                        float h00 = __uint_as_float(f2tf(z00));
                        float h01 = __uint_as_float(f2tf(z01));
                        float h10 = __uint_as_float(f2tf(z10));
                        float h11 = __uint_as_float(f2tf(z11));
                        *(float4*)&s_h2[r0 * H2ST + j0] =
                            make_float4(h00, __uint_as_float(f2tf(z00 - h00)),
                                        h01, __uint_as_float(f2tf(z01 - h01)));
                        *(float4*)&s_h2[r1 * H2ST + j0] =
                            make_float4(h10, __uint_as_float(f2tf(z10 - h10)),
                                        h11, __uint_as_float(f2tf(z11 - h11)));
                    }
                    s_m1c[net * 1024 + (j0 >> 1) * 8 + laneq] = (unsigned char)byte;
                }
            }
            __syncthreads();

            // ---- layer2 mma ----
            float D[2][4][4];
            #pragma unroll
            for (int mT = 0; mT < 2; mT++)
                #pragma unroll
                for (int t = 0; t < 4; t++)
                    #pragma unroll
                    for (int c = 0; c < 4; c++) D[mT][t][c] = 0.0f;

            const float4* BF = g_Bf[net];
            for (int ks = 0; ks < 32; ks++) {
                int base = (ks * 32 + warp * 4) * 32 + lane;
                float4 bv0 = BF[base];
                float4 bv1 = BF[base + 32];
                float4 bv2 = BF[base + 64];
                float4 bv3 = BF[base + 96];
                #pragma unroll
                for (int mT = 0; mT < 2; mT++) {
                    int r = mT * 16 + laneq;
                    const float2* p0 = s_h2 + r * H2ST + ks * 8 + lanet;
                    const float2* p1 = s_h2 + (r + 8) * H2ST + ks * 8 + lanet;
                    float2 A0 = p0[0], A2 = p0[4];
                    float2 A1 = p1[0], A3 = p1[4];
                    unsigned ah0 = __float_as_uint(A0.x), al0 = __float_as_uint(A0.y);
                    unsigned ah1 = __float_as_uint(A1.x), al1 = __float_as_uint(A1.y);
                    unsigned ah2 = __float_as_uint(A2.x), al2 = __float_as_uint(A2.y);
                    unsigned ah3 = __float_as_uint(A3.x), al3 = __float_as_uint(A3.y);
                    mma_tf32(D[mT][0][0], D[mT][0][1], D[mT][0][2], D[mT][0][3],
                             ah0, ah1, ah2, ah3, __float_as_uint(bv0.x), __float_as_uint(bv0.y));
                    mma_tf32(D[mT][0][0], D[mT][0][1], D[mT][0][2], D[mT][0][3],
                             ah0, ah1, ah2, ah3, __float_as_uint(bv0.z), __float_as_uint(bv0.w));
                    mma_tf32(D[mT][0][0], D[mT][0][1], D[mT][0][2], D[mT][0][3],
                             al0, al1, al2, al3, __float_as_uint(bv0.x), __float_as_uint(bv0.y));
                    mma_tf32(D[mT][1][0], D[mT][1][1], D[mT][1][2], D[mT][1][3],
                             ah0, ah1, ah2, ah3, __float_as_uint(bv1.x), __float_as_uint(bv1.y));
                    mma_tf32(D[mT][1][0], D[mT][1][1], D[mT][1][2], D[mT][1][3],
                             ah0, ah1, ah2, ah3, __float_as_uint(bv1.z), __float_as_uint(bv1.w));
                    mma_tf32(D[mT][1][0], D[mT][1][1], D[mT][1][2], D[mT][1][3],
                             al0, al1, al2, al3, __float_as_uint(bv1.x), __float_as_uint(bv1.y));
                    mma_tf32(D[mT][2][0], D[mT][2][1], D[mT][2][2], D[mT][2][3],
                             ah0, ah1, ah2, ah3, __float_as_uint(bv2.x), __float_as_uint(bv2.y));
                    mma_tf32(D[mT][2][0], D[mT][2][1], D[mT][2][2], D[mT][2][3],
                             ah0, ah1, ah2, ah3, __float_as_uint(bv2.z), __float_as_uint(bv2.w));
                    mma_tf32(D[mT][2][0], D[mT][2][1], D[mT][2][2], D[mT][2][3],
                             al0, al1, al2, al3, __float_as_uint(bv2.x), __float_as_uint(bv2.y));
                    mma_tf32(D[mT][3][0], D[mT][3][1], D[mT][3][2], D[mT][3][3],
                             ah0, ah1, ah2, ah3, __float_as_uint(bv3.x), __float_as_uint(bv3.y));
                    mma_tf32(D[mT][3][0], D[mT][3][1], D[mT][3][2], D[mT][3][3],
                             ah0, ah1, ah2, ah3, __float_as_uint(bv3.z), __float_as_uint(bv3.w));
                    mma_tf32(D[mT][3][0], D[mT][3][1], D[mT][3][2], D[mT][3][3],
                             al0, al1, al2, al3, __float_as_uint(bv3.x), __float_as_uint(bv3.y));
                }
            }

            // epilogue: bias, relu, mask2 bytes, q partials
            float qr[2][2] = {{0.0f, 0.0f}, {0.0f, 0.0f}};
            #pragma unroll
            for (int t = 0; t < 4; t++) {
                int j0 = warp * 32 + t * 8 + 2 * lanet;
                float b2_0 = B2[j0], b2_1 = B2[j0 + 1];
                float w3_0 = W3[j0], w3_1 = W3[j0 + 1];
                unsigned byte = 0;
                #pragma unroll
                for (int mT = 0; mT < 2; mT++) {
                    float z00 = D[mT][t][0] + b2_0;
                    float z01 = D[mT][t][1] + b2_1;
                    float z10 = D[mT][t][2] + b2_0;
                    float z11 = D[mT][t][3] + b2_1;
                    if (z00 > 0.0f) { byte |= 1u << (4 * mT + 0); qr[mT][0] += z00 * w3_0; }
                    if (z01 > 0.0f) { byte |= 1u << (4 * mT + 1); qr[mT][0] += z01 * w3_1; }
                    if (z10 > 0.0f) { byte |= 1u << (4 * mT + 2); qr[mT][1] += z10 * w3_0; }
                    if (z11 > 0.0f) { byte |= 1u << (4 * mT + 3); qr[mT][1] += z11 * w3_1; }
                }
                s_m2c[net * 1024 + (j0 >> 1) * 8 + laneq] = (unsigned char)byte;
            }
            #pragma unroll
            for (int mT = 0; mT < 2; mT++)
                #pragma unroll
                for (int u = 0; u < 2; u++) {
                    float v = qr[mT][u];
                    v += __shfl_xor_sync(0xffffffffu, v, 1);
                    v += __shfl_xor_sync(0xffffffffu, v, 2);
                    if (lanet == 0) s_red[warp * 32 + mT * 16 + 8 * u + laneq] = v;
                }
            __syncthreads();
            if (tid < NN) {
                float q = B3[0];
                #pragma unroll
                for (int w = 0; w < 8; w++) q += s_red[w * 32 + tid];
                s_q[net * 32 + tid] = q;
            }
            __syncthreads();
        }

        // ---- gate + stable partition ----
        if (tid < NN) {
            bool g = s_q[tid] <= s_q[32 + tid];
            unsigned ball = __ballot_sync(0xffffffffu, g);
            int c1 = __popc(ball);
            int below = __popc(ball & ((1u << tid) - 1u));
            int slot = g ? below : (c1 + (tid - below));
            s_orig[slot] = tid;
            if (tid == 0) s_cnt[0] = c1;
        }
        __syncthreads();

        // ================= backward: dh1 = mask2 @ V^T  (A binary/exact) =================
        {
            const int cnt1 = s_cnt[0];
            float D[2][4][4];
            #pragma unroll
            for (int mT = 0; mT < 2; mT++)
                #pragma unroll
                for (int t = 0; t < 4; t++)
                    #pragma unroll
                    for (int c = 0; c < 4; c++) D[mT][t][c] = 0.0f;

            #pragma unroll
            for (int mT = 0; mT < 2; mT++) {
                int rr0 = mT * 16 + laneq, rr1 = rr0 + 8;
                int o0 = s_orig[rr0], o1 = s_orig[rr1];
                int bit0 = 4 * (o0 >> 4) + 2 * ((o0 >> 3) & 1) + (lanet & 1);
                int bit1 = 4 * (o1 >> 4) + 2 * ((o1 >> 3) & 1) + (lanet & 1);
                int byo0 = (lanet >> 1) * 8 + (o0 & 7);
                int byo1 = (lanet >> 1) * 8 + (o1 & 7);
                bool pureA = (cnt1 >= mT * 16 + 16);
                bool pureB = (cnt1 <= mT * 16);
                if (pureA || pureB) {
                    const unsigned char* mb = s_m2c + (pureA ? 0 : 1024);
                    const float4* BB4 = pureA ? g_Bb[0] : g_Bb[1];
                    for (int ks = 0; ks < 32; ks++) {
                        const unsigned char* mk = mb + ks * 32;
                        unsigned a0 = ((mk[byo0]      >> bit0) & 1u) ? 0x3f800000u : 0u;
                        unsigned a1 = ((mk[byo1]      >> bit1) & 1u) ? 0x3f800000u : 0u;
                        unsigned a2 = ((mk[byo0 + 16] >> bit0) & 1u) ? 0x3f800000u : 0u;
                        unsigned a3 = ((mk[byo1 + 16] >> bit1) & 1u) ? 0x3f800000u : 0u;
                        int base = (ks * 32 + warp * 4) * 32 + lane;
                        #pragma unroll
                        for (int t = 0; t < 4; t++) {
                            float4 bv = BB4[base + t * 32];
                            mma_tf32(D[mT][t][0], D[mT][t][1], D[mT][t][2], D[mT][t][3],
                                     a0, a1, a2, a3,
                                     __float_as_uint(bv.x), __float_as_uint(bv.y));
                            mma_tf32(D[mT][t][0], D[mT][t][1], D[mT][t][2], D[mT][t][3],
                                     a0, a1, a2, a3,
                                     __float_as_uint(bv.z), __float_as_uint(bv.w));
                        }
                    }
                } else {
                    bool rA0 = (rr0 < cnt1), rA1 = (rr1 < cnt1);
                    for (int ks = 0; ks < 32; ks++) {
                        const unsigned char* mk0 = s_m2c + ks * 32;
                        const unsigned char* mk1 = s_m2c + 1024 + ks * 32;
                        unsigned p0 = (rA0 && ((mk0[byo0]      >> bit0) & 1u)) ? 0x3f800000u : 0u;
                        unsigned p1 = (rA1 && ((mk0[byo1]      >> bit1) & 1u)) ? 0x3f800000u : 0u;
                        unsigned p2 = (rA0 && ((mk0[byo0 + 16] >> bit0) & 1u)) ? 0x3f800000u : 0u;
                        unsigned p3 = (rA1 && ((mk0[byo1 + 16] >> bit1) & 1u)) ? 0x3f800000u : 0u;
                        unsigned q0 = (!rA0 && ((mk1[byo0]      >> bit0) & 1u)) ? 0x3f800000u : 0u;
                        unsigned q1 = (!rA1 && ((mk1[byo1]      >> bit1) & 1u)) ? 0x3f800000u : 0u;
                        unsigned q2 = (!rA0 && ((mk1[byo0 + 16] >> bit0) & 1u)) ? 0x3f800000u : 0u;
                        unsigned q3 = (!rA1 && ((mk1[byo1 + 16] >> bit1) & 1u)) ? 0x3f800000u : 0u;
                        int base = (ks * 32 + warp * 4) * 32 + lane;
                        #pragma unroll
                        for (int t = 0; t < 4; t++) {
                            float4 bvA = g_Bb[0][base + t * 32];
                            mma_tf32(D[mT][t][0], D[mT][t][1], D[mT][t][2], D[mT][t][3],
                                     p0, p1, p2, p3,
                                     __float_as_uint(bvA.x), __float_as_uint(bvA.y));
                            mma_tf32(D[mT][t][0], D[mT][t][1], D[mT][t][2], D[mT][t][3],
                                     p0, p1, p2, p3,
                                     __float_as_uint(bvA.z), __float_as_uint(bvA.w));
                            float4 bvB = g_Bb[1][base + t * 32];
                            mma_tf32(D[mT][t][0], D[mT][t][1], D[mT][t][2], D[mT][t][3],
                                     q0, q1, q2, q3,
                                     __float_as_uint(bvB.x), __float_as_uint(bvB.y));
                            mma_tf32(D[mT][t][0], D[mT][t][1], D[mT][t][2], D[mT][t][3],
                                     q0, q1, q2, q3,
                                     __float_as_uint(bvB.z), __float_as_uint(bvB.w));
                        }
                    }
                }
            }

            // dh1 epilogue: apply relu mask1 (byte-encoded), write fp32 rows
            #pragma unroll
            for (int mT = 0; mT < 2; mT++) {
                int r0 = mT * 16 + laneq, r1 = r0 + 8;
                int o0 = s_orig[r0], o1 = s_orig[r1];
                const unsigned char* mb0 = s_m1c + ((r0 < cnt1) ? 0 : 1024);
                const unsigned char* mb1 = s_m1c + ((r1 < cnt1) ? 0 : 1024);
                int bitb0 = 4 * (o0 >> 4) + 2 * ((o0 >> 3) & 1);
                int bitb1 = 4 * (o1 >> 4) + 2 * ((o1 >> 3) & 1);
                #pragma unroll
                for (int t = 0; t < 4; t++) {
                    int c0 = warp * 32 + t * 8 + 2 * lanet;
                    unsigned by0 = mb0[(c0 >> 1) * 8 + (o0 & 7)];
                    unsigned by1 = mb1[(c0 >> 1) * 8 + (o1 & 7)];
                    float2 v0, v1;
                    v0.x = (by0 >> (bitb0 + 0)) & 1u ? D[mT][t][0] : 0.0f;
                    v0.y = (by0 >> (bitb0 + 1)) & 1u ? D[mT][t][1] : 0.0f;
                    v1.x = (by1 >> (bitb1 + 0)) & 1u ? D[mT][t][2] : 0.0f;
                    v1.y = (by1 >> (bitb1 + 1)) & 1u ? D[mT][t][3] : 0.0f;
                    *(float2*)&s_hf[r0 * HFST + c0] = v0;
                    *(float2*)&s_hf[r1 * HFST + c0] = v1;
                }
            }
            __syncthreads();

            // da[orig][d] = sum_k dh1[slot][k] * W1_sel[17+d][k]
            if (tid < NN * DACT) {
                int sl = tid / DACT, d = tid % DACT;
                int o = s_orig[sl];
                const float* W1sel = (sl < cnt1) ? W1a : W1b;
                const float* w1r = W1sel + (DOBS + d) * HH;
                float sum = 0.0f;
                for (int k = 0; k < HH; k += 4) {
                    float4 h4 = *(const float4*)&s_hf[sl * HFST + k];
                    float4 w4 = *(const float4*)&w1r[k];
                    sum += h4.x * w4.x + h4.y * w4.y + h4.z * w4.z + h4.w * w4.w;
                }
                s_s[o * AST + d] = sum;
            }
            __syncthreads();
        }

        // ================= SVGD update =================
        for (int p = tid; p < NN * NN; p += 256) {
            int i = p >> 5, j = p & 31;
            float ds = 0.0f;
            #pragma unroll
            for (int d = 0; d < DACT; d++) {
                float df = s_a[i * AST + d] - s_a[j * AST + d];
                ds += df * df;
            }
            s_d2p[p] = ds;
            s_hf[p] = ds;
        }
        __syncthreads();

        for (int ks = 2; ks <= NN * NN; ks <<= 1) {
            for (int jj = ks >> 1; jj > 0; jj >>= 1) {
                #pragma unroll
                for (int e = 0; e < 4; e++) {
                    int idx = (e << 8) | tid;
                    int ixj = idx ^ jj;
                    if (ixj > idx) {
                        float va = s_hf[idx], vb = s_hf[ixj];
                        bool up = ((idx & ks) == 0);
                        if ((va > vb) == up) { s_hf[idx] = vb; s_hf[ixj] = va; }
                    }
                }
                __syncthreads();
            }
        }

        float med = 0.5f * (s_hf[511] + s_hf[512]);
        float hm = med / logf(33.0f);
        float gamma = 1.0f / (2.0f * hm + 1e-8f);
        for (int p = tid; p < NN * NN; p += 256)
            s_Kp[p] = expf(-gamma * s_d2p[p]);
        __syncthreads();

        float anew[DACT];
        float lpdelta = 0.0f;
        if (tid < NN) {
            int i = tid;
            float ai[DACT];
            #pragma unroll
            for (int d = 0; d < DACT; d++) ai[d] = s_a[i * AST + d];
            float ph[DACT] = {0, 0, 0, 0, 0, 0};
            float t1 = 0.0f, t2s = 0.0f;
            for (int j = 0; j < NN; j++) {
                float Kij = s_Kp[i * 32 + j];
                float dot = 0.0f;
                #pragma unroll
                for (int d = 0; d < DACT; d++) {
                    float df = ai[d] - s_a[j * AST + d];
                    float sj = s_s[j * AST + d];
                    dot += df * sj;
                    ph[d] += Kij * sj + 2.0f * gamma * Kij * df;
                }
                t1 += -2.0f * gamma * Kij * dot;
                float I = (i == j) ? 1.0f : 0.0f;
                t2s += 2.0f * gamma * Kij * s_d2p[i * 32 + j] - 6.0f * (Kij - I);
            }
            t1 *= (1.0f / 31.0f);
            float t2 = -2.0f * gamma * t2s * (1.0f / 31.0f);
            lpdelta = 0.05f * (t1 + t2);
            #pragma unroll
            for (int d = 0; d < DACT; d++)
                anew[d] = ai[d] + 0.05f * ph[d] * (1.0f / 32.0f);
        }
        __syncthreads();
        if (tid < NN) {
            s_logp[tid] -= lpdelta;
            #pragma unroll
            for (int d = 0; d < DACT; d++) s_a[tid * AST + d] = anew[d];
        }
        __syncthreads();
    }

    // ================= finalize =================
    __syncthreads();
    if (tid < NN) {
        int n = tid;
        float lpt = 0.0f;
        #pragma unroll
        for (int d = 0; d < DACT; d++) {
            float av = s_a[n * AST + d];
            float x = -2.0f * av;
            float sp = (x > 0.0f) ? (x + log1pf(expf(-x))) : log1pf(expf(x));
            lpt += -2.0f * (0.6931471805599453f - av - sp);
            out[(b * NN + n) * DACT + d] = tanhf(av);
        }
        s_red[n] = s_lpn[n] + s_logp[n] + lpt;
    }
    __syncthreads();
    if (tid == 0) {
        float m = 0.0f;
        for (int n = 0; n < NN; n++) m += s_red[n];
        out[BB * NN * DACT + b] = m * (1.0f / 32.0f);
    }
}

extern "C" void kernel_launch(void* const* d_in, const int* in_sizes, int n_in,
                              void* d_out, int out_size) {
    const float* obs  = (const float*)d_in[0];
    const float* a0   = (const float*)d_in[1];
    const float* q1W1 = (const float*)d_in[2];
    const float* q1b1 = (const float*)d_in[3];
    const float* q1W2 = (const float*)d_in[4];
    const float* q1b2 = (const float*)d_in[5];
    const float* q1W3 = (const float*)d_in[6];
    const float* q1b3 = (const float*)d_in[7];
    const float* q2W1 = (const float*)d_in[8];
    const float* q2b1 = (const float*)d_in[9];
    const float* q2W2 = (const float*)d_in[10];
    const float* q2b2 = (const float*)d_in[11];
    const float* q2W3 = (const float*)d_in[12];
    const float* q2b3 = (const float*)d_in[13];
    float* out = (float*)d_out;

    cudaFuncSetAttribute(svgd_kernel,
                         cudaFuncAttributeMaxDynamicSharedMemorySize, SM_TOTAL);

    prep_weights<<<dim3(128, 2), 256>>>(q1W2, q2W2, q1W3, q2W3, q1W1, q2W1);
    svgd_kernel<<<BB, 256, SM_TOTAL>>>(obs, a0,
                             q1W1, q1b1, q1W2, q1b2, q1W3, q1b3,
                             q2W1, q2b1, q2W2, q2b2, q2W3, q2b3,
                             out);
}

// round 13
// speedup vs baseline: 5.7022x; 1.3736x over previous
#include <cuda_runtime.h>
#include <cuda_bf16.h>
#include <math.h>

#define BB 1024
#define NN 32
#define DOBS 17
#define DACT 6
#define DIN 23
#define HH 256
#define NSTEPS 5
#define AST 6
#define HPST 130    // s_hp row stride (uint2 units); = 260 floats for dh1 alias
#define HFST 260
#define XPST 17     // s_xp row stride (uint2 units)

// bf16 split B fragment tables, packed uint4 = (b0hi, b1hi, b0lo, b1lo),
// flat idx = (ks*32 + nTg)*32 + lane;  laneq=lane>>2, lanet=lane&3.
// fwd l2: j = nTg*8+laneq, k0 = ks*16+2*lanet: b0={W2[k0][j],W2[k0+1][j]}, b1={W2[k0+8][j],W2[k0+9][j]}
// bwd l2: k = nTg*8+laneq, j0 = ks*16+2*lanet: V[j][k] = W3[j]*W2[k][j]
// l1:     j = nTg*8+laneq, k0 = ks*16+2*lanet (k<23 else 0), ks<2
__device__ uint4 g_BfU[2][16384];
__device__ uint4 g_BbU[2][16384];
__device__ uint4 g_B1U[2][2048];

__device__ __forceinline__ unsigned bf2pack(float v0, float v1) {
    unsigned r;  // lower 16 = bf16(v0), upper 16 = bf16(v1)
    asm("cvt.rn.bf16x2.f32 %0, %1, %2;" : "=r"(r) : "f"(v1), "f"(v0));
    return r;
}
__device__ __forceinline__ void bfsplit2(float v0, float v1, unsigned& hiP, unsigned& loP) {
    hiP = bf2pack(v0, v1);
    float h0 = __uint_as_float(hiP << 16);
    float h1 = __uint_as_float(hiP & 0xFFFF0000u);
    loP = bf2pack(v0 - h0, v1 - h1);
}

__global__ void prep_weights(const float* __restrict__ w2a,
                             const float* __restrict__ w2b,
                             const float* __restrict__ w3a,
                             const float* __restrict__ w3b,
                             const float* __restrict__ w1a,
                             const float* __restrict__ w1b) {
    int idx = blockIdx.x * 256 + threadIdx.x;   // 0..16383
    int net = blockIdx.y;
    const float* W2 = net ? w2b : w2a;
    const float* W3 = net ? w3b : w3a;
    int lane = idx & 31;
    int nTg  = (idx >> 5) & 31;
    int ks   = idx >> 10;           // 0..15
    int laneq = lane >> 2, lanet = lane & 3;
    // forward layer2
    {
        int j  = nTg * 8 + laneq;
        int k0 = ks * 16 + 2 * lanet;
        unsigned b0h, b0l, b1h, b1l;
        bfsplit2(W2[k0 * HH + j],       W2[(k0 + 1) * HH + j], b0h, b0l);
        bfsplit2(W2[(k0 + 8) * HH + j], W2[(k0 + 9) * HH + j], b1h, b1l);
        g_BfU[net][idx] = make_uint4(b0h, b1h, b0l, b1l);
    }
    // backward: V[j][k] = W3[j] * W2[k][j]
    {
        int k  = nTg * 8 + laneq;
        int j0 = ks * 16 + 2 * lanet;
        unsigned b0h, b0l, b1h, b1l;
        bfsplit2(W3[j0]     * W2[k * HH + j0],     W3[j0 + 1] * W2[k * HH + j0 + 1], b0h, b0l);
        bfsplit2(W3[j0 + 8] * W2[k * HH + j0 + 8], W3[j0 + 9] * W2[k * HH + j0 + 9], b1h, b1l);
        g_BbU[net][idx] = make_uint4(b0h, b1h, b0l, b1l);
    }
    // layer1 (K padded to 32)
    if (idx < 2048) {
        const float* W1 = net ? w1b : w1a;
        int j  = nTg * 8 + laneq;
        int k0 = ks * 16 + 2 * lanet;
        float v00 = (k0 < DIN)     ? W1[k0 * HH + j]       : 0.0f;
        float v01 = (k0 + 1 < DIN) ? W1[(k0 + 1) * HH + j] : 0.0f;
        float v10 = (k0 + 8 < DIN) ? W1[(k0 + 8) * HH + j] : 0.0f;
        float v11 = (k0 + 9 < DIN) ? W1[(k0 + 9) * HH + j] : 0.0f;
        unsigned b0h, b0l, b1h, b1l;
        bfsplit2(v00, v01, b0h, b0l);
        bfsplit2(v10, v11, b1h, b1l);
        g_B1U[net][idx] = make_uint4(b0h, b1h, b0l, b1l);
    }
}

__device__ __forceinline__ void mma_bf16(float& d0, float& d1, float& d2, float& d3,
                                         unsigned a0, unsigned a1, unsigned a2, unsigned a3,
                                         unsigned b0, unsigned b1) {
    asm("mma.sync.aligned.m16n8k16.row.col.f32.bf16.bf16.f32 "
        "{%0,%1,%2,%3}, {%4,%5,%6,%7}, {%8,%9}, {%0,%1,%2,%3};"
        : "+f"(d0), "+f"(d1), "+f"(d2), "+f"(d3)
        : "r"(a0), "r"(a1), "r"(a2), "r"(a3), "r"(b0), "r"(b1));
}

// dynamic smem layout (bytes)
#define SM_HP    0        // uint2[32*130] = 33280 (h hi/lo pairs | dh1 fp32 | sort)
#define SM_XP    33280    // uint2[32*17]  = 4352  (x pairs | d2 alias)
#define SM_U     37632    // m1c[2048] m2c[2048] K[4096] = 8192
#define SM_Q     45824    // float[64]
#define SM_S     46080    // float[192]
#define SM_A     46848    // float[192]
#define SM_LOGP  47616    // float[32]
#define SM_LPN   47744    // float[32]
#define SM_RED   47872    // float[256]
#define SM_ORIG  48896    // int[32]
#define SM_CNT   49024    // int
#define SM_TOTAL 49040

__global__ __launch_bounds__(256, 2) void svgd_kernel(
    const float* __restrict__ obs, const float* __restrict__ a0,
    const float* __restrict__ W1a, const float* __restrict__ B1a,
    const float* __restrict__ W2a, const float* __restrict__ B2a,
    const float* __restrict__ W3a, const float* __restrict__ B3a,
    const float* __restrict__ W1b, const float* __restrict__ B1b,
    const float* __restrict__ W2b, const float* __restrict__ B2b,
    const float* __restrict__ W3b, const float* __restrict__ B3b,
    float* __restrict__ out)
{
    extern __shared__ __align__(16) unsigned char smem[];
    uint2*  s_hp = (uint2*)(smem + SM_HP);
    float*  s_hf = (float*)(smem + SM_HP);
    uint2*  s_xp = (uint2*)(smem + SM_XP);
    unsigned char* s_u = smem + SM_U;
    float*  s_q  = (float*)(smem + SM_Q);
    float*  s_s  = (float*)(smem + SM_S);
    float*  s_a  = (float*)(smem + SM_A);
    float*  s_logp = (float*)(smem + SM_LOGP);
    float*  s_lpn  = (float*)(smem + SM_LPN);
    float*  s_red  = (float*)(smem + SM_RED);
    int*    s_orig = (int*)(smem + SM_ORIG);
    int*    s_cnt  = (int*)(smem + SM_CNT);

    unsigned char* s_m1c = s_u;                    // [net*1024 + (k>>1)*8 + (n&7)]
    unsigned char* s_m2c = s_u + 2048;             // [net*1024 + (j>>1)*8 + (n&7)]
    float* s_d2p = (float*)(smem + SM_XP);
    float* s_Kp  = (float*)(s_u + 4096);

    const int b = blockIdx.x;
    const int tid = threadIdx.x;
    const int lane = tid & 31;
    const int warp = tid >> 5;
    const int laneq = lane >> 2;
    const int lanet = lane & 3;

    for (int idx = tid; idx < NN * DACT; idx += 256) {
        int n = idx / DACT, d = idx % DACT;
        s_a[n * AST + d] = a0[(b * NN + n) * DACT + d];
    }
    if (tid < NN) s_logp[tid] = 0.0f;
    __syncthreads();
    if (tid < NN) {
        float ss = 0.0f;
        #pragma unroll
        for (int d = 0; d < DACT; d++) { float v = s_a[tid * AST + d]; ss += v * v; }
        s_lpn[tid] = -3.0f * logf(6.283185307179586f * 0.3f) - (0.5f / 0.3f) * ss;
    }

    for (int step = 0; step < NSTEPS; ++step) {
        __syncthreads();
        // build pre-split x pairs: pair p covers k = 2p, 2p+1 (obs|act|0)
        for (int idx = tid; idx < NN * 16; idx += 256) {
            int n = idx >> 4, p = idx & 15;
            int k0 = 2 * p, k1 = 2 * p + 1;
            float v0 = 0.0f, v1 = 0.0f;
            if (k0 < DOBS) v0 = obs[(b * NN + n) * DOBS + k0];
            else if (k0 < DIN) v0 = s_a[n * AST + (k0 - DOBS)];
            if (k1 < DOBS) v1 = obs[(b * NN + n) * DOBS + k1];
            else if (k1 < DIN) v1 = s_a[n * AST + (k1 - DOBS)];
            unsigned hiP, loP;
            bfsplit2(v0, v1, hiP, loP);
            s_xp[n * XPST + p] = make_uint2(hiP, loP);
        }
        __syncthreads();

        // ================= forward both Q nets (bf16 mma) =================
        for (int net = 0; net < 2; ++net) {
            const float* B1 = net ? B1b : B1a;
            const float* B2 = net ? B2b : B2a;
            const float* W3 = net ? W3b : W3a;
            const float* B3 = net ? B3b : B3a;

            // ---- layer1 mma ----
            {
                float D[2][4][4];
                #pragma unroll
                for (int mT = 0; mT < 2; mT++)
                    #pragma unroll
                    for (int t = 0; t < 4; t++)
                        #pragma unroll
                        for (int c = 0; c < 4; c++) D[mT][t][c] = 0.0f;

                const uint4* B1F = g_B1U[net];
                #pragma unroll
                for (int ks = 0; ks < 2; ks++) {
                    int base = (ks * 32 + warp * 4) * 32 + lane;
                    uint4 bv0 = B1F[base];
                    uint4 bv1 = B1F[base + 32];
                    uint4 bv2 = B1F[base + 64];
                    uint4 bv3 = B1F[base + 96];
                    #pragma unroll
                    for (int mT = 0; mT < 2; mT++) {
                        int r = mT * 16 + laneq;
                        uint2 A0 = s_xp[r * XPST + ks * 8 + lanet];
                        uint2 A1 = s_xp[(r + 8) * XPST + ks * 8 + lanet];
                        uint2 A2 = s_xp[r * XPST + ks * 8 + lanet + 4];
                        uint2 A3 = s_xp[(r + 8) * XPST + ks * 8 + lanet + 4];
                        mma_bf16(D[mT][0][0], D[mT][0][1], D[mT][0][2], D[mT][0][3],
                                 A0.x, A1.x, A2.x, A3.x, bv0.x, bv0.y);
                        mma_bf16(D[mT][0][0], D[mT][0][1], D[mT][0][2], D[mT][0][3],
                                 A0.x, A1.x, A2.x, A3.x, bv0.z, bv0.w);
                        mma_bf16(D[mT][0][0], D[mT][0][1], D[mT][0][2], D[mT][0][3],
                                 A0.y, A1.y, A2.y, A3.y, bv0.x, bv0.y);
                        mma_bf16(D[mT][1][0], D[mT][1][1], D[mT][1][2], D[mT][1][3],
                                 A0.x, A1.x, A2.x, A3.x, bv1.x, bv1.y);
                        mma_bf16(D[mT][1][0], D[mT][1][1], D[mT][1][2], D[mT][1][3],
                                 A0.x, A1.x, A2.x, A3.x, bv1.z, bv1.w);
                        mma_bf16(D[mT][1][0], D[mT][1][1], D[mT][1][2], D[mT][1][3],
                                 A0.y, A1.y, A2.y, A3.y, bv1.x, bv1.y);
                        mma_bf16(D[mT][2][0], D[mT][2][1], D[mT][2][2], D[mT][2][3],
                                 A0.x, A1.x, A2.x, A3.x, bv2.x, bv2.y);
                        mma_bf16(D[mT][2][0], D[mT][2][1], D[mT][2][2], D[mT][2][3],
                                 A0.x, A1.x, A2.x, A3.x, bv2.z, bv2.w);
                        mma_bf16(D[mT][2][0], D[mT][2][1], D[mT][2][2], D[mT][2][3],
                                 A0.y, A1.y, A2.y, A3.y, bv2.x, bv2.y);
                        mma_bf16(D[mT][3][0], D[mT][3][1], D[mT][3][2], D[mT][3][3],
                                 A0.x, A1.x, A2.x, A3.x, bv3.x, bv3.y);
                        mma_bf16(D[mT][3][0], D[mT][3][1], D[mT][3][2], D[mT][3][3],
                                 A0.x, A1.x, A2.x, A3.x, bv3.z, bv3.w);
                        mma_bf16(D[mT][3][0], D[mT][3][1], D[mT][3][2], D[mT][3][3],
                                 A0.y, A1.y, A2.y, A3.y, bv3.x, bv3.y);
                    }
                }

                // epilogue: bias, relu, write h hi/lo pairs + mask1 bytes
                #pragma unroll
                for (int t = 0; t < 4; t++) {
                    int j0 = warp * 32 + t * 8 + 2 * lanet;
                    int pidx = warp * 16 + t * 4 + lanet;
                    float b1_0 = B1[j0], b1_1 = B1[j0 + 1];
                    unsigned byte = 0;
                    #pragma unroll
                    for (int mT = 0; mT < 2; mT++) {
                        int r0 = mT * 16 + laneq, r1 = r0 + 8;
                        float z00 = D[mT][t][0] + b1_0;
                        float z01 = D[mT][t][1] + b1_1;
                        float z10 = D[mT][t][2] + b1_0;
                        float z11 = D[mT][t][3] + b1_1;
                        if (z00 > 0.0f) byte |= 1u << (4 * mT + 0); else z00 = 0.0f;
                        if (z01 > 0.0f) byte |= 1u << (4 * mT + 1); else z01 = 0.0f;
                        if (z10 > 0.0f) byte |= 1u << (4 * mT + 2); else z10 = 0.0f;
                        if (z11 > 0.0f) byte |= 1u << (4 * mT + 3); else z11 = 0.0f;
                        unsigned hiP, loP;
                        bfsplit2(z00, z01, hiP, loP);
                        s_hp[r0 * HPST + pidx] = make_uint2(hiP, loP);
                        bfsplit2(z10, z11, hiP, loP);
                        s_hp[r1 * HPST + pidx] = make_uint2(hiP, loP);
                    }
                    s_m1c[net * 1024 + pidx * 8 + laneq] = (unsigned char)byte;
                }
            }
            __syncthreads();

            // ---- layer2 mma ----
            float D[2][4][4];
            #pragma unroll
            for (int mT = 0; mT < 2; mT++)
                #pragma unroll
                for (int t = 0; t < 4; t++)
                    #pragma unroll
                    for (int c = 0; c < 4; c++) D[mT][t][c] = 0.0f;

            const uint4* BF = g_BfU[net];
            for (int ks = 0; ks < 16; ks++) {
                int base = (ks * 32 + warp * 4) * 32 + lane;
                uint4 bv0 = BF[base];
                uint4 bv1 = BF[base + 32];
                uint4 bv2 = BF[base + 64];
                uint4 bv3 = BF[base + 96];
                #pragma unroll
                for (int mT = 0; mT < 2; mT++) {
                    int r = mT * 16 + laneq;
                    uint2 A0 = s_hp[r * HPST + ks * 8 + lanet];
                    uint2 A1 = s_hp[(r + 8) * HPST + ks * 8 + lanet];
                    uint2 A2 = s_hp[r * HPST + ks * 8 + lanet + 4];
                    uint2 A3 = s_hp[(r + 8) * HPST + ks * 8 + lanet + 4];
                    mma_bf16(D[mT][0][0], D[mT][0][1], D[mT][0][2], D[mT][0][3],
                             A0.x, A1.x, A2.x, A3.x, bv0.x, bv0.y);
                    mma_bf16(D[mT][0][0], D[mT][0][1], D[mT][0][2], D[mT][0][3],
                             A0.x, A1.x, A2.x, A3.x, bv0.z, bv0.w);
                    mma_bf16(D[mT][0][0], D[mT][0][1], D[mT][0][2], D[mT][0][3],
                             A0.y, A1.y, A2.y, A3.y, bv0.x, bv0.y);
                    mma_bf16(D[mT][1][0], D[mT][1][1], D[mT][1][2], D[mT][1][3],
                             A0.x, A1.x, A2.x, A3.x, bv1.x, bv1.y);
                    mma_bf16(D[mT][1][0], D[mT][1][1], D[mT][1][2], D[mT][1][3],
                             A0.x, A1.x, A2.x, A3.x, bv1.z, bv1.w);
                    mma_bf16(D[mT][1][0], D[mT][1][1], D[mT][1][2], D[mT][1][3],
                             A0.y, A1.y, A2.y, A3.y, bv1.x, bv1.y);
                    mma_bf16(D[mT][2][0], D[mT][2][1], D[mT][2][2], D[mT][2][3],
                             A0.x, A1.x, A2.x, A3.x, bv2.x, bv2.y);
                    mma_bf16(D[mT][2][0], D[mT][2][1], D[mT][2][2], D[mT][2][3],
                             A0.x, A1.x, A2.x, A3.x, bv2.z, bv2.w);
                    mma_bf16(D[mT][2][0], D[mT][2][1], D[mT][2][2], D[mT][2][3],
                             A0.y, A1.y, A2.y, A3.y, bv2.x, bv2.y);
                    mma_bf16(D[mT][3][0], D[mT][3][1], D[mT][3][2], D[mT][3][3],
                             A0.x, A1.x, A2.x, A3.x, bv3.x, bv3.y);
                    mma_bf16(D[mT][3][0], D[mT][3][1], D[mT][3][2], D[mT][3][3],
                             A0.x, A1.x, A2.x, A3.x, bv3.z, bv3.w);
                    mma_bf16(D[mT][3][0], D[mT][3][1], D[mT][3][2], D[mT][3][3],
                             A0.y, A1.y, A2.y, A3.y, bv3.x, bv3.y);
                }
            }

            // epilogue: bias, relu, mask2 bytes, q partials
            float qr[2][2] = {{0.0f, 0.0f}, {0.0f, 0.0f}};
            #pragma unroll
            for (int t = 0; t < 4; t++) {
                int j0 = warp * 32 + t * 8 + 2 * lanet;
                float b2_0 = B2[j0], b2_1 = B2[j0 + 1];
                float w3_0 = W3[j0], w3_1 = W3[j0 + 1];
                unsigned byte = 0;
                #pragma unroll
                for (int mT = 0; mT < 2; mT++) {
                    float z00 = D[mT][t][0] + b2_0;
                    float z01 = D[mT][t][1] + b2_1;
                    float z10 = D[mT][t][2] + b2_0;
                    float z11 = D[mT][t][3] + b2_1;
                    if (z00 > 0.0f) { byte |= 1u << (4 * mT + 0); qr[mT][0] += z00 * w3_0; }
                    if (z01 > 0.0f) { byte |= 1u << (4 * mT + 1); qr[mT][0] += z01 * w3_1; }
                    if (z10 > 0.0f) { byte |= 1u << (4 * mT + 2); qr[mT][1] += z10 * w3_0; }
                    if (z11 > 0.0f) { byte |= 1u << (4 * mT + 3); qr[mT][1] += z11 * w3_1; }
                }
                s_m2c[net * 1024 + (j0 >> 1) * 8 + laneq] = (unsigned char)byte;
            }
            #pragma unroll
            for (int mT = 0; mT < 2; mT++)
                #pragma unroll
                for (int u = 0; u < 2; u++) {
                    float v = qr[mT][u];
                    v += __shfl_xor_sync(0xffffffffu, v, 1);
                    v += __shfl_xor_sync(0xffffffffu, v, 2);
                    if (lanet == 0) s_red[warp * 32 + mT * 16 + 8 * u + laneq] = v;
                }
            __syncthreads();
            if (tid < NN) {
                float q = B3[0];
                #pragma unroll
                for (int w = 0; w < 8; w++) q += s_red[w * 32 + tid];
                s_q[net * 32 + tid] = q;
            }
            __syncthreads();
        }

        // ---- gate + stable partition ----
        if (tid < NN) {
            bool g = s_q[tid] <= s_q[32 + tid];
            unsigned ball = __ballot_sync(0xffffffffu, g);
            int c1 = __popc(ball);
            int below = __popc(ball & ((1u << tid) - 1u));
            int slot = g ? below : (c1 + (tid - below));
            s_orig[slot] = tid;
            if (tid == 0) s_cnt[0] = c1;
        }
        __syncthreads();

        // ================= backward: dh1 = mask2 @ V^T (A exact in bf16) =================
        {
            const int cnt1 = s_cnt[0];
            float D[2][4][4];
            #pragma unroll
            for (int mT = 0; mT < 2; mT++)
                #pragma unroll
                for (int t = 0; t < 4; t++)
                    #pragma unroll
                    for (int c = 0; c < 4; c++) D[mT][t][c] = 0.0f;

            #pragma unroll
            for (int mT = 0; mT < 2; mT++) {
                int rr0 = mT * 16 + laneq, rr1 = rr0 + 8;
                int o0 = s_orig[rr0], o1 = s_orig[rr1];
                int bit0 = 4 * (o0 >> 4) + 2 * ((o0 >> 3) & 1);
                int bit1 = 4 * (o1 >> 4) + 2 * ((o1 >> 3) & 1);
                bool pureA = (cnt1 >= mT * 16 + 16);
                bool pureB = (cnt1 <= mT * 16);
                if (pureA || pureB) {
                    const unsigned char* mb = s_m2c + (pureA ? 0 : 1024);
                    const uint4* BB4 = pureA ? g_BbU[0] : g_BbU[1];
                    for (int ks = 0; ks < 16; ks++) {
                        int p = ks * 8 + lanet;
                        unsigned by00 = mb[p * 8 + (o0 & 7)];
                        unsigned by01 = mb[p * 8 + (o1 & 7)];
                        unsigned by10 = mb[(p + 4) * 8 + (o0 & 7)];
                        unsigned by11 = mb[(p + 4) * 8 + (o1 & 7)];
                        unsigned a0 = (((by00 >> bit0) & 1u) ? 0x3F80u : 0u)
                                    | (((by00 >> (bit0 + 1)) & 1u) ? 0x3F800000u : 0u);
                        unsigned a1 = (((by01 >> bit1) & 1u) ? 0x3F80u : 0u)
                                    | (((by01 >> (bit1 + 1)) & 1u) ? 0x3F800000u : 0u);
                        unsigned a2 = (((by10 >> bit0) & 1u) ? 0x3F80u : 0u)
                                    | (((by10 >> (bit0 + 1)) & 1u) ? 0x3F800000u : 0u);
                        unsigned a3 = (((by11 >> bit1) & 1u) ? 0x3F80u : 0u)
                                    | (((by11 >> (bit1 + 1)) & 1u) ? 0x3F800000u : 0u);
                        int base = (ks * 32 + warp * 4) * 32 + lane;
                        #pragma unroll
                        for (int t = 0; t < 4; t++) {
                            uint4 bv = BB4[base + t * 32];
                            mma_bf16(D[mT][t][0], D[mT][t][1], D[mT][t][2], D[mT][t][3],
                                     a0, a1, a2, a3, bv.x, bv.y);
                            mma_bf16(D[mT][t][0], D[mT][t][1], D[mT][t][2], D[mT][t][3],
                                     a0, a1, a2, a3, bv.z, bv.w);
                        }
                    }
                } else {
                    bool rA0 = (rr0 < cnt1), rA1 = (rr1 < cnt1);
                    for (int ks = 0; ks < 16; ks++) {
                        int p = ks * 8 + lanet;
                        const unsigned char* mk0 = s_m2c;
                        const unsigned char* mk1 = s_m2c + 1024;
                        unsigned by00A = mk0[p * 8 + (o0 & 7)], by00B = mk1[p * 8 + (o0 & 7)];
                        unsigned by01A = mk0[p * 8 + (o1 & 7)], by01B = mk1[p * 8 + (o1 & 7)];
                        unsigned by10A = mk0[(p + 4) * 8 + (o0 & 7)], by10B = mk1[(p + 4) * 8 + (o0 & 7)];
                        unsigned by11A = mk0[(p + 4) * 8 + (o1 & 7)], by11B = mk1[(p + 4) * 8 + (o1 & 7)];
                        unsigned p0 = rA0 ? ((((by00A >> bit0) & 1u) ? 0x3F80u : 0u)
                                           | (((by00A >> (bit0 + 1)) & 1u) ? 0x3F800000u : 0u)) : 0u;
                        unsigned p1 = rA1 ? ((((by01A >> bit1) & 1u) ? 0x3F80u : 0u)
                                           | (((by01A >> (bit1 + 1)) & 1u) ? 0x3F800000u : 0u)) : 0u;
                        unsigned p2 = rA0 ? ((((by10A >> bit0) & 1u) ? 0x3F80u : 0u)
                                           | (((by10A >> (bit0 + 1)) & 1u) ? 0x3F800000u : 0u)) : 0u;
                        unsigned p3 = rA1 ? ((((by11A >> bit1) & 1u) ? 0x3F80u : 0u)
                                           | (((by11A >> (bit1 + 1)) & 1u) ? 0x3F800000u : 0u)) : 0u;
                        unsigned q0 = !rA0 ? ((((by00B >> bit0) & 1u) ? 0x3F80u : 0u)
                                            | (((by00B >> (bit0 + 1)) & 1u) ? 0x3F800000u : 0u)) : 0u;
                        unsigned q1 = !rA1 ? ((((by01B >> bit1) & 1u) ? 0x3F80u : 0u)
                                            | (((by01B >> (bit1 + 1)) & 1u) ? 0x3F800000u : 0u)) : 0u;
                        unsigned q2 = !rA0 ? ((((by10B >> bit0) & 1u) ? 0x3F80u : 0u)
                                            | (((by10B >> (bit0 + 1)) & 1u) ? 0x3F800000u : 0u)) : 0u;
                        unsigned q3 = !rA1 ? ((((by11B >> bit1) & 1u) ? 0x3F80u : 0u)
                                            | (((by11B >> (bit1 + 1)) & 1u) ? 0x3F800000u : 0u)) : 0u;
                        int base = (ks * 32 + warp * 4) * 32 + lane;
                        #pragma unroll
                        for (int t = 0; t < 4; t++) {
                            uint4 bvA = g_BbU[0][base + t * 32];
                            mma_bf16(D[mT][t][0], D[mT][t][1], D[mT][t][2], D[mT][t][3],
                                     p0, p1, p2, p3, bvA.x, bvA.y);
                            mma_bf16(D[mT][t][0], D[mT][t][1], D[mT][t][2], D[mT][t][3],
                                     p0, p1, p2, p3, bvA.z, bvA.w);
                            uint4 bvB = g_BbU[1][base + t * 32];
                            mma_bf16(D[mT][t][0], D[mT][t][1], D[mT][t][2], D[mT][t][3],
                                     q0, q1, q2, q3, bvB.x, bvB.y);
                            mma_bf16(D[mT][t][0], D[mT][t][1], D[mT][t][2], D[mT][t][3],
                                     q0, q1, q2, q3, bvB.z, bvB.w);
                        }
                    }
                }
            }
            __syncthreads();  // h-pair reads (none) / region reuse barrier

            // dh1 epilogue: apply relu mask1 (byte-encoded), write fp32 rows
            #pragma unroll
            for (int mT = 0; mT < 2; mT++) {
                int r0 = mT * 16 + laneq, r1 = r0 + 8;
                int o0 = s_orig[r0], o1 = s_orig[r1];
                const unsigned char* mb0 = s_m1c + ((r0 < cnt1) ? 0 : 1024);
                const unsigned char* mb1 = s_m1c + ((r1 < cnt1) ? 0 : 1024);
                int bitb0 = 4 * (o0 >> 4) + 2 * ((o0 >> 3) & 1);
                int bitb1 = 4 * (o1 >> 4) + 2 * ((o1 >> 3) & 1);
                #pragma unroll
                for (int t = 0; t < 4; t++) {
                    int c0 = warp * 32 + t * 8 + 2 * lanet;
                    unsigned by0 = mb0[(c0 >> 1) * 8 + (o0 & 7)];
                    unsigned by1 = mb1[(c0 >> 1) * 8 + (o1 & 7)];
                    float2 v0, v1;
                    v0.x = (by0 >> (bitb0 + 0)) & 1u ? D[mT][t][0] : 0.0f;
                    v0.y = (by0 >> (bitb0 + 1)) & 1u ? D[mT][t][1] : 0.0f;
                    v1.x = (by1 >> (bitb1 + 0)) & 1u ? D[mT][t][2] : 0.0f;
                    v1.y = (by1 >> (bitb1 + 1)) & 1u ? D[mT][t][3] : 0.0f;
                    *(float2*)&s_hf[r0 * HFST + c0] = v0;
                    *(float2*)&s_hf[r1 * HFST + c0] = v1;
                }
            }
            __syncthreads();

            // da[orig][d] = sum_k dh1[slot][k] * W1_sel[17+d][k]
            if (tid < NN * DACT) {
                int sl = tid / DACT, d = tid % DACT;
                int o = s_orig[sl];
                const float* W1sel = (sl < cnt1) ? W1a : W1b;
                const float* w1r = W1sel + (DOBS + d) * HH;
                float sum = 0.0f;
                for (int k = 0; k < HH; k += 4) {
                    float4 h4 = *(const float4*)&s_hf[sl * HFST + k];
                    float4 w4 = *(const float4*)&w1r[k];
                    sum += h4.x * w4.x + h4.y * w4.y + h4.z * w4.z + h4.w * w4.w;
                }
                s_s[o * AST + d] = sum;
            }
            __syncthreads();
        }

        // ================= SVGD update =================
        for (int p = tid; p < NN * NN; p += 256) {
            int i = p >> 5, j = p & 31;
            float ds = 0.0f;
            #pragma unroll
            for (int d = 0; d < DACT; d++) {
                float df = s_a[i * AST + d] - s_a[j * AST + d];
                ds += df * df;
            }
            s_d2p[p] = ds;
            s_hf[p] = ds;
        }
        __syncthreads();

        for (int ks = 2; ks <= NN * NN; ks <<= 1) {
            for (int jj = ks >> 1; jj > 0; jj >>= 1) {
                #pragma unroll
                for (int e = 0; e < 4; e++) {
                    int idx = (e << 8) | tid;
                    int ixj = idx ^ jj;
                    if (ixj > idx) {
                        float va = s_hf[idx], vb = s_hf[ixj];
                        bool up = ((idx & ks) == 0);
                        if ((va > vb) == up) { s_hf[idx] = vb; s_hf[ixj] = va; }
                    }
                }
                __syncthreads();
            }
        }

        float med = 0.5f * (s_hf[511] + s_hf[512]);
        float hm = med / logf(33.0f);
        float gamma = 1.0f / (2.0f * hm + 1e-8f);
        for (int p = tid; p < NN * NN; p += 256)
            s_Kp[p] = expf(-gamma * s_d2p[p]);
        __syncthreads();

        float anew[DACT];
        float lpdelta = 0.0f;
        if (tid < NN) {
            int i = tid;
            float ai[DACT];
            #pragma unroll
            for (int d = 0; d < DACT; d++) ai[d] = s_a[i * AST + d];
            float ph[DACT] = {0, 0, 0, 0, 0, 0};
            float t1 = 0.0f, t2s = 0.0f;
            for (int j = 0; j < NN; j++) {
                float Kij = s_Kp[i * 32 + j];
                float dot = 0.0f;
                #pragma unroll
                for (int d = 0; d < DACT; d++) {
                    float df = ai[d] - s_a[j * AST + d];
                    float sj = s_s[j * AST + d];
                    dot += df * sj;
                    ph[d] += Kij * sj + 2.0f * gamma * Kij * df;
                }
                t1 += -2.0f * gamma * Kij * dot;
                float I = (i == j) ? 1.0f : 0.0f;
                t2s += 2.0f * gamma * Kij * s_d2p[i * 32 + j] - 6.0f * (Kij - I);
            }
            t1 *= (1.0f / 31.0f);
            float t2 = -2.0f * gamma * t2s * (1.0f / 31.0f);
            lpdelta = 0.05f * (t1 + t2);
            #pragma unroll
            for (int d = 0; d < DACT; d++)
                anew[d] = ai[d] + 0.05f * ph[d] * (1.0f / 32.0f);
        }
        __syncthreads();
        if (tid < NN) {
            s_logp[tid] -= lpdelta;
            #pragma unroll
            for (int d = 0; d < DACT; d++) s_a[tid * AST + d] = anew[d];
        }
        __syncthreads();
    }

    // ================= finalize =================
    __syncthreads();
    if (tid < NN) {
        int n = tid;
        float lpt = 0.0f;
        #pragma unroll
        for (int d = 0; d < DACT; d++) {
            float av = s_a[n * AST + d];
            float x = -2.0f * av;
            float sp = (x > 0.0f) ? (x + log1pf(expf(-x))) : log1pf(expf(x));
            lpt += -2.0f * (0.6931471805599453f - av - sp);
            out[(b * NN + n) * DACT + d] = tanhf(av);
        }
        s_red[n] = s_lpn[n] + s_logp[n] + lpt;
    }
    __syncthreads();
    if (tid == 0) {
        float m = 0.0f;
        for (int n = 0; n < NN; n++) m += s_red[n];
        out[BB * NN * DACT + b] = m * (1.0f / 32.0f);
    }
}

extern "C" void kernel_launch(void* const* d_in, const int* in_sizes, int n_in,
                              void* d_out, int out_size) {
    const float* obs  = (const float*)d_in[0];
    const float* a0   = (const float*)d_in[1];
    const float* q1W1 = (const float*)d_in[2];
    const float* q1b1 = (const float*)d_in[3];
    const float* q1W2 = (const float*)d_in[4];
    const float* q1b2 = (const float*)d_in[5];
    const float* q1W3 = (const float*)d_in[6];
    const float* q1b3 = (const float*)d_in[7];
    const float* q2W1 = (const float*)d_in[8];
    const float* q2b1 = (const float*)d_in[9];
    const float* q2W2 = (const float*)d_in[10];
    const float* q2b2 = (const float*)d_in[11];
    const float* q2W3 = (const float*)d_in[12];
    const float* q2b3 = (const float*)d_in[13];
    float* out = (float*)d_out;

    cudaFuncSetAttribute(svgd_kernel,
                         cudaFuncAttributeMaxDynamicSharedMemorySize, SM_TOTAL);

    prep_weights<<<dim3(64, 2), 256>>>(q1W2, q2W2, q1W3, q2W3, q1W1, q2W1);
    svgd_kernel<<<BB, 256, SM_TOTAL>>>(obs, a0,
                             q1W1, q1b1, q1W2, q1b2, q1W3, q1b3,
                             q2W1, q2b1, q2W2, q2b2, q2W3, q2b3,
                             out);
}

// round 14
// speedup vs baseline: 7.5669x; 1.3270x over previous
#include <cuda_runtime.h>
#include <cuda_bf16.h>
#include <math.h>

#define BB 1024
#define NN 32
#define DOBS 17
#define DACT 6
#define DIN 23
#define HH 256
#define NSTEPS 5
#define AST 6
#define HHROWW 132   // h hi/lo plane row stride (words); 528B, 16B-mult, conflict-free
#define XROWW  20    // x plane row stride (words); 80B
#define HFST   260   // dh1 fp32 row stride (aliases h planes)

// bf16 split B fragment tables, packed uint4 = (b0hi, b1hi, b0lo, b1lo),
// flat idx = (ks*32 + nTg)*32 + lane;  laneq=lane>>2, lanet=lane&3.
__device__ uint4 g_BfU[2][16384];
__device__ uint4 g_BbU[2][16384];
__device__ uint4 g_B1U[2][2048];

__device__ __forceinline__ unsigned bf2pack(float v0, float v1) {
    unsigned r;  // lower 16 = bf16(v0), upper 16 = bf16(v1)
    asm("cvt.rn.bf16x2.f32 %0, %1, %2;" : "=r"(r) : "f"(v1), "f"(v0));
    return r;
}
__device__ __forceinline__ void bfsplit2(float v0, float v1, unsigned& hiP, unsigned& loP) {
    hiP = bf2pack(v0, v1);
    float h0 = __uint_as_float(hiP << 16);
    float h1 = __uint_as_float(hiP & 0xFFFF0000u);
    loP = bf2pack(v0 - h0, v1 - h1);
}

__global__ void prep_weights(const float* __restrict__ w2a,
                             const float* __restrict__ w2b,
                             const float* __restrict__ w3a,
                             const float* __restrict__ w3b,
                             const float* __restrict__ w1a,
                             const float* __restrict__ w1b) {
    int idx = blockIdx.x * 256 + threadIdx.x;   // 0..16383
    int net = blockIdx.y;
    const float* W2 = net ? w2b : w2a;
    const float* W3 = net ? w3b : w3a;
    int lane = idx & 31;
    int nTg  = (idx >> 5) & 31;
    int ks   = idx >> 10;           // 0..15
    int laneq = lane >> 2, lanet = lane & 3;
    {
        int j  = nTg * 8 + laneq;
        int k0 = ks * 16 + 2 * lanet;
        unsigned b0h, b0l, b1h, b1l;
        bfsplit2(W2[k0 * HH + j],       W2[(k0 + 1) * HH + j], b0h, b0l);
        bfsplit2(W2[(k0 + 8) * HH + j], W2[(k0 + 9) * HH + j], b1h, b1l);
        g_BfU[net][idx] = make_uint4(b0h, b1h, b0l, b1l);
    }
    {
        int k  = nTg * 8 + laneq;
        int j0 = ks * 16 + 2 * lanet;
        unsigned b0h, b0l, b1h, b1l;
        bfsplit2(W3[j0]     * W2[k * HH + j0],     W3[j0 + 1] * W2[k * HH + j0 + 1], b0h, b0l);
        bfsplit2(W3[j0 + 8] * W2[k * HH + j0 + 8], W3[j0 + 9] * W2[k * HH + j0 + 9], b1h, b1l);
        g_BbU[net][idx] = make_uint4(b0h, b1h, b0l, b1l);
    }
    if (idx < 2048) {
        const float* W1 = net ? w1b : w1a;
        int j  = nTg * 8 + laneq;
        int k0 = ks * 16 + 2 * lanet;
        float v00 = (k0 < DIN)     ? W1[k0 * HH + j]       : 0.0f;
        float v01 = (k0 + 1 < DIN) ? W1[(k0 + 1) * HH + j] : 0.0f;
        float v10 = (k0 + 8 < DIN) ? W1[(k0 + 8) * HH + j] : 0.0f;
        float v11 = (k0 + 9 < DIN) ? W1[(k0 + 9) * HH + j] : 0.0f;
        unsigned b0h, b0l, b1h, b1l;
        bfsplit2(v00, v01, b0h, b0l);
        bfsplit2(v10, v11, b1h, b1l);
        g_B1U[net][idx] = make_uint4(b0h, b1h, b0l, b1l);
    }
}

__device__ __forceinline__ void mma_bf16(float& d0, float& d1, float& d2, float& d3,
                                         unsigned a0, unsigned a1, unsigned a2, unsigned a3,
                                         unsigned b0, unsigned b1) {
    asm("mma.sync.aligned.m16n8k16.row.col.f32.bf16.bf16.f32 "
        "{%0,%1,%2,%3}, {%4,%5,%6,%7}, {%8,%9}, {%0,%1,%2,%3};"
        : "+f"(d0), "+f"(d1), "+f"(d2), "+f"(d3)
        : "r"(a0), "r"(a1), "r"(a2), "r"(a3), "r"(b0), "r"(b1));
}

__device__ __forceinline__ void ldm_x4(unsigned& r0, unsigned& r1, unsigned& r2, unsigned& r3,
                                       unsigned addr) {
    asm volatile("ldmatrix.sync.aligned.m8n8.x4.shared.b16 {%0,%1,%2,%3}, [%4];"
        : "=r"(r0), "=r"(r1), "=r"(r2), "=r"(r3) : "r"(addr));
}

// dynamic smem layout (bytes)
#define SM_HH    0        // unsigned[32*132] = 16896 (h hi plane | dh1 fp32 | hist)
#define SM_HL    16896    // unsigned[32*132] = 16896 (h lo plane)
#define SM_XH    33792    // unsigned[32*20]  = 2560 (x hi | d2 alias)
#define SM_XL    36352    // 2560
#define SM_U     38912    // m1c[2048] m2c[2048] K[4096]
#define SM_Q     47104    // float[64]
#define SM_S     47360    // float[192]
#define SM_A     48128    // float[192]
#define SM_LOGP  48896
#define SM_LPN   49024
#define SM_RED   49152    // float[256]
#define SM_ORIG  50176
#define SM_CNT   50304
#define SM_TOTAL 50320

__global__ __launch_bounds__(256, 2) void svgd_kernel(
    const float* __restrict__ obs, const float* __restrict__ a0,
    const float* __restrict__ W1a, const float* __restrict__ B1a,
    const float* __restrict__ W2a, const float* __restrict__ B2a,
    const float* __restrict__ W3a, const float* __restrict__ B3a,
    const float* __restrict__ W1b, const float* __restrict__ B1b,
    const float* __restrict__ W2b, const float* __restrict__ B2b,
    const float* __restrict__ W3b, const float* __restrict__ B3b,
    float* __restrict__ out)
{
    extern __shared__ __align__(16) unsigned char smem[];
    unsigned* s_hh = (unsigned*)(smem + SM_HH);
    unsigned* s_hl = (unsigned*)(smem + SM_HL);
    float*    s_hf = (float*)(smem + SM_HH);     // dh1 fp32 rows, stride HFST
    unsigned* s_xh = (unsigned*)(smem + SM_XH);
    unsigned* s_xl = (unsigned*)(smem + SM_XL);
    unsigned char* s_u = smem + SM_U;
    float*  s_q  = (float*)(smem + SM_Q);
    float*  s_s  = (float*)(smem + SM_S);
    float*  s_a  = (float*)(smem + SM_A);
    float*  s_logp = (float*)(smem + SM_LOGP);
    float*  s_lpn  = (float*)(smem + SM_LPN);
    float*  s_red  = (float*)(smem + SM_RED);
    int*    s_orig = (int*)(smem + SM_ORIG);
    int*    s_cnt  = (int*)(smem + SM_CNT);

    unsigned char* s_m1c = s_u;                    // [net*1024 + (k>>1)*8 + (n&7)]
    unsigned char* s_m2c = s_u + 2048;             // [net*1024 + (j>>1)*8 + (n&7)]
    float* s_d2p = (float*)(smem + SM_XH);         // d2 aliases x planes
    float* s_Kp  = (float*)(s_u + 4096);

    const int b = blockIdx.x;
    const int tid = threadIdx.x;
    const int lane = tid & 31;
    const int warp = tid >> 5;
    const int laneq = lane >> 2;
    const int lanet = lane & 3;

    // ldmatrix per-lane base addresses (fixed for whole kernel)
    const unsigned sb = (unsigned)__cvta_generic_to_shared(smem);
    const int mat = lane >> 3, rw = lane & 7;
    unsigned hbH[2], hbL[2], xbH[2], xbL[2];
    #pragma unroll
    for (int mT = 0; mT < 2; mT++) {
        int row = mT * 16 + (mat & 1) * 8 + rw;
        unsigned off = (mat >> 1) * 16;
        hbH[mT] = sb + SM_HH + row * (HHROWW * 4) + off;
        hbL[mT] = sb + SM_HL + row * (HHROWW * 4) + off;
        xbH[mT] = sb + SM_XH + row * (XROWW * 4) + off;
        xbL[mT] = sb + SM_XL + row * (XROWW * 4) + off;
    }

    for (int idx = tid; idx < NN * DACT; idx += 256) {
        int n = idx / DACT, d = idx % DACT;
        s_a[n * AST + d] = a0[(b * NN + n) * DACT + d];
    }
    if (tid < NN) s_logp[tid] = 0.0f;
    __syncthreads();
    if (tid < NN) {
        float ss = 0.0f;
        #pragma unroll
        for (int d = 0; d < DACT; d++) { float v = s_a[tid * AST + d]; ss += v * v; }
        s_lpn[tid] = -3.0f * logf(6.283185307179586f * 0.3f) - (0.5f / 0.3f) * ss;
    }

    for (int step = 0; step < NSTEPS; ++step) {
        __syncthreads();
        // build pre-split x planes: pair p covers k = 2p, 2p+1 (obs|act|0)
        for (int idx = tid; idx < NN * 16; idx += 256) {
            int n = idx >> 4, p = idx & 15;
            int k0 = 2 * p, k1 = 2 * p + 1;
            float v0 = 0.0f, v1 = 0.0f;
            if (k0 < DOBS) v0 = obs[(b * NN + n) * DOBS + k0];
            else if (k0 < DIN) v0 = s_a[n * AST + (k0 - DOBS)];
            if (k1 < DOBS) v1 = obs[(b * NN + n) * DOBS + k1];
            else if (k1 < DIN) v1 = s_a[n * AST + (k1 - DOBS)];
            unsigned hiP, loP;
            bfsplit2(v0, v1, hiP, loP);
            s_xh[n * XROWW + p] = hiP;
            s_xl[n * XROWW + p] = loP;
        }
        __syncthreads();

        // ================= forward both Q nets (bf16 mma, ldmatrix A) =================
        for (int net = 0; net < 2; ++net) {
            const float* B1 = net ? B1b : B1a;
            const float* B2 = net ? B2b : B2a;
            const float* W3 = net ? W3b : W3a;
            const float* B3 = net ? B3b : B3a;

            // ---- layer1 mma ----
            {
                float D[2][4][4];
                #pragma unroll
                for (int mT = 0; mT < 2; mT++)
                    #pragma unroll
                    for (int t = 0; t < 4; t++)
                        #pragma unroll
                        for (int c = 0; c < 4; c++) D[mT][t][c] = 0.0f;

                const uint4* B1F = g_B1U[net];
                #pragma unroll
                for (int ks = 0; ks < 2; ks++) {
                    int base = (ks * 32 + warp * 4) * 32 + lane;
                    uint4 bv0 = B1F[base];
                    uint4 bv1 = B1F[base + 32];
                    uint4 bv2 = B1F[base + 64];
                    uint4 bv3 = B1F[base + 96];
                    #pragma unroll
                    for (int mT = 0; mT < 2; mT++) {
                        unsigned ah0, ah1, ah2, ah3, al0, al1, al2, al3;
                        ldm_x4(ah0, ah1, ah2, ah3, xbH[mT] + ks * 32);
                        ldm_x4(al0, al1, al2, al3, xbL[mT] + ks * 32);
                        mma_bf16(D[mT][0][0], D[mT][0][1], D[mT][0][2], D[mT][0][3],
                                 ah0, ah1, ah2, ah3, bv0.x, bv0.y);
                        mma_bf16(D[mT][0][0], D[mT][0][1], D[mT][0][2], D[mT][0][3],
                                 ah0, ah1, ah2, ah3, bv0.z, bv0.w);
                        mma_bf16(D[mT][0][0], D[mT][0][1], D[mT][0][2], D[mT][0][3],
                                 al0, al1, al2, al3, bv0.x, bv0.y);
                        mma_bf16(D[mT][1][0], D[mT][1][1], D[mT][1][2], D[mT][1][3],
                                 ah0, ah1, ah2, ah3, bv1.x, bv1.y);
                        mma_bf16(D[mT][1][0], D[mT][1][1], D[mT][1][2], D[mT][1][3],
                                 ah0, ah1, ah2, ah3, bv1.z, bv1.w);
                        mma_bf16(D[mT][1][0], D[mT][1][1], D[mT][1][2], D[mT][1][3],
                                 al0, al1, al2, al3, bv1.x, bv1.y);
                        mma_bf16(D[mT][2][0], D[mT][2][1], D[mT][2][2], D[mT][2][3],
                                 ah0, ah1, ah2, ah3, bv2.x, bv2.y);
                        mma_bf16(D[mT][2][0], D[mT][2][1], D[mT][2][2], D[mT][2][3],
                                 ah0, ah1, ah2, ah3, bv2.z, bv2.w);
                        mma_bf16(D[mT][2][0], D[mT][2][1], D[mT][2][2], D[mT][2][3],
                                 al0, al1, al2, al3, bv2.x, bv2.y);
                        mma_bf16(D[mT][3][0], D[mT][3][1], D[mT][3][2], D[mT][3][3],
                                 ah0, ah1, ah2, ah3, bv3.x, bv3.y);
                        mma_bf16(D[mT][3][0], D[mT][3][1], D[mT][3][2], D[mT][3][3],
                                 ah0, ah1, ah2, ah3, bv3.z, bv3.w);
                        mma_bf16(D[mT][3][0], D[mT][3][1], D[mT][3][2], D[mT][3][3],
                                 al0, al1, al2, al3, bv3.x, bv3.y);
                    }
                }

                // epilogue: bias, relu, write h planes + mask1 bytes
                #pragma unroll
                for (int t = 0; t < 4; t++) {
                    int j0 = warp * 32 + t * 8 + 2 * lanet;
                    int pidx = warp * 16 + t * 4 + lanet;
                    float b1_0 = B1[j0], b1_1 = B1[j0 + 1];
                    unsigned byte = 0;
                    #pragma unroll
                    for (int mT = 0; mT < 2; mT++) {
                        int r0 = mT * 16 + laneq, r1 = r0 + 8;
                        float z00 = D[mT][t][0] + b1_0;
                        float z01 = D[mT][t][1] + b1_1;
                        float z10 = D[mT][t][2] + b1_0;
                        float z11 = D[mT][t][3] + b1_1;
                        if (z00 > 0.0f) byte |= 1u << (4 * mT + 0); else z00 = 0.0f;
                        if (z01 > 0.0f) byte |= 1u << (4 * mT + 1); else z01 = 0.0f;
                        if (z10 > 0.0f) byte |= 1u << (4 * mT + 2); else z10 = 0.0f;
                        if (z11 > 0.0f) byte |= 1u << (4 * mT + 3); else z11 = 0.0f;
                        unsigned hiP, loP;
                        bfsplit2(z00, z01, hiP, loP);
                        s_hh[r0 * HHROWW + pidx] = hiP;
                        s_hl[r0 * HHROWW + pidx] = loP;
                        bfsplit2(z10, z11, hiP, loP);
                        s_hh[r1 * HHROWW + pidx] = hiP;
                        s_hl[r1 * HHROWW + pidx] = loP;
                    }
                    s_m1c[net * 1024 + pidx * 8 + laneq] = (unsigned char)byte;
                }
            }
            __syncthreads();

            // ---- layer2 mma ----
            float D[2][4][4];
            #pragma unroll
            for (int mT = 0; mT < 2; mT++)
                #pragma unroll
                for (int t = 0; t < 4; t++)
                    #pragma unroll
                    for (int c = 0; c < 4; c++) D[mT][t][c] = 0.0f;

            const uint4* BF = g_BfU[net];
            for (int ks = 0; ks < 16; ks++) {
                int base = (ks * 32 + warp * 4) * 32 + lane;
                uint4 bv0 = BF[base];
                uint4 bv1 = BF[base + 32];
                uint4 bv2 = BF[base + 64];
                uint4 bv3 = BF[base + 96];
                #pragma unroll
                for (int mT = 0; mT < 2; mT++) {
                    unsigned ah0, ah1, ah2, ah3, al0, al1, al2, al3;
                    ldm_x4(ah0, ah1, ah2, ah3, hbH[mT] + ks * 32);
                    ldm_x4(al0, al1, al2, al3, hbL[mT] + ks * 32);
                    mma_bf16(D[mT][0][0], D[mT][0][1], D[mT][0][2], D[mT][0][3],
                             ah0, ah1, ah2, ah3, bv0.x, bv0.y);
                    mma_bf16(D[mT][0][0], D[mT][0][1], D[mT][0][2], D[mT][0][3],
                             ah0, ah1, ah2, ah3, bv0.z, bv0.w);
                    mma_bf16(D[mT][0][0], D[mT][0][1], D[mT][0][2], D[mT][0][3],
                             al0, al1, al2, al3, bv0.x, bv0.y);
                    mma_bf16(D[mT][1][0], D[mT][1][1], D[mT][1][2], D[mT][1][3],
                             ah0, ah1, ah2, ah3, bv1.x, bv1.y);
                    mma_bf16(D[mT][1][0], D[mT][1][1], D[mT][1][2], D[mT][1][3],
                             ah0, ah1, ah2, ah3, bv1.z, bv1.w);
                    mma_bf16(D[mT][1][0], D[mT][1][1], D[mT][1][2], D[mT][1][3],
                             al0, al1, al2, al3, bv1.x, bv1.y);
                    mma_bf16(D[mT][2][0], D[mT][2][1], D[mT][2][2], D[mT][2][3],
                             ah0, ah1, ah2, ah3, bv2.x, bv2.y);
                    mma_bf16(D[mT][2][0], D[mT][2][1], D[mT][2][2], D[mT][2][3],
                             ah0, ah1, ah2, ah3, bv2.z, bv2.w);
                    mma_bf16(D[mT][2][0], D[mT][2][1], D[mT][2][2], D[mT][2][3],
                             al0, al1, al2, al3, bv2.x, bv2.y);
                    mma_bf16(D[mT][3][0], D[mT][3][1], D[mT][3][2], D[mT][3][3],
                             ah0, ah1, ah2, ah3, bv3.x, bv3.y);
                    mma_bf16(D[mT][3][0], D[mT][3][1], D[mT][3][2], D[mT][3][3],
                             ah0, ah1, ah2, ah3, bv3.z, bv3.w);
                    mma_bf16(D[mT][3][0], D[mT][3][1], D[mT][3][2], D[mT][3][3],
                             al0, al1, al2, al3, bv3.x, bv3.y);
                }
            }

            // epilogue: bias, relu, mask2 bytes, q partials
            float qr[2][2] = {{0.0f, 0.0f}, {0.0f, 0.0f}};
            #pragma unroll
            for (int t = 0; t < 4; t++) {
                int j0 = warp * 32 + t * 8 + 2 * lanet;
                float b2_0 = B2[j0], b2_1 = B2[j0 + 1];
                float w3_0 = W3[j0], w3_1 = W3[j0 + 1];
                unsigned byte = 0;
                #pragma unroll
                for (int mT = 0; mT < 2; mT++) {
                    float z00 = D[mT][t][0] + b2_0;
                    float z01 = D[mT][t][1] + b2_1;
                    float z10 = D[mT][t][2] + b2_0;
                    float z11 = D[mT][t][3] + b2_1;
                    if (z00 > 0.0f) { byte |= 1u << (4 * mT + 0); qr[mT][0] += z00 * w3_0; }
                    if (z01 > 0.0f) { byte |= 1u << (4 * mT + 1); qr[mT][0] += z01 * w3_1; }
                    if (z10 > 0.0f) { byte |= 1u << (4 * mT + 2); qr[mT][1] += z10 * w3_0; }
                    if (z11 > 0.0f) { byte |= 1u << (4 * mT + 3); qr[mT][1] += z11 * w3_1; }
                }
                s_m2c[net * 1024 + (j0 >> 1) * 8 + laneq] = (unsigned char)byte;
            }
            #pragma unroll
            for (int mT = 0; mT < 2; mT++)
                #pragma unroll
                for (int u = 0; u < 2; u++) {
                    float v = qr[mT][u];
                    v += __shfl_xor_sync(0xffffffffu, v, 1);
                    v += __shfl_xor_sync(0xffffffffu, v, 2);
                    if (lanet == 0) s_red[warp * 32 + mT * 16 + 8 * u + laneq] = v;
                }
            __syncthreads();
            if (tid < NN) {
                float q = B3[0];
                #pragma unroll
                for (int w = 0; w < 8; w++) q += s_red[w * 32 + tid];
                s_q[net * 32 + tid] = q;
            }
            __syncthreads();
        }

        // ---- gate + stable partition ----
        if (tid < NN) {
            bool g = s_q[tid] <= s_q[32 + tid];
            unsigned ball = __ballot_sync(0xffffffffu, g);
            int c1 = __popc(ball);
            int below = __popc(ball & ((1u << tid) - 1u));
            int slot = g ? below : (c1 + (tid - below));
            s_orig[slot] = tid;
            if (tid == 0) s_cnt[0] = c1;
        }
        __syncthreads();

        // ================= backward: dh1 = mask2 @ V^T (A exact in bf16) =================
        {
            const int cnt1 = s_cnt[0];
            float D[2][4][4];
            #pragma unroll
            for (int mT = 0; mT < 2; mT++)
                #pragma unroll
                for (int t = 0; t < 4; t++)
                    #pragma unroll
                    for (int c = 0; c < 4; c++) D[mT][t][c] = 0.0f;

            #pragma unroll
            for (int mT = 0; mT < 2; mT++) {
                int rr0 = mT * 16 + laneq, rr1 = rr0 + 8;
                int o0 = s_orig[rr0], o1 = s_orig[rr1];
                int bit0 = 4 * (o0 >> 4) + 2 * ((o0 >> 3) & 1);
                int bit1 = 4 * (o1 >> 4) + 2 * ((o1 >> 3) & 1);
                bool pureA = (cnt1 >= mT * 16 + 16);
                bool pureB = (cnt1 <= mT * 16);
                if (pureA || pureB) {
                    const unsigned char* mb = s_m2c + (pureA ? 0 : 1024);
                    const uint4* BB4 = pureA ? g_BbU[0] : g_BbU[1];
                    for (int ks = 0; ks < 16; ks++) {
                        int p = ks * 8 + lanet;
                        unsigned by00 = mb[p * 8 + (o0 & 7)];
                        unsigned by01 = mb[p * 8 + (o1 & 7)];
                        unsigned by10 = mb[(p + 4) * 8 + (o0 & 7)];
                        unsigned by11 = mb[(p + 4) * 8 + (o1 & 7)];
                        unsigned a0 = (((by00 >> bit0) & 1u) ? 0x3F80u : 0u)
                                    | (((by00 >> (bit0 + 1)) & 1u) ? 0x3F800000u : 0u);
                        unsigned a1 = (((by01 >> bit1) & 1u) ? 0x3F80u : 0u)
                                    | (((by01 >> (bit1 + 1)) & 1u) ? 0x3F800000u : 0u);
                        unsigned a2 = (((by10 >> bit0) & 1u) ? 0x3F80u : 0u)
                                    | (((by10 >> (bit0 + 1)) & 1u) ? 0x3F800000u : 0u);
                        unsigned a3 = (((by11 >> bit1) & 1u) ? 0x3F80u : 0u)
                                    | (((by11 >> (bit1 + 1)) & 1u) ? 0x3F800000u : 0u);
                        int base = (ks * 32 + warp * 4) * 32 + lane;
                        #pragma unroll
                        for (int t = 0; t < 4; t++) {
                            uint4 bv = BB4[base + t * 32];
                            mma_bf16(D[mT][t][0], D[mT][t][1], D[mT][t][2], D[mT][t][3],
                                     a0, a1, a2, a3, bv.x, bv.y);
                            mma_bf16(D[mT][t][0], D[mT][t][1], D[mT][t][2], D[mT][t][3],
                                     a0, a1, a2, a3, bv.z, bv.w);
                        }
                    }
                } else {
                    bool rA0 = (rr0 < cnt1), rA1 = (rr1 < cnt1);
                    for (int ks = 0; ks < 16; ks++) {
                        int p = ks * 8 + lanet;
                        const unsigned char* mk0 = s_m2c;
                        const unsigned char* mk1 = s_m2c + 1024;
                        unsigned by00A = mk0[p * 8 + (o0 & 7)], by00B = mk1[p * 8 + (o0 & 7)];
                        unsigned by01A = mk0[p * 8 + (o1 & 7)], by01B = mk1[p * 8 + (o1 & 7)];
                        unsigned by10A = mk0[(p + 4) * 8 + (o0 & 7)], by10B = mk1[(p + 4) * 8 + (o0 & 7)];
                        unsigned by11A = mk0[(p + 4) * 8 + (o1 & 7)], by11B = mk1[(p + 4) * 8 + (o1 & 7)];
                        unsigned p0 = rA0 ? ((((by00A >> bit0) & 1u) ? 0x3F80u : 0u)
                                           | (((by00A >> (bit0 + 1)) & 1u) ? 0x3F800000u : 0u)) : 0u;
                        unsigned p1 = rA1 ? ((((by01A >> bit1) & 1u) ? 0x3F80u : 0u)
                                           | (((by01A >> (bit1 + 1)) & 1u) ? 0x3F800000u : 0u)) : 0u;
                        unsigned p2 = rA0 ? ((((by10A >> bit0) & 1u) ? 0x3F80u : 0u)
                                           | (((by10A >> (bit0 + 1)) & 1u) ? 0x3F800000u : 0u)) : 0u;
                        unsigned p3 = rA1 ? ((((by11A >> bit1) & 1u) ? 0x3F80u : 0u)
                                           | (((by11A >> (bit1 + 1)) & 1u) ? 0x3F800000u : 0u)) : 0u;
                        unsigned q0 = !rA0 ? ((((by00B >> bit0) & 1u) ? 0x3F80u : 0u)
                                            | (((by00B >> (bit0 + 1)) & 1u) ? 0x3F800000u : 0u)) : 0u;
                        unsigned q1 = !rA1 ? ((((by01B >> bit1) & 1u) ? 0x3F80u : 0u)
                                            | (((by01B >> (bit1 + 1)) & 1u) ? 0x3F800000u : 0u)) : 0u;
                        unsigned q2 = !rA0 ? ((((by10B >> bit0) & 1u) ? 0x3F80u : 0u)
                                            | (((by10B >> (bit0 + 1)) & 1u) ? 0x3F800000u : 0u)) : 0u;
                        unsigned q3 = !rA1 ? ((((by11B >> bit1) & 1u) ? 0x3F80u : 0u)
                                            | (((by11B >> (bit1 + 1)) & 1u) ? 0x3F800000u : 0u)) : 0u;
                        int base = (ks * 32 + warp * 4) * 32 + lane;
                        #pragma unroll
                        for (int t = 0; t < 4; t++) {
                            uint4 bvA = g_BbU[0][base + t * 32];
                            mma_bf16(D[mT][t][0], D[mT][t][1], D[mT][t][2], D[mT][t][3],
                                     p0, p1, p2, p3, bvA.x, bvA.y);
                            mma_bf16(D[mT][t][0], D[mT][t][1], D[mT][t][2], D[mT][t][3],
                                     p0, p1, p2, p3, bvA.z, bvA.w);
                            uint4 bvB = g_BbU[1][base + t * 32];
                            mma_bf16(D[mT][t][0], D[mT][t][1], D[mT][t][2], D[mT][t][3],
                                     q0, q1, q2, q3, bvB.x, bvB.y);
                            mma_bf16(D[mT][t][0], D[mT][t][1], D[mT][t][2], D[mT][t][3],
                                     q0, q1, q2, q3, bvB.z, bvB.w);
                        }
                    }
                }
            }
            __syncthreads();   // h planes dead; region becomes dh1

            // dh1 epilogue: apply relu mask1 (byte-encoded), write fp32 rows
            const int cnt1e = cnt1;
            #pragma unroll
            for (int mT = 0; mT < 2; mT++) {
                int r0 = mT * 16 + laneq, r1 = r0 + 8;
                int o0 = s_orig[r0], o1 = s_orig[r1];
                const unsigned char* mb0 = s_m1c + ((r0 < cnt1e) ? 0 : 1024);
                const unsigned char* mb1 = s_m1c + ((r1 < cnt1e) ? 0 : 1024);
                int bitb0 = 4 * (o0 >> 4) + 2 * ((o0 >> 3) & 1);
                int bitb1 = 4 * (o1 >> 4) + 2 * ((o1 >> 3) & 1);
                #pragma unroll
                for (int t = 0; t < 4; t++) {
                    int c0 = warp * 32 + t * 8 + 2 * lanet;
                    unsigned by0 = mb0[(c0 >> 1) * 8 + (o0 & 7)];
                    unsigned by1 = mb1[(c0 >> 1) * 8 + (o1 & 7)];
                    float2 v0, v1;
                    v0.x = (by0 >> (bitb0 + 0)) & 1u ? D[mT][t][0] : 0.0f;
                    v0.y = (by0 >> (bitb0 + 1)) & 1u ? D[mT][t][1] : 0.0f;
                    v1.x = (by1 >> (bitb1 + 0)) & 1u ? D[mT][t][2] : 0.0f;
                    v1.y = (by1 >> (bitb1 + 1)) & 1u ? D[mT][t][3] : 0.0f;
                    *(float2*)&s_hf[r0 * HFST + c0] = v0;
                    *(float2*)&s_hf[r1 * HFST + c0] = v1;
                }
            }
            __syncthreads();

            // da[orig][d] = sum_k dh1[slot][k] * W1_sel[17+d][k]
            if (tid < NN * DACT) {
                int sl = tid / DACT, d = tid % DACT;
                int o = s_orig[sl];
                const float* W1sel = (sl < cnt1) ? W1a : W1b;
                const float* w1r = W1sel + (DOBS + d) * HH;
                float sum = 0.0f;
                for (int k = 0; k < HH; k += 4) {
                    float4 h4 = *(const float4*)&s_hf[sl * HFST + k];
                    float4 w4 = *(const float4*)&w1r[k];
                    sum += h4.x * w4.x + h4.y * w4.y + h4.z * w4.z + h4.w * w4.w;
                }
                s_s[o * AST + d] = sum;
            }
            __syncthreads();
        }

        // ================= SVGD update =================
        // d2 (kept in registers for median select)
        unsigned v[4];
        #pragma unroll
        for (int e = 0; e < 4; e++) {
            int p = (e << 8) | tid;
            int i = p >> 5, j = p & 31;
            float ds = 0.0f;
            #pragma unroll
            for (int d = 0; d < DACT; d++) {
                float df = s_a[i * AST + d] - s_a[j * AST + d];
                ds += df * df;
            }
            s_d2p[p] = ds;
            v[e] = __float_as_uint(ds);
        }
        __syncthreads();

        // exact median via 4-pass radix select (sorted[511], then sorted[512])
        unsigned* hist = (unsigned*)s_hf;
        unsigned* ws   = hist + 256;
        unsigned* bc   = hist + 280;
        unsigned prefix = 0, need = 511;
        #pragma unroll
        for (int pass = 0; pass < 4; pass++) {
            int dsh = 24 - pass * 8;
            unsigned maskHigh = (pass == 0) ? 0u : (0xFFFFFFFFu << (dsh + 8));
            hist[tid] = 0;
            __syncthreads();
            #pragma unroll
            for (int e = 0; e < 4; e++)
                if ((v[e] & maskHigh) == prefix)
                    atomicAdd(&hist[(v[e] >> dsh) & 255u], 1u);
            __syncthreads();
            unsigned h = hist[tid], x = h;
            #pragma unroll
            for (int off = 1; off < 32; off <<= 1) {
                unsigned y = __shfl_up_sync(0xffffffffu, x, off);
                if (lane >= off) x += y;
            }
            if (lane == 31) ws[warp] = x;
            __syncthreads();
            if (warp == 0) {
                unsigned sv = (lane < 8) ? ws[lane] : 0u;
                #pragma unroll
                for (int off = 1; off < 8; off <<= 1) {
                    unsigned y = __shfl_up_sync(0xffffffffu, sv, off);
                    if (lane >= off) sv += y;
                }
                if (lane < 8) ws[lane] = sv;
            }
            __syncthreads();
            unsigned cumIncl = x + (warp ? ws[warp - 1] : 0u);
            unsigned cumExcl = cumIncl - h;
            if (need >= cumExcl && need < cumIncl) { bc[0] = (unsigned)tid; bc[1] = cumExcl; }
            __syncthreads();
            prefix |= bc[0] << dsh;
            need   -= bc[1];
            __syncthreads();
        }
        // sorted[512]: = prefix if #{<=prefix} >= 513 else min{v > prefix}
        {
            unsigned cLe = 0, mA = 0xFFFFFFFFu;
            #pragma unroll
            for (int e = 0; e < 4; e++) {
                if (v[e] <= prefix) cLe++;
                else mA = min(mA, v[e]);
            }
            #pragma unroll
            for (int off = 16; off; off >>= 1) {
                cLe += __shfl_xor_sync(0xffffffffu, cLe, off);
                mA = min(mA, __shfl_xor_sync(0xffffffffu, mA, off));
            }
            if (lane == 0) { ws[warp] = cLe; ws[warp + 8] = mA; }
            __syncthreads();
            if (tid == 0) {
                unsigned c = 0, m = 0xFFFFFFFFu;
                #pragma unroll
                for (int w = 0; w < 8; w++) { c += ws[w]; m = min(m, ws[w + 8]); }
                bc[2] = (c >= 513u) ? prefix : m;
            }
            __syncthreads();
        }
        float med = 0.5f * (__uint_as_float(prefix) + __uint_as_float(bc[2]));
        float hm = med / logf(33.0f);
        float gamma = 1.0f / (2.0f * hm + 1e-8f);
        __syncthreads();
        for (int p = tid; p < NN * NN; p += 256)
            s_Kp[p] = expf(-gamma * s_d2p[p]);
        __syncthreads();

        float anew[DACT];
        float lpdelta = 0.0f;
        if (tid < NN) {
            int i = tid;
            float ai[DACT];
            #pragma unroll
            for (int d = 0; d < DACT; d++) ai[d] = s_a[i * AST + d];
            float ph[DACT] = {0, 0, 0, 0, 0, 0};
            float t1 = 0.0f, t2s = 0.0f;
            for (int j = 0; j < NN; j++) {
                float Kij = s_Kp[i * 32 + j];
                float dot = 0.0f;
                #pragma unroll
                for (int d = 0; d < DACT; d++) {
                    float df = ai[d] - s_a[j * AST + d];
                    float sj = s_s[j * AST + d];
                    dot += df * sj;
                    ph[d] += Kij * sj + 2.0f * gamma * Kij * df;
                }
                t1 += -2.0f * gamma * Kij * dot;
                float I = (i == j) ? 1.0f : 0.0f;
                t2s += 2.0f * gamma * Kij * s_d2p[i * 32 + j] - 6.0f * (Kij - I);
            }
            t1 *= (1.0f / 31.0f);
            float t2 = -2.0f * gamma * t2s * (1.0f / 31.0f);
            lpdelta = 0.05f * (t1 + t2);
            #pragma unroll
            for (int d = 0; d < DACT; d++)
                anew[d] = ai[d] + 0.05f * ph[d] * (1.0f / 32.0f);
        }
        __syncthreads();
        if (tid < NN) {
            s_logp[tid] -= lpdelta;
            #pragma unroll
            for (int d = 0; d < DACT; d++) s_a[tid * AST + d] = anew[d];
        }
        __syncthreads();
    }

    // ================= finalize =================
    __syncthreads();
    if (tid < NN) {
        int n = tid;
        float lpt = 0.0f;
        #pragma unroll
        for (int d = 0; d < DACT; d++) {
            float av = s_a[n * AST + d];
            float x = -2.0f * av;
            float sp = (x > 0.0f) ? (x + log1pf(expf(-x))) : log1pf(expf(x));
            lpt += -2.0f * (0.6931471805599453f - av - sp);
            out[(b * NN + n) * DACT + d] = tanhf(av);
        }
        s_red[n] = s_lpn[n] + s_logp[n] + lpt;
    }
    __syncthreads();
    if (tid == 0) {
        float m = 0.0f;
        for (int n = 0; n < NN; n++) m += s_red[n];
        out[BB * NN * DACT + b] = m * (1.0f / 32.0f);
    }
}

extern "C" void kernel_launch(void* const* d_in, const int* in_sizes, int n_in,
                              void* d_out, int out_size) {
    const float* obs  = (const float*)d_in[0];
    const float* a0   = (const float*)d_in[1];
    const float* q1W1 = (const float*)d_in[2];
    const float* q1b1 = (const float*)d_in[3];
    const float* q1W2 = (const float*)d_in[4];
    const float* q1b2 = (const float*)d_in[5];
    const float* q1W3 = (const float*)d_in[6];
    const float* q1b3 = (const float*)d_in[7];
    const float* q2W1 = (const float*)d_in[8];
    const float* q2b1 = (const float*)d_in[9];
    const float* q2W2 = (const float*)d_in[10];
    const float* q2b2 = (const float*)d_in[11];
    const float* q2W3 = (const float*)d_in[12];
    const float* q2b3 = (const float*)d_in[13];
    float* out = (float*)d_out;

    cudaFuncSetAttribute(svgd_kernel,
                         cudaFuncAttributeMaxDynamicSharedMemorySize, SM_TOTAL);

    prep_weights<<<dim3(64, 2), 256>>>(q1W2, q2W2, q1W3, q2W3, q1W1, q2W1);
    svgd_kernel<<<BB, 256, SM_TOTAL>>>(obs, a0,
                             q1W1, q1b1, q1W2, q1b2, q1W3, q1b3,
                             q2W1, q2b1, q2W2, q2b2, q2W3, q2b3,
                             out);
}

// round 15
// speedup vs baseline: 7.8412x; 1.0362x over previous
#include <cuda_runtime.h>
#include <cuda_bf16.h>
#include <math.h>

#define BB 1024
#define NN 32
#define DOBS 17
#define DACT 6
#define DIN 23
#define HH 256
#define NSTEPS 5
#define AST 6
#define HHROWW 132   // plane row stride (words); 528B, conflict-free
#define XROWW  20
#define HFST   260   // dh1 fp32 row stride (aliases h planes)

// bf16 split B fragment tables, packed uint4 = (b0hi, b1hi, b0lo, b1lo),
// flat idx = (ks*32 + nTg)*32 + lane;  laneq=lane>>2, lanet=lane&3.
__device__ uint4 g_BfU[2][16384];
__device__ uint4 g_BbU[2][16384];
__device__ uint4 g_B1U[2][2048];

__device__ __forceinline__ unsigned bf2pack(float v0, float v1) {
    unsigned r;  // lower 16 = bf16(v0), upper 16 = bf16(v1)
    asm("cvt.rn.bf16x2.f32 %0, %1, %2;" : "=r"(r) : "f"(v1), "f"(v0));
    return r;
}
__device__ __forceinline__ void bfsplit2(float v0, float v1, unsigned& hiP, unsigned& loP) {
    hiP = bf2pack(v0, v1);
    float h0 = __uint_as_float(hiP << 16);
    float h1 = __uint_as_float(hiP & 0xFFFF0000u);
    loP = bf2pack(v0 - h0, v1 - h1);
}

__global__ void prep_weights(const float* __restrict__ w2a,
                             const float* __restrict__ w2b,
                             const float* __restrict__ w3a,
                             const float* __restrict__ w3b,
                             const float* __restrict__ w1a,
                             const float* __restrict__ w1b) {
    int idx = blockIdx.x * 256 + threadIdx.x;   // 0..16383
    int net = blockIdx.y;
    const float* W2 = net ? w2b : w2a;
    const float* W3 = net ? w3b : w3a;
    int lane = idx & 31;
    int nTg  = (idx >> 5) & 31;
    int ks   = idx >> 10;           // 0..15
    int laneq = lane >> 2, lanet = lane & 3;
    {
        int j  = nTg * 8 + laneq;
        int k0 = ks * 16 + 2 * lanet;
        unsigned b0h, b0l, b1h, b1l;
        bfsplit2(W2[k0 * HH + j],       W2[(k0 + 1) * HH + j], b0h, b0l);
        bfsplit2(W2[(k0 + 8) * HH + j], W2[(k0 + 9) * HH + j], b1h, b1l);
        g_BfU[net][idx] = make_uint4(b0h, b1h, b0l, b1l);
    }
    {
        int k  = nTg * 8 + laneq;
        int j0 = ks * 16 + 2 * lanet;
        unsigned b0h, b0l, b1h, b1l;
        bfsplit2(W3[j0]     * W2[k * HH + j0],     W3[j0 + 1] * W2[k * HH + j0 + 1], b0h, b0l);
        bfsplit2(W3[j0 + 8] * W2[k * HH + j0 + 8], W3[j0 + 9] * W2[k * HH + j0 + 9], b1h, b1l);
        g_BbU[net][idx] = make_uint4(b0h, b1h, b0l, b1l);
    }
    if (idx < 2048) {
        const float* W1 = net ? w1b : w1a;
        int j  = nTg * 8 + laneq;
        int k0 = ks * 16 + 2 * lanet;
        float v00 = (k0 < DIN)     ? W1[k0 * HH + j]       : 0.0f;
        float v01 = (k0 + 1 < DIN) ? W1[(k0 + 1) * HH + j] : 0.0f;
        float v10 = (k0 + 8 < DIN) ? W1[(k0 + 8) * HH + j] : 0.0f;
        float v11 = (k0 + 9 < DIN) ? W1[(k0 + 9) * HH + j] : 0.0f;
        unsigned b0h, b0l, b1h, b1l;
        bfsplit2(v00, v01, b0h, b0l);
        bfsplit2(v10, v11, b1h, b1l);
        g_B1U[net][idx] = make_uint4(b0h, b1h, b0l, b1l);
    }
}

__device__ __forceinline__ void mma_bf16(float& d0, float& d1, float& d2, float& d3,
                                         unsigned a0, unsigned a1, unsigned a2, unsigned a3,
                                         unsigned b0, unsigned b1) {
    asm("mma.sync.aligned.m16n8k16.row.col.f32.bf16.bf16.f32 "
        "{%0,%1,%2,%3}, {%4,%5,%6,%7}, {%8,%9}, {%0,%1,%2,%3};"
        : "+f"(d0), "+f"(d1), "+f"(d2), "+f"(d3)
        : "r"(a0), "r"(a1), "r"(a2), "r"(a3), "r"(b0), "r"(b1));
}

__device__ __forceinline__ void ldm_x4(unsigned& r0, unsigned& r1, unsigned& r2, unsigned& r3,
                                       unsigned addr) {
    asm volatile("ldmatrix.sync.aligned.m8n8.x4.shared.b16 {%0,%1,%2,%3}, [%4];"
        : "=r"(r0), "=r"(r1), "=r"(r2), "=r"(r3) : "r"(addr));
}

// dynamic smem layout (bytes)
#define SM_HH    0        // 16896 (h hi plane | dh1 fp32 | radix hist)
#define SM_HL    16896    // 16896 (h lo plane)
#define SM_M2A   33792    // 16896 (mask2 plane net0: bf16 {1,0})
#define SM_M2B   50688    // 16896 (mask2 plane net1)
#define SM_ZROW  67584    // 576 zero row (ldmatrix filler)
#define SM_XH    68160    // 2560 (x hi | d2 alias)
#define SM_XL    70720    // 2560
#define SM_U     73280    // m1c[2048] + K[4096]
#define SM_Q     79424    // float[64]
#define SM_S     79680    // float[192]
#define SM_A     80448    // float[192]
#define SM_LOGP  81216
#define SM_LPN   81344
#define SM_RED   81472    // float[256]
#define SM_ORIG  82496
#define SM_CNT   82624
#define SM_TOTAL 82640

__global__ __launch_bounds__(256, 2) void svgd_kernel(
    const float* __restrict__ obs, const float* __restrict__ a0,
    const float* __restrict__ W1a, const float* __restrict__ B1a,
    const float* __restrict__ W2a, const float* __restrict__ B2a,
    const float* __restrict__ W3a, const float* __restrict__ B3a,
    const float* __restrict__ W1b, const float* __restrict__ B1b,
    const float* __restrict__ W2b, const float* __restrict__ B2b,
    const float* __restrict__ W3b, const float* __restrict__ B3b,
    float* __restrict__ out)
{
    extern __shared__ __align__(16) unsigned char smem[];
    unsigned* s_hh = (unsigned*)(smem + SM_HH);
    unsigned* s_hl = (unsigned*)(smem + SM_HL);
    float*    s_hf = (float*)(smem + SM_HH);     // dh1 fp32 rows, stride HFST
    unsigned* s_m2pA = (unsigned*)(smem + SM_M2A);
    unsigned* s_m2pB = (unsigned*)(smem + SM_M2B);
    unsigned* s_xh = (unsigned*)(smem + SM_XH);
    unsigned* s_xl = (unsigned*)(smem + SM_XL);
    unsigned char* s_u = smem + SM_U;
    float*  s_q  = (float*)(smem + SM_Q);
    float*  s_s  = (float*)(smem + SM_S);
    float*  s_a  = (float*)(smem + SM_A);
    float*  s_logp = (float*)(smem + SM_LOGP);
    float*  s_lpn  = (float*)(smem + SM_LPN);
    float*  s_red  = (float*)(smem + SM_RED);
    int*    s_orig = (int*)(smem + SM_ORIG);
    int*    s_cnt  = (int*)(smem + SM_CNT);

    unsigned char* s_m1c = s_u;                    // [net*1024 + (k>>1)*8 + (n&7)]
    float* s_d2p = (float*)(smem + SM_XH);         // d2 aliases x planes
    float* s_Kp  = (float*)(s_u + 2048);

    const int b = blockIdx.x;
    const int tid = threadIdx.x;
    const int lane = tid & 31;
    const int warp = tid >> 5;
    const int laneq = lane >> 2;
    const int lanet = lane & 3;

    // ldmatrix per-lane base addresses
    const unsigned sb = (unsigned)__cvta_generic_to_shared(smem);
    const int mat = lane >> 3, rw = lane & 7;
    unsigned hbH[2], hbL[2], xbH[2], xbL[2];
    #pragma unroll
    for (int mT = 0; mT < 2; mT++) {
        int row = mT * 16 + (mat & 1) * 8 + rw;
        unsigned off = (mat >> 1) * 16;
        hbH[mT] = sb + SM_HH + row * (HHROWW * 4) + off;
        hbL[mT] = sb + SM_HL + row * (HHROWW * 4) + off;
        xbH[mT] = sb + SM_XH + row * (XROWW * 4) + off;
        xbL[mT] = sb + SM_XL + row * (XROWW * 4) + off;
    }

    for (int idx = tid; idx < NN * DACT; idx += 256) {
        int n = idx / DACT, d = idx % DACT;
        s_a[n * AST + d] = a0[(b * NN + n) * DACT + d];
    }
    for (int i = tid; i < 144; i += 256) ((unsigned*)(smem + SM_ZROW))[i] = 0u;
    if (tid < NN) s_logp[tid] = 0.0f;
    __syncthreads();
    if (tid < NN) {
        float ss = 0.0f;
        #pragma unroll
        for (int d = 0; d < DACT; d++) { float v = s_a[tid * AST + d]; ss += v * v; }
        s_lpn[tid] = -3.0f * logf(6.283185307179586f * 0.3f) - (0.5f / 0.3f) * ss;
    }

    for (int step = 0; step < NSTEPS; ++step) {
        __syncthreads();
        // build pre-split x planes
        for (int idx = tid; idx < NN * 16; idx += 256) {
            int n = idx >> 4, p = idx & 15;
            int k0 = 2 * p, k1 = 2 * p + 1;
            float v0 = 0.0f, v1 = 0.0f;
            if (k0 < DOBS) v0 = obs[(b * NN + n) * DOBS + k0];
            else if (k0 < DIN) v0 = s_a[n * AST + (k0 - DOBS)];
            if (k1 < DOBS) v1 = obs[(b * NN + n) * DOBS + k1];
            else if (k1 < DIN) v1 = s_a[n * AST + (k1 - DOBS)];
            unsigned hiP, loP;
            bfsplit2(v0, v1, hiP, loP);
            s_xh[n * XROWW + p] = hiP;
            s_xl[n * XROWW + p] = loP;
        }
        __syncthreads();

        // ================= forward both Q nets =================
        for (int net = 0; net < 2; ++net) {
            const float* B1 = net ? B1b : B1a;
            const float* B2 = net ? B2b : B2a;
            const float* W3 = net ? W3b : W3a;
            const float* B3 = net ? B3b : B3a;
            unsigned* m2plane = net ? s_m2pB : s_m2pA;

            // ---- layer1 mma ----
            {
                float D[2][4][4];
                #pragma unroll
                for (int mT = 0; mT < 2; mT++)
                    #pragma unroll
                    for (int t = 0; t < 4; t++)
                        #pragma unroll
                        for (int c = 0; c < 4; c++) D[mT][t][c] = 0.0f;

                const uint4* B1F = g_B1U[net];
                #pragma unroll
                for (int ks = 0; ks < 2; ks++) {
                    int base = (ks * 32 + warp * 4) * 32 + lane;
                    uint4 bv0 = B1F[base];
                    uint4 bv1 = B1F[base + 32];
                    uint4 bv2 = B1F[base + 64];
                    uint4 bv3 = B1F[base + 96];
                    #pragma unroll
                    for (int mT = 0; mT < 2; mT++) {
                        unsigned ah0, ah1, ah2, ah3, al0, al1, al2, al3;
                        ldm_x4(ah0, ah1, ah2, ah3, xbH[mT] + ks * 32);
                        ldm_x4(al0, al1, al2, al3, xbL[mT] + ks * 32);
                        mma_bf16(D[mT][0][0], D[mT][0][1], D[mT][0][2], D[mT][0][3],
                                 ah0, ah1, ah2, ah3, bv0.x, bv0.y);
                        mma_bf16(D[mT][0][0], D[mT][0][1], D[mT][0][2], D[mT][0][3],
                                 ah0, ah1, ah2, ah3, bv0.z, bv0.w);
                        mma_bf16(D[mT][0][0], D[mT][0][1], D[mT][0][2], D[mT][0][3],
                                 al0, al1, al2, al3, bv0.x, bv0.y);
                        mma_bf16(D[mT][1][0], D[mT][1][1], D[mT][1][2], D[mT][1][3],
                                 ah0, ah1, ah2, ah3, bv1.x, bv1.y);
                        mma_bf16(D[mT][1][0], D[mT][1][1], D[mT][1][2], D[mT][1][3],
                                 ah0, ah1, ah2, ah3, bv1.z, bv1.w);
                        mma_bf16(D[mT][1][0], D[mT][1][1], D[mT][1][2], D[mT][1][3],
                                 al0, al1, al2, al3, bv1.x, bv1.y);
                        mma_bf16(D[mT][2][0], D[mT][2][1], D[mT][2][2], D[mT][2][3],
                                 ah0, ah1, ah2, ah3, bv2.x, bv2.y);
                        mma_bf16(D[mT][2][0], D[mT][2][1], D[mT][2][2], D[mT][2][3],
                                 ah0, ah1, ah2, ah3, bv2.z, bv2.w);
                        mma_bf16(D[mT][2][0], D[mT][2][1], D[mT][2][2], D[mT][2][3],
                                 al0, al1, al2, al3, bv2.x, bv2.y);
                        mma_bf16(D[mT][3][0], D[mT][3][1], D[mT][3][2], D[mT][3][3],
                                 ah0, ah1, ah2, ah3, bv3.x, bv3.y);
                        mma_bf16(D[mT][3][0], D[mT][3][1], D[mT][3][2], D[mT][3][3],
                                 ah0, ah1, ah2, ah3, bv3.z, bv3.w);
                        mma_bf16(D[mT][3][0], D[mT][3][1], D[mT][3][2], D[mT][3][3],
                                 al0, al1, al2, al3, bv3.x, bv3.y);
                    }
                }

                // epilogue: bias, relu, write h planes + mask1 bytes
                #pragma unroll
                for (int t = 0; t < 4; t++) {
                    int j0 = warp * 32 + t * 8 + 2 * lanet;
                    int pidx = warp * 16 + t * 4 + lanet;
                    float b1_0 = B1[j0], b1_1 = B1[j0 + 1];
                    unsigned byte = 0;
                    #pragma unroll
                    for (int mT = 0; mT < 2; mT++) {
                        int r0 = mT * 16 + laneq, r1 = r0 + 8;
                        float z00 = D[mT][t][0] + b1_0;
                        float z01 = D[mT][t][1] + b1_1;
                        float z10 = D[mT][t][2] + b1_0;
                        float z11 = D[mT][t][3] + b1_1;
                        if (z00 > 0.0f) byte |= 1u << (4 * mT + 0); else z00 = 0.0f;
                        if (z01 > 0.0f) byte |= 1u << (4 * mT + 1); else z01 = 0.0f;
                        if (z10 > 0.0f) byte |= 1u << (4 * mT + 2); else z10 = 0.0f;
                        if (z11 > 0.0f) byte |= 1u << (4 * mT + 3); else z11 = 0.0f;
                        unsigned hiP, loP;
                        bfsplit2(z00, z01, hiP, loP);
                        s_hh[r0 * HHROWW + pidx] = hiP;
                        s_hl[r0 * HHROWW + pidx] = loP;
                        bfsplit2(z10, z11, hiP, loP);
                        s_hh[r1 * HHROWW + pidx] = hiP;
                        s_hl[r1 * HHROWW + pidx] = loP;
                    }
                    s_m1c[net * 1024 + pidx * 8 + laneq] = (unsigned char)byte;
                }
            }
            __syncthreads();

            // ---- layer2 mma ----
            float D[2][4][4];
            #pragma unroll
            for (int mT = 0; mT < 2; mT++)
                #pragma unroll
                for (int t = 0; t < 4; t++)
                    #pragma unroll
                    for (int c = 0; c < 4; c++) D[mT][t][c] = 0.0f;

            const uint4* BF = g_BfU[net];
            for (int ks = 0; ks < 16; ks++) {
                int base = (ks * 32 + warp * 4) * 32 + lane;
                uint4 bv0 = BF[base];
                uint4 bv1 = BF[base + 32];
                uint4 bv2 = BF[base + 64];
                uint4 bv3 = BF[base + 96];
                #pragma unroll
                for (int mT = 0; mT < 2; mT++) {
                    unsigned ah0, ah1, ah2, ah3, al0, al1, al2, al3;
                    ldm_x4(ah0, ah1, ah2, ah3, hbH[mT] + ks * 32);
                    ldm_x4(al0, al1, al2, al3, hbL[mT] + ks * 32);
                    mma_bf16(D[mT][0][0], D[mT][0][1], D[mT][0][2], D[mT][0][3],
                             ah0, ah1, ah2, ah3, bv0.x, bv0.y);
                    mma_bf16(D[mT][0][0], D[mT][0][1], D[mT][0][2], D[mT][0][3],
                             ah0, ah1, ah2, ah3, bv0.z, bv0.w);
                    mma_bf16(D[mT][0][0], D[mT][0][1], D[mT][0][2], D[mT][0][3],
                             al0, al1, al2, al3, bv0.x, bv0.y);
                    mma_bf16(D[mT][1][0], D[mT][1][1], D[mT][1][2], D[mT][1][3],
                             ah0, ah1, ah2, ah3, bv1.x, bv1.y);
                    mma_bf16(D[mT][1][0], D[mT][1][1], D[mT][1][2], D[mT][1][3],
                             ah0, ah1, ah2, ah3, bv1.z, bv1.w);
                    mma_bf16(D[mT][1][0], D[mT][1][1], D[mT][1][2], D[mT][1][3],
                             al0, al1, al2, al3, bv1.x, bv1.y);
                    mma_bf16(D[mT][2][0], D[mT][2][1], D[mT][2][2], D[mT][2][3],
                             ah0, ah1, ah2, ah3, bv2.x, bv2.y);
                    mma_bf16(D[mT][2][0], D[mT][2][1], D[mT][2][2], D[mT][2][3],
                             ah0, ah1, ah2, ah3, bv2.z, bv2.w);
                    mma_bf16(D[mT][2][0], D[mT][2][1], D[mT][2][2], D[mT][2][3],
                             al0, al1, al2, al3, bv2.x, bv2.y);
                    mma_bf16(D[mT][3][0], D[mT][3][1], D[mT][3][2], D[mT][3][3],
                             ah0, ah1, ah2, ah3, bv3.x, bv3.y);
                    mma_bf16(D[mT][3][0], D[mT][3][1], D[mT][3][2], D[mT][3][3],
                             ah0, ah1, ah2, ah3, bv3.z, bv3.w);
                    mma_bf16(D[mT][3][0], D[mT][3][1], D[mT][3][2], D[mT][3][3],
                             al0, al1, al2, al3, bv3.x, bv3.y);
                }
            }

            // epilogue: bias, relu, mask2 bf16 plane, q partials
            float qr[2][2] = {{0.0f, 0.0f}, {0.0f, 0.0f}};
            #pragma unroll
            for (int t = 0; t < 4; t++) {
                int j0 = warp * 32 + t * 8 + 2 * lanet;
                int pidx = warp * 16 + t * 4 + lanet;
                float b2_0 = B2[j0], b2_1 = B2[j0 + 1];
                float w3_0 = W3[j0], w3_1 = W3[j0 + 1];
                #pragma unroll
                for (int mT = 0; mT < 2; mT++) {
                    int r0 = mT * 16 + laneq, r1 = r0 + 8;
                    float z00 = D[mT][t][0] + b2_0;
                    float z01 = D[mT][t][1] + b2_1;
                    float z10 = D[mT][t][2] + b2_0;
                    float z11 = D[mT][t][3] + b2_1;
                    unsigned w0 = 0, w1 = 0;
                    if (z00 > 0.0f) { w0 |= 0x3F80u;     qr[mT][0] += z00 * w3_0; }
                    if (z01 > 0.0f) { w0 |= 0x3F800000u; qr[mT][0] += z01 * w3_1; }
                    if (z10 > 0.0f) { w1 |= 0x3F80u;     qr[mT][1] += z10 * w3_0; }
                    if (z11 > 0.0f) { w1 |= 0x3F800000u; qr[mT][1] += z11 * w3_1; }
                    m2plane[r0 * HHROWW + pidx] = w0;
                    m2plane[r1 * HHROWW + pidx] = w1;
                }
            }
            #pragma unroll
            for (int mT = 0; mT < 2; mT++)
                #pragma unroll
                for (int u = 0; u < 2; u++) {
                    float v = qr[mT][u];
                    v += __shfl_xor_sync(0xffffffffu, v, 1);
                    v += __shfl_xor_sync(0xffffffffu, v, 2);
                    if (lanet == 0) s_red[warp * 32 + mT * 16 + 8 * u + laneq] = v;
                }
            __syncthreads();
            if (tid < NN) {
                float q = B3[0];
                #pragma unroll
                for (int w = 0; w < 8; w++) q += s_red[w * 32 + tid];
                s_q[net * 32 + tid] = q;
            }
            __syncthreads();
        }

        // ---- gate + stable partition ----
        if (tid < NN) {
            bool g = s_q[tid] <= s_q[32 + tid];
            unsigned ball = __ballot_sync(0xffffffffu, g);
            int c1 = __popc(ball);
            int below = __popc(ball & ((1u << tid) - 1u));
            int slot = g ? below : (c1 + (tid - below));
            s_orig[slot] = tid;
            if (tid == 0) s_cnt[0] = c1;
        }
        __syncthreads();

        // ================= backward: dh1 = mask2 @ V^T (plane A via ldmatrix) =================
        {
            const int cnt1 = s_cnt[0];
            // per-lane permuted A addresses (net-select + gate permutation folded in)
            unsigned adA[2], adB[2];
            bool hasA[2], hasB[2];
            #pragma unroll
            for (int mT = 0; mT < 2; mT++) {
                int r = mT * 16 + (mat & 1) * 8 + rw;
                int o = s_orig[r];
                bool isA = r < cnt1;
                unsigned off = (mat >> 1) * 16;
                unsigned real = sb + (isA ? SM_M2A : SM_M2B) + o * (HHROWW * 4) + off;
                unsigned zadr = sb + SM_ZROW + off;
                adA[mT] = isA ? real : zadr;
                adB[mT] = isA ? zadr : real;
                hasA[mT] = (cnt1 > mT * 16);
                hasB[mT] = (cnt1 < mT * 16 + 16);
            }

            float D[2][4][4];
            #pragma unroll
            for (int mT = 0; mT < 2; mT++)
                #pragma unroll
                for (int t = 0; t < 4; t++)
                    #pragma unroll
                    for (int c = 0; c < 4; c++) D[mT][t][c] = 0.0f;

            #pragma unroll
            for (int mT = 0; mT < 2; mT++) {
                if (hasA[mT]) {
                    for (int ks = 0; ks < 16; ks++) {
                        unsigned a0, a1, a2, a3;
                        ldm_x4(a0, a1, a2, a3, adA[mT] + ks * 32);
                        int base = (ks * 32 + warp * 4) * 32 + lane;
                        #pragma unroll
                        for (int t = 0; t < 4; t++) {
                            uint4 bv = g_BbU[0][base + t * 32];
                            mma_bf16(D[mT][t][0], D[mT][t][1], D[mT][t][2], D[mT][t][3],
                                     a0, a1, a2, a3, bv.x, bv.y);
                            mma_bf16(D[mT][t][0], D[mT][t][1], D[mT][t][2], D[mT][t][3],
                                     a0, a1, a2, a3, bv.z, bv.w);
                        }
                    }
                }
                if (hasB[mT]) {
                    for (int ks = 0; ks < 16; ks++) {
                        unsigned a0, a1, a2, a3;
                        ldm_x4(a0, a1, a2, a3, adB[mT] + ks * 32);
                        int base = (ks * 32 + warp * 4) * 32 + lane;
                        #pragma unroll
                        for (int t = 0; t < 4; t++) {
                            uint4 bv = g_BbU[1][base + t * 32];
                            mma_bf16(D[mT][t][0], D[mT][t][1], D[mT][t][2], D[mT][t][3],
                                     a0, a1, a2, a3, bv.x, bv.y);
                            mma_bf16(D[mT][t][0], D[mT][t][1], D[mT][t][2], D[mT][t][3],
                                     a0, a1, a2, a3, bv.z, bv.w);
                        }
                    }
                }
            }

            // dh1 epilogue: apply relu mask1 (byte-encoded), write fp32 rows
            #pragma unroll
            for (int mT = 0; mT < 2; mT++) {
                int r0 = mT * 16 + laneq, r1 = r0 + 8;
                int o0 = s_orig[r0], o1 = s_orig[r1];
                const unsigned char* mb0 = s_m1c + ((r0 < cnt1) ? 0 : 1024);
                const unsigned char* mb1 = s_m1c + ((r1 < cnt1) ? 0 : 1024);
                int bitb0 = 4 * (o0 >> 4) + 2 * ((o0 >> 3) & 1);
                int bitb1 = 4 * (o1 >> 4) + 2 * ((o1 >> 3) & 1);
                #pragma unroll
                for (int t = 0; t < 4; t++) {
                    int c0 = warp * 32 + t * 8 + 2 * lanet;
                    unsigned by0 = mb0[(c0 >> 1) * 8 + (o0 & 7)];
                    unsigned by1 = mb1[(c0 >> 1) * 8 + (o1 & 7)];
                    float2 v0, v1;
                    v0.x = (by0 >> (bitb0 + 0)) & 1u ? D[mT][t][0] : 0.0f;
                    v0.y = (by0 >> (bitb0 + 1)) & 1u ? D[mT][t][1] : 0.0f;
                    v1.x = (by1 >> (bitb1 + 0)) & 1u ? D[mT][t][2] : 0.0f;
                    v1.y = (by1 >> (bitb1 + 1)) & 1u ? D[mT][t][3] : 0.0f;
                    *(float2*)&s_hf[r0 * HFST + c0] = v0;
                    *(float2*)&s_hf[r1 * HFST + c0] = v1;
                }
            }
            __syncthreads();

            // da[orig][d] = sum_k dh1[slot][k] * W1_sel[17+d][k]
            if (tid < NN * DACT) {
                int sl = tid / DACT, d = tid % DACT;
                int o = s_orig[sl];
                const float* W1sel = (sl < cnt1) ? W1a : W1b;
                const float* w1r = W1sel + (DOBS + d) * HH;
                float sum = 0.0f;
                for (int k = 0; k < HH; k += 4) {
                    float4 h4 = *(const float4*)&s_hf[sl * HFST + k];
                    float4 w4 = *(const float4*)&w1r[k];
                    sum += h4.x * w4.x + h4.y * w4.y + h4.z * w4.z + h4.w * w4.w;
                }
                s_s[o * AST + d] = sum;
            }
            __syncthreads();
        }

        // ================= SVGD update =================
        unsigned v[4];
        #pragma unroll
        for (int e = 0; e < 4; e++) {
            int p = (e << 8) | tid;
            int i = p >> 5, j = p & 31;
            float ds = 0.0f;
            #pragma unroll
            for (int d = 0; d < DACT; d++) {
                float df = s_a[i * AST + d] - s_a[j * AST + d];
                ds += df * df;
            }
            s_d2p[p] = ds;
            v[e] = __float_as_uint(ds);
        }
        __syncthreads();

        // exact median via 4-pass radix select (sorted[511], then sorted[512])
        unsigned* hist = (unsigned*)s_hf;
        unsigned* ws   = hist + 256;
        unsigned* bc   = hist + 280;
        unsigned prefix = 0, need = 511;
        #pragma unroll
        for (int pass = 0; pass < 4; pass++) {
            int dsh = 24 - pass * 8;
            unsigned maskHigh = (pass == 0) ? 0u : (0xFFFFFFFFu << (dsh + 8));
            hist[tid] = 0;
            __syncthreads();
            #pragma unroll
            for (int e = 0; e < 4; e++)
                if ((v[e] & maskHigh) == prefix)
                    atomicAdd(&hist[(v[e] >> dsh) & 255u], 1u);
            __syncthreads();
            unsigned h = hist[tid], x = h;
            #pragma unroll
            for (int off = 1; off < 32; off <<= 1) {
                unsigned y = __shfl_up_sync(0xffffffffu, x, off);
                if (lane >= off) x += y;
            }
            if (lane == 31) ws[warp] = x;
            __syncthreads();
            if (warp == 0) {
                unsigned sv = (lane < 8) ? ws[lane] : 0u;
                #pragma unroll
                for (int off = 1; off < 8; off <<= 1) {
                    unsigned y = __shfl_up_sync(0xffffffffu, sv, off);
                    if (lane >= off) sv += y;
                }
                if (lane < 8) ws[lane] = sv;
            }
            __syncthreads();
            unsigned cumIncl = x + (warp ? ws[warp - 1] : 0u);
            unsigned cumExcl = cumIncl - h;
            if (need >= cumExcl && need < cumIncl) { bc[0] = (unsigned)tid; bc[1] = cumExcl; }
            __syncthreads();
            prefix |= bc[0] << dsh;
            need   -= bc[1];
            __syncthreads();
        }
        {
            unsigned cLe = 0, mA = 0xFFFFFFFFu;
            #pragma unroll
            for (int e = 0; e < 4; e++) {
                if (v[e] <= prefix) cLe++;
                else mA = min(mA, v[e]);
            }
            #pragma unroll
            for (int off = 16; off; off >>= 1) {
                cLe += __shfl_xor_sync(0xffffffffu, cLe, off);
                mA = min(mA, __shfl_xor_sync(0xffffffffu, mA, off));
            }
            if (lane == 0) { ws[warp] = cLe; ws[warp + 8] = mA; }
            __syncthreads();
            if (tid == 0) {
                unsigned c = 0, m = 0xFFFFFFFFu;
                #pragma unroll
                for (int w = 0; w < 8; w++) { c += ws[w]; m = min(m, ws[w + 8]); }
                bc[2] = (c >= 513u) ? prefix : m;
            }
            __syncthreads();
        }
        float med = 0.5f * (__uint_as_float(prefix) + __uint_as_float(bc[2]));
        float hm = med / logf(33.0f);
        float gamma = 1.0f / (2.0f * hm + 1e-8f);
        __syncthreads();
        for (int p = tid; p < NN * NN; p += 256)
            s_Kp[p] = expf(-gamma * s_d2p[p]);
        __syncthreads();

        float anew[DACT];
        float lpdelta = 0.0f;
        if (tid < NN) {
            int i = tid;
            float ai[DACT];
            #pragma unroll
            for (int d = 0; d < DACT; d++) ai[d] = s_a[i * AST + d];
            float ph[DACT] = {0, 0, 0, 0, 0, 0};
            float t1 = 0.0f, t2s = 0.0f;
            for (int j = 0; j < NN; j++) {
                float Kij = s_Kp[i * 32 + j];
                float dot = 0.0f;
                #pragma unroll
                for (int d = 0; d < DACT; d++) {
                    float df = ai[d] - s_a[j * AST + d];
                    float sj = s_s[j * AST + d];
                    dot += df * sj;
                    ph[d] += Kij * sj + 2.0f * gamma * Kij * df;
                }
                t1 += -2.0f * gamma * Kij * dot;
                float I = (i == j) ? 1.0f : 0.0f;
                t2s += 2.0f * gamma * Kij * s_d2p[i * 32 + j] - 6.0f * (Kij - I);
            }
            t1 *= (1.0f / 31.0f);
            float t2 = -2.0f * gamma * t2s * (1.0f / 31.0f);
            lpdelta = 0.05f * (t1 + t2);
            #pragma unroll
            for (int d = 0; d < DACT; d++)
                anew[d] = ai[d] + 0.05f * ph[d] * (1.0f / 32.0f);
        }
        __syncthreads();
        if (tid < NN) {
            s_logp[tid] -= lpdelta;
            #pragma unroll
            for (int d = 0; d < DACT; d++) s_a[tid * AST + d] = anew[d];
        }
        __syncthreads();
    }

    // ================= finalize =================
    __syncthreads();
    if (tid < NN) {
        int n = tid;
        float lpt = 0.0f;
        #pragma unroll
        for (int d = 0; d < DACT; d++) {
            float av = s_a[n * AST + d];
            float x = -2.0f * av;
            float sp = (x > 0.0f) ? (x + log1pf(expf(-x))) : log1pf(expf(x));
            lpt += -2.0f * (0.6931471805599453f - av - sp);
            out[(b * NN + n) * DACT + d] = tanhf(av);
        }
        s_red[n] = s_lpn[n] + s_logp[n] + lpt;
    }
    __syncthreads();
    if (tid == 0) {
        float m = 0.0f;
        for (int n = 0; n < NN; n++) m += s_red[n];
        out[BB * NN * DACT + b] = m * (1.0f / 32.0f);
    }
}

extern "C" void kernel_launch(void* const* d_in, const int* in_sizes, int n_in,
                              void* d_out, int out_size) {
    const float* obs  = (const float*)d_in[0];
    const float* a0   = (const float*)d_in[1];
    const float* q1W1 = (const float*)d_in[2];
    const float* q1b1 = (const float*)d_in[3];
    const float* q1W2 = (const float*)d_in[4];
    const float* q1b2 = (const float*)d_in[5];
    const float* q1W3 = (const float*)d_in[6];
    const float* q1b3 = (const float*)d_in[7];
    const float* q2W1 = (const float*)d_in[8];
    const float* q2b1 = (const float*)d_in[9];
    const float* q2W2 = (const float*)d_in[10];
    const float* q2b2 = (const float*)d_in[11];
    const float* q2W3 = (const float*)d_in[12];
    const float* q2b3 = (const float*)d_in[13];
    float* out = (float*)d_out;

    cudaFuncSetAttribute(svgd_kernel,
                         cudaFuncAttributeMaxDynamicSharedMemorySize, SM_TOTAL);

    prep_weights<<<dim3(64, 2), 256>>>(q1W2, q2W2, q1W3, q2W3, q1W1, q2W1);
    svgd_kernel<<<BB, 256, SM_TOTAL>>>(obs, a0,
                             q1W1, q1b1, q1W2, q1b2, q1W3, q1b3,
                             q2W1, q2b1, q2W2, q2b2, q2W3, q2b3,
                             out);
}

// round 16
// speedup vs baseline: 9.9839x; 1.2733x over previous
#include <cuda_runtime.h>
#include <cuda_bf16.h>
#include <math.h>

#define BB 1024
#define NN 32
#define DOBS 17
#define DACT 6
#define DIN 23
#define HH 256
#define NSTEPS 5
#define AST 6
#define HHROWW 132   // plane row stride (words); 528B, conflict-free
#define XROWW  20

// bf16 split B fragment tables, packed uint4 = (b0hi, b1hi, b0lo, b1lo),
// flat idx = (ks*32 + nTg)*32 + lane;  laneq=lane>>2, lanet=lane&3.
__device__ uint4 g_BfU[2][16384];
__device__ uint4 g_BbU[2][16384];
__device__ uint4 g_B1U[2][2048];
__device__ uint4 g_BdU[2][512];    // da GEMM: B = W1_act^T (n=8 pad, k=256)

__device__ __forceinline__ unsigned bf2pack(float v0, float v1) {
    unsigned r;  // lower 16 = bf16(v0), upper 16 = bf16(v1)
    asm("cvt.rn.bf16x2.f32 %0, %1, %2;" : "=r"(r) : "f"(v1), "f"(v0));
    return r;
}
__device__ __forceinline__ void bfsplit2(float v0, float v1, unsigned& hiP, unsigned& loP) {
    hiP = bf2pack(v0, v1);
    float h0 = __uint_as_float(hiP << 16);
    float h1 = __uint_as_float(hiP & 0xFFFF0000u);
    loP = bf2pack(v0 - h0, v1 - h1);
}

__global__ void prep_weights(const float* __restrict__ w2a,
                             const float* __restrict__ w2b,
                             const float* __restrict__ w3a,
                             const float* __restrict__ w3b,
                             const float* __restrict__ w1a,
                             const float* __restrict__ w1b) {
    int idx = blockIdx.x * 256 + threadIdx.x;   // 0..16383
    int net = blockIdx.y;
    const float* W2 = net ? w2b : w2a;
    const float* W3 = net ? w3b : w3a;
    const float* W1 = net ? w1b : w1a;
    int lane = idx & 31;
    int nTg  = (idx >> 5) & 31;
    int ks   = idx >> 10;           // 0..15
    int laneq = lane >> 2, lanet = lane & 3;
    {
        int j  = nTg * 8 + laneq;
        int k0 = ks * 16 + 2 * lanet;
        unsigned b0h, b0l, b1h, b1l;
        bfsplit2(W2[k0 * HH + j],       W2[(k0 + 1) * HH + j], b0h, b0l);
        bfsplit2(W2[(k0 + 8) * HH + j], W2[(k0 + 9) * HH + j], b1h, b1l);
        g_BfU[net][idx] = make_uint4(b0h, b1h, b0l, b1l);
    }
    {
        int k  = nTg * 8 + laneq;
        int j0 = ks * 16 + 2 * lanet;
        unsigned b0h, b0l, b1h, b1l;
        bfsplit2(W3[j0]     * W2[k * HH + j0],     W3[j0 + 1] * W2[k * HH + j0 + 1], b0h, b0l);
        bfsplit2(W3[j0 + 8] * W2[k * HH + j0 + 8], W3[j0 + 9] * W2[k * HH + j0 + 9], b1h, b1l);
        g_BbU[net][idx] = make_uint4(b0h, b1h, b0l, b1l);
    }
    if (idx < 2048) {
        int j  = nTg * 8 + laneq;
        int k0 = ks * 16 + 2 * lanet;
        float v00 = (k0 < DIN)     ? W1[k0 * HH + j]       : 0.0f;
        float v01 = (k0 + 1 < DIN) ? W1[(k0 + 1) * HH + j] : 0.0f;
        float v10 = (k0 + 8 < DIN) ? W1[(k0 + 8) * HH + j] : 0.0f;
        float v11 = (k0 + 9 < DIN) ? W1[(k0 + 9) * HH + j] : 0.0f;
        unsigned b0h, b0l, b1h, b1l;
        bfsplit2(v00, v01, b0h, b0l);
        bfsplit2(v10, v11, b1h, b1l);
        g_B1U[net][idx] = make_uint4(b0h, b1h, b0l, b1l);
    }
    // da table: B[k][n] = W1_act[n][k] = W1[(DOBS+n)*HH + k], n=laneq (pad>=6 -> 0)
    if (idx < 512) {
        int ks2 = idx >> 5;                     // 0..15
        int n = laneq;
        int k0 = ks2 * 16 + 2 * lanet;
        float v00 = (n < DACT) ? W1[(DOBS + n) * HH + k0]     : 0.0f;
        float v01 = (n < DACT) ? W1[(DOBS + n) * HH + k0 + 1] : 0.0f;
        float v10 = (n < DACT) ? W1[(DOBS + n) * HH + k0 + 8] : 0.0f;
        float v11 = (n < DACT) ? W1[(DOBS + n) * HH + k0 + 9] : 0.0f;
        unsigned b0h, b0l, b1h, b1l;
        bfsplit2(v00, v01, b0h, b0l);
        bfsplit2(v10, v11, b1h, b1l);
        g_BdU[net][idx] = make_uint4(b0h, b1h, b0l, b1l);
    }
}

__device__ __forceinline__ void mma_bf16(float& d0, float& d1, float& d2, float& d3,
                                         unsigned a0, unsigned a1, unsigned a2, unsigned a3,
                                         unsigned b0, unsigned b1) {
    asm("mma.sync.aligned.m16n8k16.row.col.f32.bf16.bf16.f32 "
        "{%0,%1,%2,%3}, {%4,%5,%6,%7}, {%8,%9}, {%0,%1,%2,%3};"
        : "+f"(d0), "+f"(d1), "+f"(d2), "+f"(d3)
        : "r"(a0), "r"(a1), "r"(a2), "r"(a3), "r"(b0), "r"(b1));
}

__device__ __forceinline__ void ldm_x4(unsigned& r0, unsigned& r1, unsigned& r2, unsigned& r3,
                                       unsigned addr) {
    asm volatile("ldmatrix.sync.aligned.m8n8.x4.shared.b16 {%0,%1,%2,%3}, [%4];"
        : "=r"(r0), "=r"(r1), "=r"(r2), "=r"(r3) : "r"(addr));
}

// dynamic smem layout (bytes)
#define SM_HH    0        // 16896 (h hi plane | dh1 hi plane | radix hist)
#define SM_HL    16896    // 16896 (h lo plane | dh1 lo plane)
#define SM_M2A   33792    // 16896 (mask2 plane net0 | da partials 8KB)
#define SM_M2B   50688    // 16896 (mask2 plane net1)
#define SM_ZROW  67584    // 576 zero row (ldmatrix filler)
#define SM_XH    68160    // 2560 (x hi | d2 alias)
#define SM_XL    70720    // 2560
#define SM_U     73280    // m1c[2048] + K[4096]
#define SM_Q     79424    // float[64]
#define SM_S     79680    // float[192]
#define SM_A     80448    // float[192]
#define SM_LOGP  81216
#define SM_LPN   81344
#define SM_RED   81472    // float[256]
#define SM_ORIG  82496
#define SM_CNT   82624
#define SM_TOTAL 82640

__global__ __launch_bounds__(256, 2) void svgd_kernel(
    const float* __restrict__ obs, const float* __restrict__ a0,
    const float* __restrict__ W1a, const float* __restrict__ B1a,
    const float* __restrict__ W2a, const float* __restrict__ B2a,
    const float* __restrict__ W3a, const float* __restrict__ B3a,
    const float* __restrict__ W1b, const float* __restrict__ B1b,
    const float* __restrict__ W2b, const float* __restrict__ B2b,
    const float* __restrict__ W3b, const float* __restrict__ B3b,
    float* __restrict__ out)
{
    extern __shared__ __align__(16) unsigned char smem[];
    unsigned* s_hh = (unsigned*)(smem + SM_HH);
    unsigned* s_hl = (unsigned*)(smem + SM_HL);
    float*    s_hf = (float*)(smem + SM_HH);     // radix hist alias
    unsigned* s_m2pA = (unsigned*)(smem + SM_M2A);
    unsigned* s_m2pB = (unsigned*)(smem + SM_M2B);
    float*    s_part = (float*)(smem + SM_M2A);  // da partials (after masks dead)
    unsigned* s_xh = (unsigned*)(smem + SM_XH);
    unsigned* s_xl = (unsigned*)(smem + SM_XL);
    unsigned char* s_u = smem + SM_U;
    float*  s_q  = (float*)(smem + SM_Q);
    float*  s_s  = (float*)(smem + SM_S);
    float*  s_a  = (float*)(smem + SM_A);
    float*  s_logp = (float*)(smem + SM_LOGP);
    float*  s_lpn  = (float*)(smem + SM_LPN);
    float*  s_red  = (float*)(smem + SM_RED);
    int*    s_orig = (int*)(smem + SM_ORIG);
    int*    s_cnt  = (int*)(smem + SM_CNT);

    unsigned char* s_m1c = s_u;                    // [net*1024 + (k>>1)*8 + (n&7)]
    float* s_d2p = (float*)(smem + SM_XH);         // d2 aliases x planes
    float* s_Kp  = (float*)(s_u + 2048);

    const int b = blockIdx.x;
    const int tid = threadIdx.x;
    const int lane = tid & 31;
    const int warp = tid >> 5;
    const int laneq = lane >> 2;
    const int lanet = lane & 3;

    // ldmatrix per-lane base addresses
    const unsigned sb = (unsigned)__cvta_generic_to_shared(smem);
    const int mat = lane >> 3, rw = lane & 7;
    unsigned hbH[2], hbL[2], xbH[2], xbL[2];
    #pragma unroll
    for (int mT = 0; mT < 2; mT++) {
        int row = mT * 16 + (mat & 1) * 8 + rw;
        unsigned off = (mat >> 1) * 16;
        hbH[mT] = sb + SM_HH + row * (HHROWW * 4) + off;
        hbL[mT] = sb + SM_HL + row * (HHROWW * 4) + off;
        xbH[mT] = sb + SM_XH + row * (XROWW * 4) + off;
        xbL[mT] = sb + SM_XL + row * (XROWW * 4) + off;
    }

    for (int idx = tid; idx < NN * DACT; idx += 256) {
        int n = idx / DACT, d = idx % DACT;
        s_a[n * AST + d] = a0[(b * NN + n) * DACT + d];
    }
    for (int i = tid; i < 144; i += 256) ((unsigned*)(smem + SM_ZROW))[i] = 0u;
    if (tid < NN) s_logp[tid] = 0.0f;
    __syncthreads();
    if (tid < NN) {
        float ss = 0.0f;
        #pragma unroll
        for (int d = 0; d < DACT; d++) { float v = s_a[tid * AST + d]; ss += v * v; }
        s_lpn[tid] = -3.0f * logf(6.283185307179586f * 0.3f) - (0.5f / 0.3f) * ss;
    }

    for (int step = 0; step < NSTEPS; ++step) {
        __syncthreads();
        // build pre-split x planes
        for (int idx = tid; idx < NN * 16; idx += 256) {
            int n = idx >> 4, p = idx & 15;
            int k0 = 2 * p, k1 = 2 * p + 1;
            float v0 = 0.0f, v1 = 0.0f;
            if (k0 < DOBS) v0 = obs[(b * NN + n) * DOBS + k0];
            else if (k0 < DIN) v0 = s_a[n * AST + (k0 - DOBS)];
            if (k1 < DOBS) v1 = obs[(b * NN + n) * DOBS + k1];
            else if (k1 < DIN) v1 = s_a[n * AST + (k1 - DOBS)];
            unsigned hiP, loP;
            bfsplit2(v0, v1, hiP, loP);
            s_xh[n * XROWW + p] = hiP;
            s_xl[n * XROWW + p] = loP;
        }
        __syncthreads();

        // ================= forward both Q nets =================
        for (int net = 0; net < 2; ++net) {
            const float* B1 = net ? B1b : B1a;
            const float* B2 = net ? B2b : B2a;
            const float* W3 = net ? W3b : W3a;
            const float* B3 = net ? B3b : B3a;
            unsigned* m2plane = net ? s_m2pB : s_m2pA;

            // ---- layer1 mma ----
            {
                float D[2][4][4];
                #pragma unroll
                for (int mT = 0; mT < 2; mT++)
                    #pragma unroll
                    for (int t = 0; t < 4; t++)
                        #pragma unroll
                        for (int c = 0; c < 4; c++) D[mT][t][c] = 0.0f;

                const uint4* B1F = g_B1U[net];
                #pragma unroll
                for (int ks = 0; ks < 2; ks++) {
                    int base = (ks * 32 + warp * 4) * 32 + lane;
                    uint4 bv0 = B1F[base];
                    uint4 bv1 = B1F[base + 32];
                    uint4 bv2 = B1F[base + 64];
                    uint4 bv3 = B1F[base + 96];
                    #pragma unroll
                    for (int mT = 0; mT < 2; mT++) {
                        unsigned ah0, ah1, ah2, ah3, al0, al1, al2, al3;
                        ldm_x4(ah0, ah1, ah2, ah3, xbH[mT] + ks * 32);
                        ldm_x4(al0, al1, al2, al3, xbL[mT] + ks * 32);
                        mma_bf16(D[mT][0][0], D[mT][0][1], D[mT][0][2], D[mT][0][3],
                                 ah0, ah1, ah2, ah3, bv0.x, bv0.y);
                        mma_bf16(D[mT][0][0], D[mT][0][1], D[mT][0][2], D[mT][0][3],
                                 ah0, ah1, ah2, ah3, bv0.z, bv0.w);
                        mma_bf16(D[mT][0][0], D[mT][0][1], D[mT][0][2], D[mT][0][3],
                                 al0, al1, al2, al3, bv0.x, bv0.y);
                        mma_bf16(D[mT][1][0], D[mT][1][1], D[mT][1][2], D[mT][1][3],
                                 ah0, ah1, ah2, ah3, bv1.x, bv1.y);
                        mma_bf16(D[mT][1][0], D[mT][1][1], D[mT][1][2], D[mT][1][3],
                                 ah0, ah1, ah2, ah3, bv1.z, bv1.w);
                        mma_bf16(D[mT][1][0], D[mT][1][1], D[mT][1][2], D[mT][1][3],
                                 al0, al1, al2, al3, bv1.x, bv1.y);
                        mma_bf16(D[mT][2][0], D[mT][2][1], D[mT][2][2], D[mT][2][3],
                                 ah0, ah1, ah2, ah3, bv2.x, bv2.y);
                        mma_bf16(D[mT][2][0], D[mT][2][1], D[mT][2][2], D[mT][2][3],
                                 ah0, ah1, ah2, ah3, bv2.z, bv2.w);
                        mma_bf16(D[mT][2][0], D[mT][2][1], D[mT][2][2], D[mT][2][3],
                                 al0, al1, al2, al3, bv2.x, bv2.y);
                        mma_bf16(D[mT][3][0], D[mT][3][1], D[mT][3][2], D[mT][3][3],
                                 ah0, ah1, ah2, ah3, bv3.x, bv3.y);
                        mma_bf16(D[mT][3][0], D[mT][3][1], D[mT][3][2], D[mT][3][3],
                                 ah0, ah1, ah2, ah3, bv3.z, bv3.w);
                        mma_bf16(D[mT][3][0], D[mT][3][1], D[mT][3][2], D[mT][3][3],
                                 al0, al1, al2, al3, bv3.x, bv3.y);
                    }
                }

                // epilogue: bias, relu, write h planes + mask1 bytes
                #pragma unroll
                for (int t = 0; t < 4; t++) {
                    int j0 = warp * 32 + t * 8 + 2 * lanet;
                    int pidx = warp * 16 + t * 4 + lanet;
                    float b1_0 = B1[j0], b1_1 = B1[j0 + 1];
                    unsigned byte = 0;
                    #pragma unroll
                    for (int mT = 0; mT < 2; mT++) {
                        int r0 = mT * 16 + laneq, r1 = r0 + 8;
                        float z00 = D[mT][t][0] + b1_0;
                        float z01 = D[mT][t][1] + b1_1;
                        float z10 = D[mT][t][2] + b1_0;
                        float z11 = D[mT][t][3] + b1_1;
                        if (z00 > 0.0f) byte |= 1u << (4 * mT + 0); else z00 = 0.0f;
                        if (z01 > 0.0f) byte |= 1u << (4 * mT + 1); else z01 = 0.0f;
                        if (z10 > 0.0f) byte |= 1u << (4 * mT + 2); else z10 = 0.0f;
                        if (z11 > 0.0f) byte |= 1u << (4 * mT + 3); else z11 = 0.0f;
                        unsigned hiP, loP;
                        bfsplit2(z00, z01, hiP, loP);
                        s_hh[r0 * HHROWW + pidx] = hiP;
                        s_hl[r0 * HHROWW + pidx] = loP;
                        bfsplit2(z10, z11, hiP, loP);
                        s_hh[r1 * HHROWW + pidx] = hiP;
                        s_hl[r1 * HHROWW + pidx] = loP;
                    }
                    s_m1c[net * 1024 + pidx * 8 + laneq] = (unsigned char)byte;
                }
            }
            __syncthreads();

            // ---- layer2 mma ----
            float D[2][4][4];
            #pragma unroll
            for (int mT = 0; mT < 2; mT++)
                #pragma unroll
                for (int t = 0; t < 4; t++)
                    #pragma unroll
                    for (int c = 0; c < 4; c++) D[mT][t][c] = 0.0f;

            const uint4* BF = g_BfU[net];
            for (int ks = 0; ks < 16; ks++) {
                int base = (ks * 32 + warp * 4) * 32 + lane;
                uint4 bv0 = BF[base];
                uint4 bv1 = BF[base + 32];
                uint4 bv2 = BF[base + 64];
                uint4 bv3 = BF[base + 96];
                #pragma unroll
                for (int mT = 0; mT < 2; mT++) {
                    unsigned ah0, ah1, ah2, ah3, al0, al1, al2, al3;
                    ldm_x4(ah0, ah1, ah2, ah3, hbH[mT] + ks * 32);
                    ldm_x4(al0, al1, al2, al3, hbL[mT] + ks * 32);
                    mma_bf16(D[mT][0][0], D[mT][0][1], D[mT][0][2], D[mT][0][3],
                             ah0, ah1, ah2, ah3, bv0.x, bv0.y);
                    mma_bf16(D[mT][0][0], D[mT][0][1], D[mT][0][2], D[mT][0][3],
                             ah0, ah1, ah2, ah3, bv0.z, bv0.w);
                    mma_bf16(D[mT][0][0], D[mT][0][1], D[mT][0][2], D[mT][0][3],
                             al0, al1, al2, al3, bv0.x, bv0.y);
                    mma_bf16(D[mT][1][0], D[mT][1][1], D[mT][1][2], D[mT][1][3],
                             ah0, ah1, ah2, ah3, bv1.x, bv1.y);
                    mma_bf16(D[mT][1][0], D[mT][1][1], D[mT][1][2], D[mT][1][3],
                             ah0, ah1, ah2, ah3, bv1.z, bv1.w);
                    mma_bf16(D[mT][1][0], D[mT][1][1], D[mT][1][2], D[mT][1][3],
                             al0, al1, al2, al3, bv1.x, bv1.y);
                    mma_bf16(D[mT][2][0], D[mT][2][1], D[mT][2][2], D[mT][2][3],
                             ah0, ah1, ah2, ah3, bv2.x, bv2.y);
                    mma_bf16(D[mT][2][0], D[mT][2][1], D[mT][2][2], D[mT][2][3],
                             ah0, ah1, ah2, ah3, bv2.z, bv2.w);
                    mma_bf16(D[mT][2][0], D[mT][2][1], D[mT][2][2], D[mT][2][3],
                             al0, al1, al2, al3, bv2.x, bv2.y);
                    mma_bf16(D[mT][3][0], D[mT][3][1], D[mT][3][2], D[mT][3][3],
                             ah0, ah1, ah2, ah3, bv3.x, bv3.y);
                    mma_bf16(D[mT][3][0], D[mT][3][1], D[mT][3][2], D[mT][3][3],
                             ah0, ah1, ah2, ah3, bv3.z, bv3.w);
                    mma_bf16(D[mT][3][0], D[mT][3][1], D[mT][3][2], D[mT][3][3],
                             al0, al1, al2, al3, bv3.x, bv3.y);
                }
            }

            // epilogue: bias, relu, mask2 bf16 plane, q partials
            float qr[2][2] = {{0.0f, 0.0f}, {0.0f, 0.0f}};
            #pragma unroll
            for (int t = 0; t < 4; t++) {
                int j0 = warp * 32 + t * 8 + 2 * lanet;
                int pidx = warp * 16 + t * 4 + lanet;
                float b2_0 = B2[j0], b2_1 = B2[j0 + 1];
                float w3_0 = W3[j0], w3_1 = W3[j0 + 1];
                #pragma unroll
                for (int mT = 0; mT < 2; mT++) {
                    int r0 = mT * 16 + laneq, r1 = r0 + 8;
                    float z00 = D[mT][t][0] + b2_0;
                    float z01 = D[mT][t][1] + b2_1;
                    float z10 = D[mT][t][2] + b2_0;
                    float z11 = D[mT][t][3] + b2_1;
                    unsigned w0 = 0, w1 = 0;
                    if (z00 > 0.0f) { w0 |= 0x3F80u;     qr[mT][0] += z00 * w3_0; }
                    if (z01 > 0.0f) { w0 |= 0x3F800000u; qr[mT][0] += z01 * w3_1; }
                    if (z10 > 0.0f) { w1 |= 0x3F80u;     qr[mT][1] += z10 * w3_0; }
                    if (z11 > 0.0f) { w1 |= 0x3F800000u; qr[mT][1] += z11 * w3_1; }
                    m2plane[r0 * HHROWW + pidx] = w0;
                    m2plane[r1 * HHROWW + pidx] = w1;
                }
            }
            #pragma unroll
            for (int mT = 0; mT < 2; mT++)
                #pragma unroll
                for (int u = 0; u < 2; u++) {
                    float v = qr[mT][u];
                    v += __shfl_xor_sync(0xffffffffu, v, 1);
                    v += __shfl_xor_sync(0xffffffffu, v, 2);
                    if (lanet == 0) s_red[warp * 32 + mT * 16 + 8 * u + laneq] = v;
                }
            __syncthreads();
            if (tid < NN) {
                float q = B3[0];
                #pragma unroll
                for (int w = 0; w < 8; w++) q += s_red[w * 32 + tid];
                s_q[net * 32 + tid] = q;
            }
            __syncthreads();
        }

        // ---- gate + stable partition ----
        if (tid < NN) {
            bool g = s_q[tid] <= s_q[32 + tid];
            unsigned ball = __ballot_sync(0xffffffffu, g);
            int c1 = __popc(ball);
            int below = __popc(ball & ((1u << tid) - 1u));
            int slot = g ? below : (c1 + (tid - below));
            s_orig[slot] = tid;
            if (tid == 0) s_cnt[0] = c1;
        }
        __syncthreads();

        // ============ backward: dh1 = mask2 @ V^T (2 net-passes, shared B) ============
        {
            const int cnt1 = s_cnt[0];
            const unsigned zadr = sb + SM_ZROW + (mat >> 1) * 16;
            // per-(pass,mT) mask-plane A addresses (permutation + net select + zeroing)
            unsigned adP[2][2];
            #pragma unroll
            for (int mT = 0; mT < 2; mT++) {
                int r = mT * 16 + (mat & 1) * 8 + rw;
                int o = s_orig[r];
                bool isA = r < cnt1;
                unsigned off = (mat >> 1) * 16;
                adP[0][mT] = isA  ? (sb + SM_M2A + o * (HHROWW * 4) + off) : zadr;
                adP[1][mT] = !isA ? (sb + SM_M2B + o * (HHROWW * 4) + off) : zadr;
            }

            float D[2][4][4];
            #pragma unroll
            for (int mT = 0; mT < 2; mT++)
                #pragma unroll
                for (int t = 0; t < 4; t++)
                    #pragma unroll
                    for (int c = 0; c < 4; c++) D[mT][t][c] = 0.0f;

            #pragma unroll
            for (int pass = 0; pass < 2; pass++) {
                if (pass == 0 && cnt1 == 0) continue;
                if (pass == 1 && cnt1 == NN) continue;
                const uint4* BT = g_BbU[pass];
                for (int ks = 0; ks < 16; ks++) {
                    int base = (ks * 32 + warp * 4) * 32 + lane;
                    uint4 bv0 = BT[base];
                    uint4 bv1 = BT[base + 32];
                    uint4 bv2 = BT[base + 64];
                    uint4 bv3 = BT[base + 96];
                    #pragma unroll
                    for (int mT = 0; mT < 2; mT++) {
                        unsigned a0, a1, a2, a3;
                        ldm_x4(a0, a1, a2, a3, adP[pass][mT] + ks * 32);
                        mma_bf16(D[mT][0][0], D[mT][0][1], D[mT][0][2], D[mT][0][3],
                                 a0, a1, a2, a3, bv0.x, bv0.y);
                        mma_bf16(D[mT][0][0], D[mT][0][1], D[mT][0][2], D[mT][0][3],
                                 a0, a1, a2, a3, bv0.z, bv0.w);
                        mma_bf16(D[mT][1][0], D[mT][1][1], D[mT][1][2], D[mT][1][3],
                                 a0, a1, a2, a3, bv1.x, bv1.y);
                        mma_bf16(D[mT][1][0], D[mT][1][1], D[mT][1][2], D[mT][1][3],
                                 a0, a1, a2, a3, bv1.z, bv1.w);
                        mma_bf16(D[mT][2][0], D[mT][2][1], D[mT][2][2], D[mT][2][3],
                                 a0, a1, a2, a3, bv2.x, bv2.y);
                        mma_bf16(D[mT][2][0], D[mT][2][1], D[mT][2][2], D[mT][2][3],
                                 a0, a1, a2, a3, bv2.z, bv2.w);
                        mma_bf16(D[mT][3][0], D[mT][3][1], D[mT][3][2], D[mT][3][3],
                                 a0, a1, a2, a3, bv3.x, bv3.y);
                        mma_bf16(D[mT][3][0], D[mT][3][1], D[mT][3][2], D[mT][3][3],
                                 a0, a1, a2, a3, bv3.z, bv3.w);
                    }
                }
            }

            // dh1 epilogue: relu mask1, bf16 split, write planes (slot-indexed)
            #pragma unroll
            for (int mT = 0; mT < 2; mT++) {
                int r0 = mT * 16 + laneq, r1 = r0 + 8;
                int o0 = s_orig[r0], o1 = s_orig[r1];
                const unsigned char* mb0 = s_m1c + ((r0 < cnt1) ? 0 : 1024);
                const unsigned char* mb1 = s_m1c + ((r1 < cnt1) ? 0 : 1024);
                int bitb0 = 4 * (o0 >> 4) + 2 * ((o0 >> 3) & 1);
                int bitb1 = 4 * (o1 >> 4) + 2 * ((o1 >> 3) & 1);
                #pragma unroll
                for (int t = 0; t < 4; t++) {
                    int c0 = warp * 32 + t * 8 + 2 * lanet;
                    int pidx = warp * 16 + t * 4 + lanet;
                    unsigned by0 = mb0[(c0 >> 1) * 8 + (o0 & 7)];
                    unsigned by1 = mb1[(c0 >> 1) * 8 + (o1 & 7)];
                    float v00 = (by0 >> (bitb0 + 0)) & 1u ? D[mT][t][0] : 0.0f;
                    float v01 = (by0 >> (bitb0 + 1)) & 1u ? D[mT][t][1] : 0.0f;
                    float v10 = (by1 >> (bitb1 + 0)) & 1u ? D[mT][t][2] : 0.0f;
                    float v11 = (by1 >> (bitb1 + 1)) & 1u ? D[mT][t][3] : 0.0f;
                    unsigned hiP, loP;
                    bfsplit2(v00, v01, hiP, loP);
                    s_hh[r0 * HHROWW + pidx] = hiP;
                    s_hl[r0 * HHROWW + pidx] = loP;
                    bfsplit2(v10, v11, hiP, loP);
                    s_hh[r1 * HHROWW + pidx] = hiP;
                    s_hl[r1 * HHROWW + pidx] = loP;
                }
            }
            __syncthreads();

            // ---- da via mma: da = dh1 @ W1act^T, k-split across warps ----
            {
                unsigned dhH[2][2], dhL[2][2];   // [pass][mT]
                #pragma unroll
                for (int mT = 0; mT < 2; mT++) {
                    int r = mT * 16 + (mat & 1) * 8 + rw;
                    bool isA = r < cnt1;
                    unsigned off = (mat >> 1) * 16;
                    unsigned hh = sb + SM_HH + r * (HHROWW * 4) + off;
                    unsigned ll = sb + SM_HL + r * (HHROWW * 4) + off;
                    dhH[0][mT] = isA ? hh : zadr;
                    dhL[0][mT] = isA ? ll : zadr;
                    dhH[1][mT] = !isA ? hh : zadr;
                    dhL[1][mT] = !isA ? ll : zadr;
                }
                float Dd[2][4];
                #pragma unroll
                for (int mT = 0; mT < 2; mT++)
                    #pragma unroll
                    for (int c = 0; c < 4; c++) Dd[mT][c] = 0.0f;

                #pragma unroll
                for (int pass = 0; pass < 2; pass++) {
                    if (pass == 0 && cnt1 == 0) continue;
                    if (pass == 1 && cnt1 == NN) continue;
                    #pragma unroll
                    for (int kc = 0; kc < 2; kc++) {
                        int ks = warp * 2 + kc;
                        uint4 bv = g_BdU[pass][ks * 32 + lane];
                        #pragma unroll
                        for (int mT = 0; mT < 2; mT++) {
                            unsigned ah0, ah1, ah2, ah3, al0, al1, al2, al3;
                            ldm_x4(ah0, ah1, ah2, ah3, dhH[pass][mT] + ks * 32);
                            ldm_x4(al0, al1, al2, al3, dhL[pass][mT] + ks * 32);
                            mma_bf16(Dd[mT][0], Dd[mT][1], Dd[mT][2], Dd[mT][3],
                                     ah0, ah1, ah2, ah3, bv.x, bv.y);
                            mma_bf16(Dd[mT][0], Dd[mT][1], Dd[mT][2], Dd[mT][3],
                                     ah0, ah1, ah2, ah3, bv.z, bv.w);
                            mma_bf16(Dd[mT][0], Dd[mT][1], Dd[mT][2], Dd[mT][3],
                                     al0, al1, al2, al3, bv.x, bv.y);
                        }
                    }
                }
                // store partials: [warp][slot][d8]
                #pragma unroll
                for (int mT = 0; mT < 2; mT++) {
                    int r0 = mT * 16 + laneq, r1 = r0 + 8;
                    *(float2*)&s_part[warp * 256 + r0 * 8 + 2 * lanet] =
                        make_float2(Dd[mT][0], Dd[mT][1]);
                    *(float2*)&s_part[warp * 256 + r1 * 8 + 2 * lanet] =
                        make_float2(Dd[mT][2], Dd[mT][3]);
                }
            }
            __syncthreads();

            // reduce 8 partials -> s_s[orig][d]
            {
                int sl = tid >> 3, d = tid & 7;
                if (d < DACT) {
                    float sum = 0.0f;
                    #pragma unroll
                    for (int w = 0; w < 8; w++) sum += s_part[w * 256 + sl * 8 + d];
                    s_s[s_orig[sl] * AST + d] = sum;
                }
            }
            __syncthreads();
        }

        // ================= SVGD update =================
        unsigned v[4];
        #pragma unroll
        for (int e = 0; e < 4; e++) {
            int p = (e << 8) | tid;
            int i = p >> 5, j = p & 31;
            float ds = 0.0f;
            #pragma unroll
            for (int d = 0; d < DACT; d++) {
                float df = s_a[i * AST + d] - s_a[j * AST + d];
                ds += df * df;
            }
            s_d2p[p] = ds;
            v[e] = __float_as_uint(ds);
        }
        __syncthreads();

        // exact median via 4-pass radix select (sorted[511], then sorted[512])
        unsigned* hist = (unsigned*)s_hf;
        unsigned* ws   = hist + 256;
        unsigned* bc   = hist + 280;
        unsigned prefix = 0, need = 511;
        #pragma unroll
        for (int pass = 0; pass < 4; pass++) {
            int dsh = 24 - pass * 8;
            unsigned maskHigh = (pass == 0) ? 0u : (0xFFFFFFFFu << (dsh + 8));
            hist[tid] = 0;
            __syncthreads();
            #pragma unroll
            for (int e = 0; e < 4; e++)
                if ((v[e] & maskHigh) == prefix)
                    atomicAdd(&hist[(v[e] >> dsh) & 255u], 1u);
            __syncthreads();
            unsigned h = hist[tid], x = h;
            #pragma unroll
            for (int off = 1; off < 32; off <<= 1) {
                unsigned y = __shfl_up_sync(0xffffffffu, x, off);
                if (lane >= off) x += y;
            }
            if (lane == 31) ws[warp] = x;
            __syncthreads();
            if (warp == 0) {
                unsigned sv = (lane < 8) ? ws[lane] : 0u;
                #pragma unroll
                for (int off = 1; off < 8; off <<= 1) {
                    unsigned y = __shfl_up_sync(0xffffffffu, sv, off);
                    if (lane >= off) sv += y;
                }
                if (lane < 8) ws[lane] = sv;
            }
            __syncthreads();
            unsigned cumIncl = x + (warp ? ws[warp - 1] : 0u);
            unsigned cumExcl = cumIncl - h;
            if (need >= cumExcl && need < cumIncl) { bc[0] = (unsigned)tid; bc[1] = cumExcl; }
            __syncthreads();
            prefix |= bc[0] << dsh;
            need   -= bc[1];
            __syncthreads();
        }
        {
            unsigned cLe = 0, mA = 0xFFFFFFFFu;
            #pragma unroll
            for (int e = 0; e < 4; e++) {
                if (v[e] <= prefix) cLe++;
                else mA = min(mA, v[e]);
            }
            #pragma unroll
            for (int off = 16; off; off >>= 1) {
                cLe += __shfl_xor_sync(0xffffffffu, cLe, off);
                mA = min(mA, __shfl_xor_sync(0xffffffffu, mA, off));
            }
            if (lane == 0) { ws[warp] = cLe; ws[warp + 8] = mA; }
            __syncthreads();
            if (tid == 0) {
                unsigned c = 0, m = 0xFFFFFFFFu;
                #pragma unroll
                for (int w = 0; w < 8; w++) { c += ws[w]; m = min(m, ws[w + 8]); }
                bc[2] = (c >= 513u) ? prefix : m;
            }
            __syncthreads();
        }
        float med = 0.5f * (__uint_as_float(prefix) + __uint_as_float(bc[2]));
        float hm = med / logf(33.0f);
        float gamma = 1.0f / (2.0f * hm + 1e-8f);
        __syncthreads();
        for (int p = tid; p < NN * NN; p += 256)
            s_Kp[p] = expf(-gamma * s_d2p[p]);
        __syncthreads();

        float anew[DACT];
        float lpdelta = 0.0f;
        if (tid < NN) {
            int i = tid;
            float ai[DACT];
            #pragma unroll
            for (int d = 0; d < DACT; d++) ai[d] = s_a[i * AST + d];
            float ph[DACT] = {0, 0, 0, 0, 0, 0};
            float t1 = 0.0f, t2s = 0.0f;
            for (int j = 0; j < NN; j++) {
                float Kij = s_Kp[i * 32 + j];
                float dot = 0.0f;
                #pragma unroll
                for (int d = 0; d < DACT; d++) {
                    float df = ai[d] - s_a[j * AST + d];
                    float sj = s_s[j * AST + d];
                    dot += df * sj;
                    ph[d] += Kij * sj + 2.0f * gamma * Kij * df;
                }
                t1 += -2.0f * gamma * Kij * dot;
                float I = (i == j) ? 1.0f : 0.0f;
                t2s += 2.0f * gamma * Kij * s_d2p[i * 32 + j] - 6.0f * (Kij - I);
            }
            t1 *= (1.0f / 31.0f);
            float t2 = -2.0f * gamma * t2s * (1.0f / 31.0f);
            lpdelta = 0.05f * (t1 + t2);
            #pragma unroll
            for (int d = 0; d < DACT; d++)
                anew[d] = ai[d] + 0.05f * ph[d] * (1.0f / 32.0f);
        }
        __syncthreads();
        if (tid < NN) {
            s_logp[tid] -= lpdelta;
            #pragma unroll
            for (int d = 0; d < DACT; d++) s_a[tid * AST + d] = anew[d];
        }
        __syncthreads();
    }

    // ================= finalize =================
    __syncthreads();
    if (tid < NN) {
        int n = tid;
        float lpt = 0.0f;
        #pragma unroll
        for (int d = 0; d < DACT; d++) {
            float av = s_a[n * AST + d];
            float x = -2.0f * av;
            float sp = (x > 0.0f) ? (x + log1pf(expf(-x))) : log1pf(expf(x));
            lpt += -2.0f * (0.6931471805599453f - av - sp);
            out[(b * NN + n) * DACT + d] = tanhf(av);
        }
        s_red[n] = s_lpn[n] + s_logp[n] + lpt;
    }
    __syncthreads();
    if (tid == 0) {
        float m = 0.0f;
        for (int n = 0; n < NN; n++) m += s_red[n];
        out[BB * NN * DACT + b] = m * (1.0f / 32.0f);
    }
}

extern "C" void kernel_launch(void* const* d_in, const int* in_sizes, int n_in,
                              void* d_out, int out_size) {
    const float* obs  = (const float*)d_in[0];
    const float* a0   = (const float*)d_in[1];
    const float* q1W1 = (const float*)d_in[2];
    const float* q1b1 = (const float*)d_in[3];
    const float* q1W2 = (const float*)d_in[4];
    const float* q1b2 = (const float*)d_in[5];
    const float* q1W3 = (const float*)d_in[6];
    const float* q1b3 = (const float*)d_in[7];
    const float* q2W1 = (const float*)d_in[8];
    const float* q2b1 = (const float*)d_in[9];
    const float* q2W2 = (const float*)d_in[10];
    const float* q2b2 = (const float*)d_in[11];
    const float* q2W3 = (const float*)d_in[12];
    const float* q2b3 = (const float*)d_in[13];
    float* out = (float*)d_out;

    cudaFuncSetAttribute(svgd_kernel,
                         cudaFuncAttributeMaxDynamicSharedMemorySize, SM_TOTAL);

    prep_weights<<<dim3(64, 2), 256>>>(q1W2, q2W2, q1W3, q2W3, q1W1, q2W1);
    svgd_kernel<<<BB, 256, SM_TOTAL>>>(obs, a0,
                             q1W1, q1b1, q1W2, q1b2, q1W3, q1b3,
                             q2W1, q2b1, q2W2, q2b2, q2W3, q2b3,
                             out);
}